// round 12
// baseline (speedup 1.0000x reference)
#include <cuda_runtime.h>
#include <cuda_bf16.h>
#include <math.h>
#include <stdint.h>

// ---------------------------------------------------------------------------
// Problem constants
// ---------------------------------------------------------------------------
#define TOK      8192
#define IDIM     256
#define NU       512
#define EU       2048
#define NLAYERS  4
#define HEADS    8
#define DK       64
#define SEQ      1024
#define NBATCH   8
#define QKVW     1536
#define BH       (NBATCH * HEADS)   // 64

// ---------------------------------------------------------------------------
// Scratch (static device memory; allocation APIs are forbidden)
// ---------------------------------------------------------------------------
__device__ float g_e[TOK * NU];

// split-bf16 operand buffers (K-concat: activations [hi|hi|lo], weights [hi|lo|hi])
__device__ __nv_bfloat16 g_xcvt [TOK * 3 * IDIM];
__device__ __nv_bfloat16 g_ecvt [TOK * 3 * NU];
__device__ __nv_bfloat16 g_ccvt [TOK * 3 * NU];
__device__ __nv_bfloat16 g_hcvt [TOK * 3 * EU];

__device__ __nv_bfloat16 g_Winc  [NU * 3 * IDIM];
__device__ __nv_bfloat16 g_Wqkvc [NLAYERS * QKVW * 3 * NU];
__device__ __nv_bfloat16 g_Woc   [NLAYERS * NU * 3 * NU];
__device__ __nv_bfloat16 g_W1c   [NLAYERS * EU * 3 * NU];
__device__ __nv_bfloat16 g_W2c   [NLAYERS * NU * 3 * EU];
__device__ float         g_bqkv  [NLAYERS * QKVW];

// attention operands, 2-slab [hi|lo] layouts
__device__ __nv_bfloat16 g_qs [BH * SEQ * 128];        // [bh][t][hi64|lo64] (scaled)
__device__ __nv_bfloat16 g_ks [BH * SEQ * 128];        // [bh][t][hi64|lo64]
__device__ __nv_bfloat16 g_vt [BH * DK * 2 * SEQ];     // [bh][d][hi@s | lo@1024+s]

// ---------------------------------------------------------------------------
// split helpers
// ---------------------------------------------------------------------------
__device__ __forceinline__ void split_bf16(float f, __nv_bfloat16& hi, __nv_bfloat16& lo) {
    hi = __float2bfloat16(f);
    lo = __float2bfloat16(f - __bfloat162float(hi));
}
__device__ __forceinline__ uint32_t packbf(float a, float b) {
    __nv_bfloat162 t = __halves2bfloat162(__float2bfloat16(a), __float2bfloat16(b));
    return *(uint32_t*)&t;
}
__device__ __forceinline__ float lof(float a) {
    return a - __bfloat162float(__float2bfloat16(a));
}

// weights: out row = [hi | lo | hi], row width 3K
__global__ void convert_B_kernel(const float* __restrict__ W, __nv_bfloat16* __restrict__ out,
                                 int K, int total) {
    int idx = blockIdx.x * 256 + threadIdx.x;
    if (idx >= total) return;
    int n = idx / K, k = idx - n * K;
    __nv_bfloat16 hi, lo;
    split_bf16(W[idx], hi, lo);
    size_t base = (size_t)n * 3 * K;
    out[base + k] = hi;
    out[base + K + k] = lo;
    out[base + 2 * K + k] = hi;
}

// activations: out row = [hi | hi | lo]
__global__ void convert_A_kernel(const float* __restrict__ A, __nv_bfloat16* __restrict__ out,
                                 int K, int total) {
    int idx = blockIdx.x * 256 + threadIdx.x;
    if (idx >= total) return;
    int n = idx / K, k = idx - n * K;
    __nv_bfloat16 hi, lo;
    split_bf16(A[idx], hi, lo);
    size_t base = (size_t)n * 3 * K;
    out[base + k] = hi;
    out[base + K + k] = hi;
    out[base + 2 * K + k] = lo;
}

// pack per-layer q|k|v biases into 1536-wide rows
__global__ void pack_bqkv_kernel(const float* __restrict__ bq, const float* __restrict__ bk,
                                 const float* __restrict__ bv, float* __restrict__ out) {
    int i = blockIdx.x * 256 + threadIdx.x;
    if (i >= NLAYERS * QKVW) return;
    int l = i / QKVW, c = i - l * QKVW;
    float v = (c < NU) ? bq[l * NU + c]
            : (c < 2 * NU) ? bk[l * NU + c - NU]
            : bv[l * NU + c - 2 * NU];
    out[i] = v;
}

// ---------------------------------------------------------------------------
// mma.sync common pieces
// ---------------------------------------------------------------------------
#define STAGE_BYTES 32768
#define GEMM_DSMEM  (3 * STAGE_BYTES)
#define FA_STAGE    65536          // Khi 16K | Klo 16K | V 4x8K
#define FA_DSMEM    (32768 + 2 * FA_STAGE)   // Q 32K + 2 stages = 160K

__device__ __forceinline__ uint32_t smem_u32(const void* p) {
    uint32_t a;
    asm("{ .reg .u64 t; cvta.to.shared.u64 t, %1; cvt.u32.u64 %0, t; }" : "=r"(a) : "l"(p));
    return a;
}

#define CP_ASYNC16(dst, src) \
    asm volatile("cp.async.cg.shared.global [%0], [%1], 16;" :: "r"(dst), "l"(src) : "memory")
#define CP_COMMIT() asm volatile("cp.async.commit_group;" ::: "memory")
#define CP_WAIT1()  asm volatile("cp.async.wait_group 1;" ::: "memory")
#define CP_WAIT2()  asm volatile("cp.async.wait_group 2;" ::: "memory")

#define LDMATRIX_X4(r0, r1, r2, r3, addr) \
    asm volatile("ldmatrix.sync.aligned.m8n8.x4.shared.b16 {%0,%1,%2,%3}, [%4];" \
        : "=r"(r0), "=r"(r1), "=r"(r2), "=r"(r3) : "r"(addr))

__device__ __forceinline__ void mma16816(float* d, const uint32_t* a, const uint32_t* b) {
    asm volatile(
        "mma.sync.aligned.m16n8k16.row.col.f32.bf16.bf16.f32 "
        "{%0,%1,%2,%3}, {%4,%5,%6,%7}, {%8,%9}, {%0,%1,%2,%3};"
        : "+f"(d[0]), "+f"(d[1]), "+f"(d[2]), "+f"(d[3])
        : "r"(a[0]), "r"(a[1]), "r"(a[2]), "r"(a[3]), "r"(b[0]), "r"(b[1]));
}

// ---------------------------------------------------------------------------
// Linear GEMM, 3-stage cp.async: C[M,N] = A[M,Kp] @ B[N,Kp]^T
// EP: 0 = fp32 out, 1 = fp32 + residual, 2 = relu + split-bf16 out (A-style)
//     3 = fused qkv epilogue: write per-head attention operand layouts
// ---------------------------------------------------------------------------
template<int EP>
__global__ __launch_bounds__(256) void mma_gemm(
    const __nv_bfloat16* __restrict__ A, const __nv_bfloat16* __restrict__ B,
    const float* __restrict__ bias, const float* __restrict__ res,
    float* __restrict__ Cf, __nv_bfloat16* __restrict__ Cb,
    __nv_bfloat16* __restrict__ q_out, __nv_bfloat16* __restrict__ k_out,
    __nv_bfloat16* __restrict__ v_out,
    int N, int Kp)
{
    extern __shared__ __align__(16) char dsm[];
    const uint32_t sbase = smem_u32(dsm);

    const int tid  = threadIdx.x;
    const int wid  = tid >> 5;
    const int lane = tid & 31;
    const int g    = lane >> 2;
    const int cq   = lane & 3;
    const int lr   = lane & 15;
    const int lc   = lane >> 4;
    const int wm   = wid & 3;
    const int wn   = wid >> 2;
    const int n0   = blockIdx.x * 128;
    const int m0   = blockIdx.y * 128;

    const __nv_bfloat16* Ap = A + (size_t)m0 * Kp;
    const __nv_bfloat16* Bp = B + (size_t)n0 * Kp;
    const int nchunk = Kp >> 6;

    float acc[2][8][4];
#pragma unroll
    for (int mi = 0; mi < 2; mi++)
#pragma unroll
        for (int ni = 0; ni < 8; ni++)
#pragma unroll
            for (int r = 0; r < 4; r++) acc[mi][ni][r] = 0.0f;

    auto load_stage = [&](int c, int stage) {
        const int k0 = c << 6;
        const uint32_t sA = sbase + stage * STAGE_BYTES;
        const uint32_t sB = sA + 16384;
#pragma unroll
        for (int i = 0; i < 4; i++) {
            int lin = tid + i * 256;
            int r   = lin >> 3;
            int c16 = lin & 7;
            uint32_t off = (uint32_t)(r * 128 + ((c16 ^ (r & 7)) * 16));
            CP_ASYNC16(sA + off, (const void*)(Ap + (size_t)r * Kp + k0 + c16 * 8));
            CP_ASYNC16(sB + off, (const void*)(Bp + (size_t)r * Kp + k0 + c16 * 8));
        }
    };

    load_stage(0, 0);
    CP_COMMIT();
    if (nchunk > 1) load_stage(1, 1);
    CP_COMMIT();

    for (int c = 0; c < nchunk; c++) {
        if (c + 2 < nchunk) {
            int s2 = c + 2;
            load_stage(s2, s2 - (s2 / 3) * 3);
        }
        CP_COMMIT();
        CP_WAIT2();
        __syncthreads();

        const int cur = c - (c / 3) * 3;
        const uint32_t sA = sbase + cur * STAGE_BYTES;
        const uint32_t sB = sA + 16384;

#pragma unroll
        for (int ks = 0; ks < 4; ks++) {
            const int kblk = ks * 2 + lc;
            uint32_t afr[2][4], bfr[4][4];
#pragma unroll
            for (int mi = 0; mi < 2; mi++) {
                int row = wm * 32 + mi * 16 + lr;
                uint32_t addr = sA + (uint32_t)(row * 128 + ((kblk ^ (row & 7)) * 16));
                LDMATRIX_X4(afr[mi][0], afr[mi][1], afr[mi][2], afr[mi][3], addr);
            }
#pragma unroll
            for (int p = 0; p < 4; p++) {
                int row = wn * 64 + p * 16 + lr;
                uint32_t addr = sB + (uint32_t)(row * 128 + ((kblk ^ (row & 7)) * 16));
                LDMATRIX_X4(bfr[p][0], bfr[p][1], bfr[p][2], bfr[p][3], addr);
            }
#pragma unroll
            for (int mi = 0; mi < 2; mi++)
#pragma unroll
                for (int ni = 0; ni < 8; ni++) {
                    const int p = ni >> 1, o = ni & 1;
                    uint32_t b2[2] = { bfr[p][o], bfr[p][2 + o] };
                    mma16816(acc[mi][ni], afr[mi], b2);
                }
        }
        __syncthreads();
    }

#pragma unroll
    for (int mi = 0; mi < 2; mi++) {
#pragma unroll
        for (int half = 0; half < 2; half++) {
            const int m = m0 + wm * 32 + mi * 16 + g + half * 8;
#pragma unroll
            for (int ni = 0; ni < 8; ni++) {
                const int n = n0 + wn * 64 + ni * 8 + 2 * cq;
                float2 bv = *(const float2*)(bias + n);
                float v0 = acc[mi][ni][half * 2 + 0] + bv.x;
                float v1 = acc[mi][ni][half * 2 + 1] + bv.y;
                if (EP == 2) {
                    v0 = fmaxf(v0, 0.f); v1 = fmaxf(v1, 0.f);
                    __nv_bfloat16 h0, h1, l0, l1;
                    split_bf16(v0, h0, l0); split_bf16(v1, h1, l1);
                    uint32_t hp, lp;
                    *(__nv_bfloat162*)&hp = __halves2bfloat162(h0, h1);
                    *(__nv_bfloat162*)&lp = __halves2bfloat162(l0, l1);
                    size_t rb = (size_t)m * 3 * N;
                    *(uint32_t*)(Cb + rb + n)         = hp;
                    *(uint32_t*)(Cb + rb + N + n)     = hp;
                    *(uint32_t*)(Cb + rb + 2 * N + n) = lp;
                } else if (EP == 3) {
                    // fused qkv epilogue: n in [0,1536) = q|k|v sections
                    const int sec = n >> 9;            // 0=q 1=k 2=v
                    const int hh  = (n >> 6) & 7;      // head
                    const int d   = n & 63;            // dim within head (even)
                    const int t   = m & (SEQ - 1);
                    const int bh  = (m >> 10) * HEADS + hh;
                    if (sec == 0) {
                        float q0 = v0 * 0.125f, q1 = v1 * 0.125f;
                        __nv_bfloat16 h0, h1, l0, l1;
                        split_bf16(q0, h0, l0); split_bf16(q1, h1, l1);
                        uint32_t hp, lp;
                        *(__nv_bfloat162*)&hp = __halves2bfloat162(h0, h1);
                        *(__nv_bfloat162*)&lp = __halves2bfloat162(l0, l1);
                        __nv_bfloat16* qb = q_out + ((size_t)bh * SEQ + t) * 128 + d;
                        *(uint32_t*)(qb)      = hp;
                        *(uint32_t*)(qb + 64) = lp;
                    } else if (sec == 1) {
                        __nv_bfloat16 h0, h1, l0, l1;
                        split_bf16(v0, h0, l0); split_bf16(v1, h1, l1);
                        uint32_t hp, lp;
                        *(__nv_bfloat162*)&hp = __halves2bfloat162(h0, h1);
                        *(__nv_bfloat162*)&lp = __halves2bfloat162(l0, l1);
                        __nv_bfloat16* kb = k_out + ((size_t)bh * SEQ + t) * 128 + d;
                        *(uint32_t*)(kb)      = hp;
                        *(uint32_t*)(kb + 64) = lp;
                    } else {
                        __nv_bfloat16 h0, h1, l0, l1;
                        split_bf16(v0, h0, l0); split_bf16(v1, h1, l1);
                        __nv_bfloat16* vb0 = v_out + ((size_t)bh * DK + d) * (2 * SEQ) + t;
                        __nv_bfloat16* vb1 = vb0 + 2 * SEQ;
                        vb0[0]   = h0; vb0[SEQ] = l0;
                        vb1[0]   = h1; vb1[SEQ] = l1;
                    }
                } else {
                    if (EP == 1) {
                        float2 rv = *(const float2*)(res + (size_t)m * N + n);
                        v0 += rv.x; v1 += rv.y;
                    }
                    *(float2*)(Cf + (size_t)m * N + n) = make_float2(v0, v1);
                }
            }
        }
    }
}

// ---------------------------------------------------------------------------
// Fused flash attention (no-max softmax) — verified in R10, unchanged.
// ---------------------------------------------------------------------------
__global__ __launch_bounds__(256) void flash_attn(
    const __nv_bfloat16* __restrict__ qs, const __nv_bfloat16* __restrict__ ks,
    const __nv_bfloat16* __restrict__ vt, __nv_bfloat16* __restrict__ Ccvt)
{
    extern __shared__ __align__(16) char dsm[];
    const uint32_t sb  = smem_u32(dsm);
    const uint32_t Qhi = sb;               // [128][64] bf16
    const uint32_t Qlo = sb + 16384;
    const uint32_t ST0 = sb + 32768;       // stage: Khi 16K | Klo 16K | V 4x8K

    const int tid  = threadIdx.x;
    const int wid  = tid >> 5;
    const int lane = tid & 31;
    const int g    = lane >> 2;
    const int cq   = lane & 3;
    const int lr   = lane & 15;
    const int lc   = lane >> 4;
    const int q0   = blockIdx.x * 128;
    const int bh   = blockIdx.y;
    const int b    = bh >> 3, h = bh & 7;

    // --- load Q (once) ---
#pragma unroll
    for (int i = 0; i < 8; i++) {
        int id = tid + i * 256;
        int slab = id >> 10, r = (id >> 3) & 127, u = id & 7;
        const __nv_bfloat16* src = qs + ((size_t)bh * SEQ + q0 + r) * 128 + slab * 64 + u * 8;
        CP_ASYNC16((slab ? Qlo : Qhi) + (uint32_t)(r * 128 + ((u ^ (r & 7)) * 16)), src);
    }

    auto load_kv = [&](int st, uint32_t stage) {
        const int s0 = st * 128;
#pragma unroll
        for (int i = 0; i < 8; i++) {          // K: 2 slabs x 128 rows x 8 units
            int id = tid + i * 256;
            int slab = id >> 10, r = (id >> 3) & 127, u = id & 7;
            const __nv_bfloat16* src = ks + ((size_t)bh * SEQ + s0 + r) * 128 + slab * 64 + u * 8;
            CP_ASYNC16(stage + slab * 16384 + (uint32_t)(r * 128 + ((u ^ (r & 7)) * 16)), src);
        }
#pragma unroll
        for (int i = 0; i < 8; i++) {          // V: 4 slabs x 64 rows x 8 units
            int id = tid + i * 256;
            int slab = id >> 9;                // 0:hi_a 1:hi_b 2:lo_a 3:lo_b
            int r = (id >> 3) & 63, u = id & 7;
            int col = (slab >> 1) * SEQ + s0 + (slab & 1) * 64 + u * 8;
            const __nv_bfloat16* src = vt + ((size_t)bh * DK + r) * (2 * SEQ) + col;
            CP_ASYNC16(stage + 32768 + slab * 8192 + (uint32_t)(r * 128 + ((u ^ (r & 7)) * 16)), src);
        }
    };

    load_kv(0, ST0);
    CP_COMMIT();

    float oacc[8][4];
#pragma unroll
    for (int ni = 0; ni < 8; ni++)
#pragma unroll
        for (int r = 0; r < 4; r++) oacc[ni][r] = 0.0f;
    float lsum0 = 0.0f, lsum1 = 0.0f;

    const int arow = wid * 16 + lr;
    const uint32_t aoff = (uint32_t)(arow * 128);

    for (int st = 0; st < 8; st++) {
        const int cur = st & 1;
        if (st + 1 < 8) load_kv(st + 1, ST0 + (cur ^ 1) * FA_STAGE);
        CP_COMMIT();
        CP_WAIT1();
        __syncthreads();

        const uint32_t Kh = ST0 + cur * FA_STAGE;
        const uint32_t Kl = Kh + 16384;
        const uint32_t Vb = Kh + 32768;

        // ---- S = Q K^T (3 logical slabs) ----
        float sacc[16][4];
#pragma unroll
        for (int ni = 0; ni < 16; ni++)
#pragma unroll
            for (int r = 0; r < 4; r++) sacc[ni][r] = 0.0f;

        uint32_t ahi[4][4];
#pragma unroll
        for (int j = 0; j < 4; j++) {
            const int kblk = j * 2 + lc;
            const uint32_t asw = (uint32_t)((kblk ^ (arow & 7)) * 16);
            LDMATRIX_X4(ahi[j][0], ahi[j][1], ahi[j][2], ahi[j][3], Qhi + aoff + asw);
#pragma unroll
            for (int p = 0; p < 8; p++) {
                int row = p * 16 + lr;
                uint32_t addr = Kh + (uint32_t)(row * 128 + ((kblk ^ (row & 7)) * 16));
                uint32_t bfr[4];
                LDMATRIX_X4(bfr[0], bfr[1], bfr[2], bfr[3], addr);
#pragma unroll
                for (int o = 0; o < 2; o++) {
                    uint32_t b2[2] = { bfr[o], bfr[2 + o] };
                    mma16816(sacc[2 * p + o], ahi[j], b2);
                }
            }
#pragma unroll
            for (int p = 0; p < 8; p++) {
                int row = p * 16 + lr;
                uint32_t addr = Kl + (uint32_t)(row * 128 + ((kblk ^ (row & 7)) * 16));
                uint32_t bfr[4];
                LDMATRIX_X4(bfr[0], bfr[1], bfr[2], bfr[3], addr);
#pragma unroll
                for (int o = 0; o < 2; o++) {
                    uint32_t b2[2] = { bfr[o], bfr[2 + o] };
                    mma16816(sacc[2 * p + o], ahi[j], b2);
                }
            }
        }
#pragma unroll
        for (int j = 0; j < 4; j++) {
            const int kblk = j * 2 + lc;
            const uint32_t asw = (uint32_t)((kblk ^ (arow & 7)) * 16);
            uint32_t alo[4];
            LDMATRIX_X4(alo[0], alo[1], alo[2], alo[3], Qlo + aoff + asw);
#pragma unroll
            for (int p = 0; p < 8; p++) {
                int row = p * 16 + lr;
                uint32_t addr = Kh + (uint32_t)(row * 128 + ((kblk ^ (row & 7)) * 16));
                uint32_t bfr[4];
                LDMATRIX_X4(bfr[0], bfr[1], bfr[2], bfr[3], addr);
#pragma unroll
                for (int o = 0; o < 2; o++) {
                    uint32_t b2[2] = { bfr[o], bfr[2 + o] };
                    mma16816(sacc[2 * p + o], alo, b2);
                }
            }
        }

        // ---- P = exp(S); accumulate row sums; build hi A-fragments ----
#pragma unroll
        for (int ni = 0; ni < 16; ni++) {
            float p0 = __expf(sacc[ni][0]);
            float p1 = __expf(sacc[ni][1]);
            float p2 = __expf(sacc[ni][2]);
            float p3 = __expf(sacc[ni][3]);
            lsum0 += p0 + p1;
            lsum1 += p2 + p3;
            sacc[ni][0] = p0; sacc[ni][1] = p1;
            sacc[ni][2] = p2; sacc[ni][3] = p3;
        }
        uint32_t phi[8][4];
#pragma unroll
        for (int jj = 0; jj < 8; jj++) {
            phi[jj][0] = packbf(sacc[2 * jj][0],     sacc[2 * jj][1]);
            phi[jj][1] = packbf(sacc[2 * jj][2],     sacc[2 * jj][3]);
            phi[jj][2] = packbf(sacc[2 * jj + 1][0], sacc[2 * jj + 1][1]);
            phi[jj][3] = packbf(sacc[2 * jj + 1][2], sacc[2 * jj + 1][3]);
        }

        // ---- ctx += P V^T (3 logical slabs) ----
#pragma unroll
        for (int jj = 0; jj < 8; jj++) {
            const int kblk = (jj & 3) * 2 + lc;
            const uint32_t baseH = Vb + (jj >> 2) * 8192;
            const uint32_t baseL = Vb + 16384 + (jj >> 2) * 8192;
            // P_hi x V_hi
#pragma unroll
            for (int p = 0; p < 4; p++) {
                int row = p * 16 + lr;
                uint32_t addr = baseH + (uint32_t)(row * 128 + ((kblk ^ (row & 7)) * 16));
                uint32_t bfr[4];
                LDMATRIX_X4(bfr[0], bfr[1], bfr[2], bfr[3], addr);
#pragma unroll
                for (int o = 0; o < 2; o++) {
                    uint32_t b2[2] = { bfr[o], bfr[2 + o] };
                    mma16816(oacc[2 * p + o], phi[jj], b2);
                }
            }
            // P_hi x V_lo
#pragma unroll
            for (int p = 0; p < 4; p++) {
                int row = p * 16 + lr;
                uint32_t addr = baseL + (uint32_t)(row * 128 + ((kblk ^ (row & 7)) * 16));
                uint32_t bfr[4];
                LDMATRIX_X4(bfr[0], bfr[1], bfr[2], bfr[3], addr);
#pragma unroll
                for (int o = 0; o < 2; o++) {
                    uint32_t b2[2] = { bfr[o], bfr[2 + o] };
                    mma16816(oacc[2 * p + o], phi[jj], b2);
                }
            }
            // P_lo x V_hi
            uint32_t plo[4];
            plo[0] = packbf(lof(sacc[2 * jj][0]),     lof(sacc[2 * jj][1]));
            plo[1] = packbf(lof(sacc[2 * jj][2]),     lof(sacc[2 * jj][3]));
            plo[2] = packbf(lof(sacc[2 * jj + 1][0]), lof(sacc[2 * jj + 1][1]));
            plo[3] = packbf(lof(sacc[2 * jj + 1][2]), lof(sacc[2 * jj + 1][3]));
#pragma unroll
            for (int p = 0; p < 4; p++) {
                int row = p * 16 + lr;
                uint32_t addr = baseH + (uint32_t)(row * 128 + ((kblk ^ (row & 7)) * 16));
                uint32_t bfr[4];
                LDMATRIX_X4(bfr[0], bfr[1], bfr[2], bfr[3], addr);
#pragma unroll
                for (int o = 0; o < 2; o++) {
                    uint32_t b2[2] = { bfr[o], bfr[2 + o] };
                    mma16816(oacc[2 * p + o], plo, b2);
                }
            }
        }
        __syncthreads();
    }

    // row-sum reduction over the quad (cq lanes)
    lsum0 += __shfl_xor_sync(0xffffffffu, lsum0, 1);
    lsum0 += __shfl_xor_sync(0xffffffffu, lsum0, 2);
    lsum1 += __shfl_xor_sync(0xffffffffu, lsum1, 1);
    lsum1 += __shfl_xor_sync(0xffffffffu, lsum1, 2);
    const float inv0 = 1.0f / lsum0;
    const float inv1 = 1.0f / lsum1;

    // epilogue: split write into g_ccvt [tok][3*512] at cols h*64 + n
#pragma unroll
    for (int half = 0; half < 2; half++) {
        const int m = q0 + wid * 16 + g + half * 8;
        const size_t tok = (size_t)b * SEQ + m;
        const size_t rb = tok * (3 * NU);
        const float inv = half ? inv1 : inv0;
#pragma unroll
        for (int ni = 0; ni < 8; ni++) {
            const int col = h * DK + ni * 8 + 2 * cq;
            float v0 = oacc[ni][half * 2 + 0] * inv;
            float v1 = oacc[ni][half * 2 + 1] * inv;
            __nv_bfloat16 h0, h1, l0, l1;
            split_bf16(v0, h0, l0); split_bf16(v1, h1, l1);
            uint32_t hp, lp;
            *(__nv_bfloat162*)&hp = __halves2bfloat162(h0, h1);
            *(__nv_bfloat162*)&lp = __halves2bfloat162(l0, l1);
            *(uint32_t*)(Ccvt + rb + col)          = hp;
            *(uint32_t*)(Ccvt + rb + NU + col)     = hp;
            *(uint32_t*)(Ccvt + rb + 2 * NU + col) = lp;
        }
    }
}

// ---------------------------------------------------------------------------
// LayerNorm over rows of 512; optionally also writes split-bf16 (A-style)
// ---------------------------------------------------------------------------
template<bool CVT>
__global__ __launch_bounds__(128) void ln_kernel(
    const float* __restrict__ X, const float* __restrict__ gamma,
    const float* __restrict__ beta, float* __restrict__ O,
    __nv_bfloat16* __restrict__ Ocvt)
{
    __shared__ float red[4];
    const int row = blockIdx.x;
    const int tid = threadIdx.x;

    float4 v = *(const float4*)(X + (size_t)row * NU + tid * 4);
    float s = v.x + v.y + v.z + v.w;
#pragma unroll
    for (int o = 16; o > 0; o >>= 1) s += __shfl_xor_sync(0xffffffffu, s, o);
    if ((tid & 31) == 0) red[tid >> 5] = s;
    __syncthreads();
    float mean = (red[0] + red[1] + red[2] + red[3]) * (1.0f / 512.0f);
    __syncthreads();

    float dx = v.x - mean, dy = v.y - mean, dz = v.z - mean, dw = v.w - mean;
    float sq = dx * dx + dy * dy + dz * dz + dw * dw;
#pragma unroll
    for (int o = 16; o > 0; o >>= 1) sq += __shfl_xor_sync(0xffffffffu, sq, o);
    if ((tid & 31) == 0) red[tid >> 5] = sq;
    __syncthreads();
    float var = (red[0] + red[1] + red[2] + red[3]) * (1.0f / 512.0f);
    float inv = rsqrtf(var + 1e-5f);

    float4 g = *(const float4*)(gamma + tid * 4);
    float4 b = *(const float4*)(beta  + tid * 4);
    float4 o4;
    o4.x = dx * inv * g.x + b.x;
    o4.y = dy * inv * g.y + b.y;
    o4.z = dz * inv * g.z + b.z;
    o4.w = dw * inv * g.w + b.w;
    *(float4*)(O + (size_t)row * NU + tid * 4) = o4;

    if (CVT) {
        __nv_bfloat16 h0, h1, h2, h3, l0, l1, l2, l3;
        split_bf16(o4.x, h0, l0); split_bf16(o4.y, h1, l1);
        split_bf16(o4.z, h2, l2); split_bf16(o4.w, h3, l3);
        uint2 hp, lp;
        *(__nv_bfloat162*)&hp.x = __halves2bfloat162(h0, h1);
        *(__nv_bfloat162*)&hp.y = __halves2bfloat162(h2, h3);
        *(__nv_bfloat162*)&lp.x = __halves2bfloat162(l0, l1);
        *(__nv_bfloat162*)&lp.y = __halves2bfloat162(l2, l3);
        size_t rb = (size_t)row * (3 * NU);
        int col = tid * 4;
        *(uint2*)(Ocvt + rb + col)            = hp;
        *(uint2*)(Ocvt + rb + NU + col)       = hp;
        *(uint2*)(Ocvt + rb + 2 * NU + col)   = lp;
    }
}

// ---------------------------------------------------------------------------
// Host orchestration (graph-capturable: kernel launches only)
// ---------------------------------------------------------------------------
extern "C" void kernel_launch(void* const* d_in, const int* in_sizes, int n_in,
                              void* d_out, int out_size)
{
    (void)in_sizes; (void)n_in; (void)out_size;

    const float* x     = (const float*)d_in[0];
    const float* Win   = (const float*)d_in[1];
    const float* bin   = (const float*)d_in[2];
    const float* ln1_g = (const float*)d_in[3];
    const float* ln1_b = (const float*)d_in[4];
    const float* Wq    = (const float*)d_in[5];
    const float* bq    = (const float*)d_in[6];
    const float* Wk    = (const float*)d_in[7];
    const float* bk    = (const float*)d_in[8];
    const float* Wv    = (const float*)d_in[9];
    const float* bv    = (const float*)d_in[10];
    const float* Wo    = (const float*)d_in[11];
    const float* bo    = (const float*)d_in[12];
    const float* ln2_g = (const float*)d_in[13];
    const float* ln2_b = (const float*)d_in[14];
    const float* W1    = (const float*)d_in[15];
    const float* b1    = (const float*)d_in[16];
    const float* W2    = (const float*)d_in[17];
    const float* b2    = (const float*)d_in[18];
    const float* lno_g = (const float*)d_in[19];
    const float* lno_b = (const float*)d_in[20];
    float* out = (float*)d_out;

    float *e, *bqkv;
    __nv_bfloat16 *xc, *ec, *cc, *hc, *Winc, *Wqkvc, *Woc, *W1c, *W2c;
    __nv_bfloat16 *qs, *ks, *vt;
    cudaGetSymbolAddress((void**)&e,    g_e);
    cudaGetSymbolAddress((void**)&bqkv, g_bqkv);
    cudaGetSymbolAddress((void**)&xc,   g_xcvt);
    cudaGetSymbolAddress((void**)&ec,   g_ecvt);
    cudaGetSymbolAddress((void**)&cc,   g_ccvt);
    cudaGetSymbolAddress((void**)&hc,   g_hcvt);
    cudaGetSymbolAddress((void**)&Winc,  g_Winc);
    cudaGetSymbolAddress((void**)&Wqkvc, g_Wqkvc);
    cudaGetSymbolAddress((void**)&Woc,   g_Woc);
    cudaGetSymbolAddress((void**)&W1c,   g_W1c);
    cudaGetSymbolAddress((void**)&W2c,   g_W2c);
    cudaGetSymbolAddress((void**)&qs,   g_qs);
    cudaGetSymbolAddress((void**)&ks,   g_ks);
    cudaGetSymbolAddress((void**)&vt,   g_vt);

    cudaFuncSetAttribute(mma_gemm<0>, cudaFuncAttributeMaxDynamicSharedMemorySize, GEMM_DSMEM);
    cudaFuncSetAttribute(mma_gemm<1>, cudaFuncAttributeMaxDynamicSharedMemorySize, GEMM_DSMEM);
    cudaFuncSetAttribute(mma_gemm<2>, cudaFuncAttributeMaxDynamicSharedMemorySize, GEMM_DSMEM);
    cudaFuncSetAttribute(mma_gemm<3>, cudaFuncAttributeMaxDynamicSharedMemorySize, GEMM_DSMEM);
    cudaFuncSetAttribute(flash_attn,  cudaFuncAttributeMaxDynamicSharedMemorySize, FA_DSMEM);

    // operand conversions (every launch; deterministic)
    {
        int t;
        t = NU * IDIM;          convert_B_kernel<<<(t + 255) / 256, 256>>>(Win, Winc, IDIM, t);
        for (int i = 0; i < NLAYERS; i++) {
            const size_t lb = (size_t)i * QKVW * 3 * NU;
            int tt = NU * NU;
            convert_B_kernel<<<(tt + 255) / 256, 256>>>(Wq + (size_t)i * NU * NU, Wqkvc + lb, NU, tt);
            convert_B_kernel<<<(tt + 255) / 256, 256>>>(Wk + (size_t)i * NU * NU, Wqkvc + lb + (size_t)NU * 3 * NU, NU, tt);
            convert_B_kernel<<<(tt + 255) / 256, 256>>>(Wv + (size_t)i * NU * NU, Wqkvc + lb + (size_t)2 * NU * 3 * NU, NU, tt);
        }
        t = NLAYERS * NU * NU;  convert_B_kernel<<<(t + 255) / 256, 256>>>(Wo, Woc, NU, t);
        t = NLAYERS * EU * NU;  convert_B_kernel<<<(t + 255) / 256, 256>>>(W1, W1c, NU, t);
        t = NLAYERS * NU * EU;  convert_B_kernel<<<(t + 255) / 256, 256>>>(W2, W2c, EU, t);
        t = TOK * IDIM;         convert_A_kernel<<<(t + 255) / 256, 256>>>(x, xc, IDIM, t);
        t = NLAYERS * QKVW;     pack_bqkv_kernel<<<(t + 255) / 256, 256>>>(bq, bk, bv, bqkv);
    }

    dim3 g512 (NU   / 128, TOK / 128);   // (4, 64)
    dim3 gqkv (QKVW / 128, TOK / 128);   // (12, 64)
    dim3 g2048(EU   / 128, TOK / 128);   // (16, 64)
    dim3 gflash(SEQ / 128, BH);          // (8, 64)

    // input projection: e = x @ Win^T + bin
    mma_gemm<0><<<g512, 256, GEMM_DSMEM>>>(xc, Winc, bin, nullptr, e, nullptr,
                                           nullptr, nullptr, nullptr, NU, 3 * IDIM);

    for (int i = 0; i < NLAYERS; i++) {
        const size_t wqkv = (size_t)i * QKVW * 3 * NU;
        const size_t wo   = (size_t)i * NU * 3 * NU;
        const size_t w1o  = (size_t)i * EU * 3 * NU;
        const size_t w2o  = (size_t)i * NU * 3 * EU;

        ln_kernel<true><<<TOK, 128>>>(e, ln1_g + i * NU, ln1_b + i * NU, e, ec);

        // fused qkv GEMM with direct attention-operand epilogue
        mma_gemm<3><<<gqkv, 256, GEMM_DSMEM>>>(ec, Wqkvc + wqkv, bqkv + i * QKVW, nullptr,
                                               nullptr, nullptr, qs, ks, vt, QKVW, 3 * NU);

        // fused attention
        flash_attn<<<gflash, 256, FA_DSMEM>>>(qs, ks, vt, cc);

        // e = e + ctx @ Wo^T + bo
        mma_gemm<1><<<g512, 256, GEMM_DSMEM>>>(cc, Woc + wo, bo + i * NU, e, e, nullptr,
                                               nullptr, nullptr, nullptr, NU, 3 * NU);

        ln_kernel<true><<<TOK, 128>>>(e, ln2_g + i * NU, ln2_b + i * NU, e, ec);

        // h = relu(e @ W1^T + b1) -> split bf16
        mma_gemm<2><<<g2048, 256, GEMM_DSMEM>>>(ec, W1c + w1o, b1 + (size_t)i * EU, nullptr,
                                                nullptr, hc, nullptr, nullptr, nullptr, EU, 3 * NU);
        // e = e + h @ W2^T + b2
        mma_gemm<1><<<g512, 256, GEMM_DSMEM>>>(hc, W2c + w2o, b2 + i * NU, e, e, nullptr,
                                               nullptr, nullptr, nullptr, NU, 3 * EU);
    }

    ln_kernel<false><<<TOK, 128>>>(e, lno_g, lno_b, out, nullptr);
}

// round 13
// speedup vs baseline: 1.0735x; 1.0735x over previous
#include <cuda_runtime.h>
#include <cuda_bf16.h>
#include <math.h>
#include <stdint.h>

// ---------------------------------------------------------------------------
// Problem constants
// ---------------------------------------------------------------------------
#define TOK      8192
#define IDIM     256
#define NU       512
#define EU       2048
#define NLAYERS  4
#define HEADS    8
#define DK       64
#define SEQ      1024
#define NBATCH   8
#define QKVW     1536
#define BH       (NBATCH * HEADS)   // 64

// ---------------------------------------------------------------------------
// Scratch (static device memory; allocation APIs are forbidden)
// ---------------------------------------------------------------------------
__device__ float g_e[TOK * NU];

// split-bf16 operand buffers (K-concat: activations [hi|hi|lo], weights [hi|lo|hi])
__device__ __nv_bfloat16 g_xcvt [TOK * 3 * IDIM];
__device__ __nv_bfloat16 g_ecvt [TOK * 3 * NU];
__device__ __nv_bfloat16 g_ccvt [TOK * 3 * NU];
__device__ __nv_bfloat16 g_hcvt [TOK * 3 * EU];

__device__ __nv_bfloat16 g_Winc  [NU * 3 * IDIM];
__device__ __nv_bfloat16 g_Wqkvc [NLAYERS * QKVW * 3 * NU];
__device__ __nv_bfloat16 g_Woc   [NLAYERS * NU * 3 * NU];
__device__ __nv_bfloat16 g_W1c   [NLAYERS * EU * 3 * NU];
__device__ __nv_bfloat16 g_W2c   [NLAYERS * NU * 3 * EU];
__device__ float         g_bqkv  [NLAYERS * QKVW];

// attention operands, 2-slab [hi|lo] layouts
__device__ __nv_bfloat16 g_qs [BH * SEQ * 128];        // [bh][t][hi64|lo64] (scaled)
__device__ __nv_bfloat16 g_ks [BH * SEQ * 128];        // [bh][t][hi64|lo64]
__device__ __nv_bfloat16 g_vt [BH * DK * 2 * SEQ];     // [bh][d][hi@s | lo@1024+s]

// ---------------------------------------------------------------------------
// split helpers
// ---------------------------------------------------------------------------
__device__ __forceinline__ void split_bf16(float f, __nv_bfloat16& hi, __nv_bfloat16& lo) {
    hi = __float2bfloat16(f);
    lo = __float2bfloat16(f - __bfloat162float(hi));
}
__device__ __forceinline__ uint32_t packbf(float a, float b) {
    __nv_bfloat162 t = __halves2bfloat162(__float2bfloat16(a), __float2bfloat16(b));
    return *(uint32_t*)&t;
}
__device__ __forceinline__ float lof(float a) {
    return a - __bfloat162float(__float2bfloat16(a));
}

// weights: out row = [hi | lo | hi], row width 3K
__global__ void convert_B_kernel(const float* __restrict__ W, __nv_bfloat16* __restrict__ out,
                                 int K, int total) {
    int idx = blockIdx.x * 256 + threadIdx.x;
    if (idx >= total) return;
    int n = idx / K, k = idx - n * K;
    __nv_bfloat16 hi, lo;
    split_bf16(W[idx], hi, lo);
    size_t base = (size_t)n * 3 * K;
    out[base + k] = hi;
    out[base + K + k] = lo;
    out[base + 2 * K + k] = hi;
}

// activations: out row = [hi | hi | lo]
__global__ void convert_A_kernel(const float* __restrict__ A, __nv_bfloat16* __restrict__ out,
                                 int K, int total) {
    int idx = blockIdx.x * 256 + threadIdx.x;
    if (idx >= total) return;
    int n = idx / K, k = idx - n * K;
    __nv_bfloat16 hi, lo;
    split_bf16(A[idx], hi, lo);
    size_t base = (size_t)n * 3 * K;
    out[base + k] = hi;
    out[base + K + k] = hi;
    out[base + 2 * K + k] = lo;
}

// pack per-layer q|k|v biases into 1536-wide rows
__global__ void pack_bqkv_kernel(const float* __restrict__ bq, const float* __restrict__ bk,
                                 const float* __restrict__ bv, float* __restrict__ out) {
    int i = blockIdx.x * 256 + threadIdx.x;
    if (i >= NLAYERS * QKVW) return;
    int l = i / QKVW, c = i - l * QKVW;
    float v = (c < NU) ? bq[l * NU + c]
            : (c < 2 * NU) ? bk[l * NU + c - NU]
            : bv[l * NU + c - 2 * NU];
    out[i] = v;
}

// ---------------------------------------------------------------------------
// mma.sync common pieces
// ---------------------------------------------------------------------------
#define STAGE_BYTES 32768
#define GEMM_DSMEM  (2 * STAGE_BYTES)
#define FA_STAGE    65536          // Khi 16K | Klo 16K | V 4x8K
#define FA_DSMEM    (32768 + 2 * FA_STAGE)   // Q 32K + 2 stages = 160K

__device__ __forceinline__ uint32_t smem_u32(const void* p) {
    uint32_t a;
    asm("{ .reg .u64 t; cvta.to.shared.u64 t, %1; cvt.u32.u64 %0, t; }" : "=r"(a) : "l"(p));
    return a;
}

#define CP_ASYNC16(dst, src) \
    asm volatile("cp.async.cg.shared.global [%0], [%1], 16;" :: "r"(dst), "l"(src) : "memory")
#define CP_COMMIT() asm volatile("cp.async.commit_group;" ::: "memory")
#define CP_WAIT1()  asm volatile("cp.async.wait_group 1;" ::: "memory")

#define LDMATRIX_X4(r0, r1, r2, r3, addr) \
    asm volatile("ldmatrix.sync.aligned.m8n8.x4.shared.b16 {%0,%1,%2,%3}, [%4];" \
        : "=r"(r0), "=r"(r1), "=r"(r2), "=r"(r3) : "r"(addr))

__device__ __forceinline__ void mma16816(float* d, const uint32_t* a, const uint32_t* b) {
    asm volatile(
        "mma.sync.aligned.m16n8k16.row.col.f32.bf16.bf16.f32 "
        "{%0,%1,%2,%3}, {%4,%5,%6,%7}, {%8,%9}, {%0,%1,%2,%3};"
        : "+f"(d[0]), "+f"(d[1]), "+f"(d[2]), "+f"(d[3])
        : "r"(a[0]), "r"(a[1]), "r"(a[2]), "r"(a[3]), "r"(b[0]), "r"(b[1]));
}

// ---------------------------------------------------------------------------
// Linear GEMM, 2-stage cp.async (verified R10 datapath): C = A @ B^T
// EP: 0 = fp32 out, 1 = fp32 + residual, 2 = relu + split-bf16 out (A-style)
//     3 = fused qkv epilogue: write per-head attention operand layouts
// ---------------------------------------------------------------------------
template<int EP>
__global__ __launch_bounds__(256) void mma_gemm(
    const __nv_bfloat16* __restrict__ A, const __nv_bfloat16* __restrict__ B,
    const float* __restrict__ bias, const float* __restrict__ res,
    float* __restrict__ Cf, __nv_bfloat16* __restrict__ Cb,
    __nv_bfloat16* __restrict__ q_out, __nv_bfloat16* __restrict__ k_out,
    __nv_bfloat16* __restrict__ v_out,
    int N, int Kp)
{
    extern __shared__ __align__(16) char dsm[];
    const uint32_t sbase = smem_u32(dsm);

    const int tid  = threadIdx.x;
    const int wid  = tid >> 5;
    const int lane = tid & 31;
    const int g    = lane >> 2;
    const int cq   = lane & 3;
    const int lr   = lane & 15;
    const int lc   = lane >> 4;
    const int wm   = wid & 3;
    const int wn   = wid >> 2;
    const int n0   = blockIdx.x * 128;
    const int m0   = blockIdx.y * 128;

    const __nv_bfloat16* Ap = A + (size_t)m0 * Kp;
    const __nv_bfloat16* Bp = B + (size_t)n0 * Kp;
    const int nchunk = Kp >> 6;

    float acc[2][8][4];
#pragma unroll
    for (int mi = 0; mi < 2; mi++)
#pragma unroll
        for (int ni = 0; ni < 8; ni++)
#pragma unroll
            for (int r = 0; r < 4; r++) acc[mi][ni][r] = 0.0f;

    auto load_stage = [&](int c, int stage) {
        const int k0 = c << 6;
        const uint32_t sA = sbase + stage * STAGE_BYTES;
        const uint32_t sB = sA + 16384;
#pragma unroll
        for (int i = 0; i < 4; i++) {
            int lin = tid + i * 256;
            int r   = lin >> 3;
            int c16 = lin & 7;
            uint32_t off = (uint32_t)(r * 128 + ((c16 ^ (r & 7)) * 16));
            CP_ASYNC16(sA + off, (const void*)(Ap + (size_t)r * Kp + k0 + c16 * 8));
            CP_ASYNC16(sB + off, (const void*)(Bp + (size_t)r * Kp + k0 + c16 * 8));
        }
    };

    load_stage(0, 0);
    CP_COMMIT();

    for (int c = 0; c < nchunk; c++) {
        const int cur = c & 1;
        if (c + 1 < nchunk) load_stage(c + 1, cur ^ 1);
        CP_COMMIT();
        CP_WAIT1();
        __syncthreads();

        const uint32_t sA = sbase + cur * STAGE_BYTES;
        const uint32_t sB = sA + 16384;

#pragma unroll
        for (int ks = 0; ks < 4; ks++) {
            const int kblk = ks * 2 + lc;
            uint32_t afr[2][4], bfr[4][4];
#pragma unroll
            for (int mi = 0; mi < 2; mi++) {
                int row = wm * 32 + mi * 16 + lr;
                uint32_t addr = sA + (uint32_t)(row * 128 + ((kblk ^ (row & 7)) * 16));
                LDMATRIX_X4(afr[mi][0], afr[mi][1], afr[mi][2], afr[mi][3], addr);
            }
#pragma unroll
            for (int p = 0; p < 4; p++) {
                int row = wn * 64 + p * 16 + lr;
                uint32_t addr = sB + (uint32_t)(row * 128 + ((kblk ^ (row & 7)) * 16));
                LDMATRIX_X4(bfr[p][0], bfr[p][1], bfr[p][2], bfr[p][3], addr);
            }
#pragma unroll
            for (int mi = 0; mi < 2; mi++)
#pragma unroll
                for (int ni = 0; ni < 8; ni++) {
                    const int p = ni >> 1, o = ni & 1;
                    uint32_t b2[2] = { bfr[p][o], bfr[p][2 + o] };
                    mma16816(acc[mi][ni], afr[mi], b2);
                }
        }
        __syncthreads();
    }

#pragma unroll
    for (int mi = 0; mi < 2; mi++) {
#pragma unroll
        for (int half = 0; half < 2; half++) {
            const int m = m0 + wm * 32 + mi * 16 + g + half * 8;
#pragma unroll
            for (int ni = 0; ni < 8; ni++) {
                const int n = n0 + wn * 64 + ni * 8 + 2 * cq;
                float2 bv = *(const float2*)(bias + n);
                float v0 = acc[mi][ni][half * 2 + 0] + bv.x;
                float v1 = acc[mi][ni][half * 2 + 1] + bv.y;
                if (EP == 2) {
                    v0 = fmaxf(v0, 0.f); v1 = fmaxf(v1, 0.f);
                    __nv_bfloat16 h0, h1, l0, l1;
                    split_bf16(v0, h0, l0); split_bf16(v1, h1, l1);
                    uint32_t hp, lp;
                    *(__nv_bfloat162*)&hp = __halves2bfloat162(h0, h1);
                    *(__nv_bfloat162*)&lp = __halves2bfloat162(l0, l1);
                    size_t rb = (size_t)m * 3 * N;
                    *(uint32_t*)(Cb + rb + n)         = hp;
                    *(uint32_t*)(Cb + rb + N + n)     = hp;
                    *(uint32_t*)(Cb + rb + 2 * N + n) = lp;
                } else if (EP == 3) {
                    // fused qkv epilogue: n in [0,1536) = q|k|v sections
                    const int sec = n >> 9;            // 0=q 1=k 2=v
                    const int hh  = (n >> 6) & 7;      // head
                    const int d   = n & 63;            // dim within head (even)
                    const int t   = m & (SEQ - 1);
                    const int bh  = (m >> 10) * HEADS + hh;
                    if (sec == 0) {
                        float q0 = v0 * 0.125f, q1 = v1 * 0.125f;
                        __nv_bfloat16 h0, h1, l0, l1;
                        split_bf16(q0, h0, l0); split_bf16(q1, h1, l1);
                        uint32_t hp, lp;
                        *(__nv_bfloat162*)&hp = __halves2bfloat162(h0, h1);
                        *(__nv_bfloat162*)&lp = __halves2bfloat162(l0, l1);
                        __nv_bfloat16* qb = q_out + ((size_t)bh * SEQ + t) * 128 + d;
                        *(uint32_t*)(qb)      = hp;
                        *(uint32_t*)(qb + 64) = lp;
                    } else if (sec == 1) {
                        __nv_bfloat16 h0, h1, l0, l1;
                        split_bf16(v0, h0, l0); split_bf16(v1, h1, l1);
                        uint32_t hp, lp;
                        *(__nv_bfloat162*)&hp = __halves2bfloat162(h0, h1);
                        *(__nv_bfloat162*)&lp = __halves2bfloat162(l0, l1);
                        __nv_bfloat16* kb = k_out + ((size_t)bh * SEQ + t) * 128 + d;
                        *(uint32_t*)(kb)      = hp;
                        *(uint32_t*)(kb + 64) = lp;
                    } else {
                        __nv_bfloat16 h0, h1, l0, l1;
                        split_bf16(v0, h0, l0); split_bf16(v1, h1, l1);
                        __nv_bfloat16* vb0 = v_out + ((size_t)bh * DK + d) * (2 * SEQ) + t;
                        __nv_bfloat16* vb1 = vb0 + 2 * SEQ;
                        vb0[0]   = h0; vb0[SEQ] = l0;
                        vb1[0]   = h1; vb1[SEQ] = l1;
                    }
                } else {
                    if (EP == 1) {
                        float2 rv = *(const float2*)(res + (size_t)m * N + n);
                        v0 += rv.x; v1 += rv.y;
                    }
                    *(float2*)(Cf + (size_t)m * N + n) = make_float2(v0, v1);
                }
            }
        }
    }
}

// ---------------------------------------------------------------------------
// Fused flash attention (no-max softmax) — verified in R10, unchanged.
// ---------------------------------------------------------------------------
__global__ __launch_bounds__(256) void flash_attn(
    const __nv_bfloat16* __restrict__ qs, const __nv_bfloat16* __restrict__ ks,
    const __nv_bfloat16* __restrict__ vt, __nv_bfloat16* __restrict__ Ccvt)
{
    extern __shared__ __align__(16) char dsm[];
    const uint32_t sb  = smem_u32(dsm);
    const uint32_t Qhi = sb;               // [128][64] bf16
    const uint32_t Qlo = sb + 16384;
    const uint32_t ST0 = sb + 32768;       // stage: Khi 16K | Klo 16K | V 4x8K

    const int tid  = threadIdx.x;
    const int wid  = tid >> 5;
    const int lane = tid & 31;
    const int g    = lane >> 2;
    const int cq   = lane & 3;
    const int lr   = lane & 15;
    const int lc   = lane >> 4;
    const int q0   = blockIdx.x * 128;
    const int bh   = blockIdx.y;
    const int b    = bh >> 3, h = bh & 7;

    // --- load Q (once) ---
#pragma unroll
    for (int i = 0; i < 8; i++) {
        int id = tid + i * 256;
        int slab = id >> 10, r = (id >> 3) & 127, u = id & 7;
        const __nv_bfloat16* src = qs + ((size_t)bh * SEQ + q0 + r) * 128 + slab * 64 + u * 8;
        CP_ASYNC16((slab ? Qlo : Qhi) + (uint32_t)(r * 128 + ((u ^ (r & 7)) * 16)), src);
    }

    auto load_kv = [&](int st, uint32_t stage) {
        const int s0 = st * 128;
#pragma unroll
        for (int i = 0; i < 8; i++) {          // K: 2 slabs x 128 rows x 8 units
            int id = tid + i * 256;
            int slab = id >> 10, r = (id >> 3) & 127, u = id & 7;
            const __nv_bfloat16* src = ks + ((size_t)bh * SEQ + s0 + r) * 128 + slab * 64 + u * 8;
            CP_ASYNC16(stage + slab * 16384 + (uint32_t)(r * 128 + ((u ^ (r & 7)) * 16)), src);
        }
#pragma unroll
        for (int i = 0; i < 8; i++) {          // V: 4 slabs x 64 rows x 8 units
            int id = tid + i * 256;
            int slab = id >> 9;                // 0:hi_a 1:hi_b 2:lo_a 3:lo_b
            int r = (id >> 3) & 63, u = id & 7;
            int col = (slab >> 1) * SEQ + s0 + (slab & 1) * 64 + u * 8;
            const __nv_bfloat16* src = vt + ((size_t)bh * DK + r) * (2 * SEQ) + col;
            CP_ASYNC16(stage + 32768 + slab * 8192 + (uint32_t)(r * 128 + ((u ^ (r & 7)) * 16)), src);
        }
    };

    load_kv(0, ST0);
    CP_COMMIT();

    float oacc[8][4];
#pragma unroll
    for (int ni = 0; ni < 8; ni++)
#pragma unroll
        for (int r = 0; r < 4; r++) oacc[ni][r] = 0.0f;
    float lsum0 = 0.0f, lsum1 = 0.0f;

    const int arow = wid * 16 + lr;
    const uint32_t aoff = (uint32_t)(arow * 128);

    for (int st = 0; st < 8; st++) {
        const int cur = st & 1;
        if (st + 1 < 8) load_kv(st + 1, ST0 + (cur ^ 1) * FA_STAGE);
        CP_COMMIT();
        CP_WAIT1();
        __syncthreads();

        const uint32_t Kh = ST0 + cur * FA_STAGE;
        const uint32_t Kl = Kh + 16384;
        const uint32_t Vb = Kh + 32768;

        // ---- S = Q K^T (3 logical slabs) ----
        float sacc[16][4];
#pragma unroll
        for (int ni = 0; ni < 16; ni++)
#pragma unroll
            for (int r = 0; r < 4; r++) sacc[ni][r] = 0.0f;

        uint32_t ahi[4][4];
#pragma unroll
        for (int j = 0; j < 4; j++) {
            const int kblk = j * 2 + lc;
            const uint32_t asw = (uint32_t)((kblk ^ (arow & 7)) * 16);
            LDMATRIX_X4(ahi[j][0], ahi[j][1], ahi[j][2], ahi[j][3], Qhi + aoff + asw);
#pragma unroll
            for (int p = 0; p < 8; p++) {
                int row = p * 16 + lr;
                uint32_t addr = Kh + (uint32_t)(row * 128 + ((kblk ^ (row & 7)) * 16));
                uint32_t bfr[4];
                LDMATRIX_X4(bfr[0], bfr[1], bfr[2], bfr[3], addr);
#pragma unroll
                for (int o = 0; o < 2; o++) {
                    uint32_t b2[2] = { bfr[o], bfr[2 + o] };
                    mma16816(sacc[2 * p + o], ahi[j], b2);
                }
            }
#pragma unroll
            for (int p = 0; p < 8; p++) {
                int row = p * 16 + lr;
                uint32_t addr = Kl + (uint32_t)(row * 128 + ((kblk ^ (row & 7)) * 16));
                uint32_t bfr[4];
                LDMATRIX_X4(bfr[0], bfr[1], bfr[2], bfr[3], addr);
#pragma unroll
                for (int o = 0; o < 2; o++) {
                    uint32_t b2[2] = { bfr[o], bfr[2 + o] };
                    mma16816(sacc[2 * p + o], ahi[j], b2);
                }
            }
        }
#pragma unroll
        for (int j = 0; j < 4; j++) {
            const int kblk = j * 2 + lc;
            const uint32_t asw = (uint32_t)((kblk ^ (arow & 7)) * 16);
            uint32_t alo[4];
            LDMATRIX_X4(alo[0], alo[1], alo[2], alo[3], Qlo + aoff + asw);
#pragma unroll
            for (int p = 0; p < 8; p++) {
                int row = p * 16 + lr;
                uint32_t addr = Kh + (uint32_t)(row * 128 + ((kblk ^ (row & 7)) * 16));
                uint32_t bfr[4];
                LDMATRIX_X4(bfr[0], bfr[1], bfr[2], bfr[3], addr);
#pragma unroll
                for (int o = 0; o < 2; o++) {
                    uint32_t b2[2] = { bfr[o], bfr[2 + o] };
                    mma16816(sacc[2 * p + o], alo, b2);
                }
            }
        }

        // ---- P = exp(S); accumulate row sums; build hi A-fragments ----
#pragma unroll
        for (int ni = 0; ni < 16; ni++) {
            float p0 = __expf(sacc[ni][0]);
            float p1 = __expf(sacc[ni][1]);
            float p2 = __expf(sacc[ni][2]);
            float p3 = __expf(sacc[ni][3]);
            lsum0 += p0 + p1;
            lsum1 += p2 + p3;
            sacc[ni][0] = p0; sacc[ni][1] = p1;
            sacc[ni][2] = p2; sacc[ni][3] = p3;
        }
        uint32_t phi[8][4];
#pragma unroll
        for (int jj = 0; jj < 8; jj++) {
            phi[jj][0] = packbf(sacc[2 * jj][0],     sacc[2 * jj][1]);
            phi[jj][1] = packbf(sacc[2 * jj][2],     sacc[2 * jj][3]);
            phi[jj][2] = packbf(sacc[2 * jj + 1][0], sacc[2 * jj + 1][1]);
            phi[jj][3] = packbf(sacc[2 * jj + 1][2], sacc[2 * jj + 1][3]);
        }

        // ---- ctx += P V^T (3 logical slabs) ----
#pragma unroll
        for (int jj = 0; jj < 8; jj++) {
            const int kblk = (jj & 3) * 2 + lc;
            const uint32_t baseH = Vb + (jj >> 2) * 8192;
            const uint32_t baseL = Vb + 16384 + (jj >> 2) * 8192;
            // P_hi x V_hi
#pragma unroll
            for (int p = 0; p < 4; p++) {
                int row = p * 16 + lr;
                uint32_t addr = baseH + (uint32_t)(row * 128 + ((kblk ^ (row & 7)) * 16));
                uint32_t bfr[4];
                LDMATRIX_X4(bfr[0], bfr[1], bfr[2], bfr[3], addr);
#pragma unroll
                for (int o = 0; o < 2; o++) {
                    uint32_t b2[2] = { bfr[o], bfr[2 + o] };
                    mma16816(oacc[2 * p + o], phi[jj], b2);
                }
            }
            // P_hi x V_lo
#pragma unroll
            for (int p = 0; p < 4; p++) {
                int row = p * 16 + lr;
                uint32_t addr = baseL + (uint32_t)(row * 128 + ((kblk ^ (row & 7)) * 16));
                uint32_t bfr[4];
                LDMATRIX_X4(bfr[0], bfr[1], bfr[2], bfr[3], addr);
#pragma unroll
                for (int o = 0; o < 2; o++) {
                    uint32_t b2[2] = { bfr[o], bfr[2 + o] };
                    mma16816(oacc[2 * p + o], phi[jj], b2);
                }
            }
            // P_lo x V_hi
            uint32_t plo[4];
            plo[0] = packbf(lof(sacc[2 * jj][0]),     lof(sacc[2 * jj][1]));
            plo[1] = packbf(lof(sacc[2 * jj][2]),     lof(sacc[2 * jj][3]));
            plo[2] = packbf(lof(sacc[2 * jj + 1][0]), lof(sacc[2 * jj + 1][1]));
            plo[3] = packbf(lof(sacc[2 * jj + 1][2]), lof(sacc[2 * jj + 1][3]));
#pragma unroll
            for (int p = 0; p < 4; p++) {
                int row = p * 16 + lr;
                uint32_t addr = baseH + (uint32_t)(row * 128 + ((kblk ^ (row & 7)) * 16));
                uint32_t bfr[4];
                LDMATRIX_X4(bfr[0], bfr[1], bfr[2], bfr[3], addr);
#pragma unroll
                for (int o = 0; o < 2; o++) {
                    uint32_t b2[2] = { bfr[o], bfr[2 + o] };
                    mma16816(oacc[2 * p + o], plo, b2);
                }
            }
        }
        __syncthreads();
    }

    // row-sum reduction over the quad (cq lanes)
    lsum0 += __shfl_xor_sync(0xffffffffu, lsum0, 1);
    lsum0 += __shfl_xor_sync(0xffffffffu, lsum0, 2);
    lsum1 += __shfl_xor_sync(0xffffffffu, lsum1, 1);
    lsum1 += __shfl_xor_sync(0xffffffffu, lsum1, 2);
    const float inv0 = 1.0f / lsum0;
    const float inv1 = 1.0f / lsum1;

    // epilogue: split write into g_ccvt [tok][3*512] at cols h*64 + n
#pragma unroll
    for (int half = 0; half < 2; half++) {
        const int m = q0 + wid * 16 + g + half * 8;
        const size_t tok = (size_t)b * SEQ + m;
        const size_t rb = tok * (3 * NU);
        const float inv = half ? inv1 : inv0;
#pragma unroll
        for (int ni = 0; ni < 8; ni++) {
            const int col = h * DK + ni * 8 + 2 * cq;
            float v0 = oacc[ni][half * 2 + 0] * inv;
            float v1 = oacc[ni][half * 2 + 1] * inv;
            __nv_bfloat16 h0, h1, l0, l1;
            split_bf16(v0, h0, l0); split_bf16(v1, h1, l1);
            uint32_t hp, lp;
            *(__nv_bfloat162*)&hp = __halves2bfloat162(h0, h1);
            *(__nv_bfloat162*)&lp = __halves2bfloat162(l0, l1);
            *(uint32_t*)(Ccvt + rb + col)          = hp;
            *(uint32_t*)(Ccvt + rb + NU + col)     = hp;
            *(uint32_t*)(Ccvt + rb + 2 * NU + col) = lp;
        }
    }
}

// ---------------------------------------------------------------------------
// LayerNorm over rows of 512; optionally also writes split-bf16 (A-style)
// ---------------------------------------------------------------------------
template<bool CVT>
__global__ __launch_bounds__(128) void ln_kernel(
    const float* __restrict__ X, const float* __restrict__ gamma,
    const float* __restrict__ beta, float* __restrict__ O,
    __nv_bfloat16* __restrict__ Ocvt)
{
    __shared__ float red[4];
    const int row = blockIdx.x;
    const int tid = threadIdx.x;

    float4 v = *(const float4*)(X + (size_t)row * NU + tid * 4);
    float s = v.x + v.y + v.z + v.w;
#pragma unroll
    for (int o = 16; o > 0; o >>= 1) s += __shfl_xor_sync(0xffffffffu, s, o);
    if ((tid & 31) == 0) red[tid >> 5] = s;
    __syncthreads();
    float mean = (red[0] + red[1] + red[2] + red[3]) * (1.0f / 512.0f);
    __syncthreads();

    float dx = v.x - mean, dy = v.y - mean, dz = v.z - mean, dw = v.w - mean;
    float sq = dx * dx + dy * dy + dz * dz + dw * dw;
#pragma unroll
    for (int o = 16; o > 0; o >>= 1) sq += __shfl_xor_sync(0xffffffffu, sq, o);
    if ((tid & 31) == 0) red[tid >> 5] = sq;
    __syncthreads();
    float var = (red[0] + red[1] + red[2] + red[3]) * (1.0f / 512.0f);
    float inv = rsqrtf(var + 1e-5f);

    float4 g = *(const float4*)(gamma + tid * 4);
    float4 b = *(const float4*)(beta  + tid * 4);
    float4 o4;
    o4.x = dx * inv * g.x + b.x;
    o4.y = dy * inv * g.y + b.y;
    o4.z = dz * inv * g.z + b.z;
    o4.w = dw * inv * g.w + b.w;
    *(float4*)(O + (size_t)row * NU + tid * 4) = o4;

    if (CVT) {
        __nv_bfloat16 h0, h1, h2, h3, l0, l1, l2, l3;
        split_bf16(o4.x, h0, l0); split_bf16(o4.y, h1, l1);
        split_bf16(o4.z, h2, l2); split_bf16(o4.w, h3, l3);
        uint2 hp, lp;
        *(__nv_bfloat162*)&hp.x = __halves2bfloat162(h0, h1);
        *(__nv_bfloat162*)&hp.y = __halves2bfloat162(h2, h3);
        *(__nv_bfloat162*)&lp.x = __halves2bfloat162(l0, l1);
        *(__nv_bfloat162*)&lp.y = __halves2bfloat162(l2, l3);
        size_t rb = (size_t)row * (3 * NU);
        int col = tid * 4;
        *(uint2*)(Ocvt + rb + col)            = hp;
        *(uint2*)(Ocvt + rb + NU + col)       = hp;
        *(uint2*)(Ocvt + rb + 2 * NU + col)   = lp;
    }
}

// ---------------------------------------------------------------------------
// Host orchestration (graph-capturable: kernel launches only)
// ---------------------------------------------------------------------------
extern "C" void kernel_launch(void* const* d_in, const int* in_sizes, int n_in,
                              void* d_out, int out_size)
{
    (void)in_sizes; (void)n_in; (void)out_size;

    const float* x     = (const float*)d_in[0];
    const float* Win   = (const float*)d_in[1];
    const float* bin   = (const float*)d_in[2];
    const float* ln1_g = (const float*)d_in[3];
    const float* ln1_b = (const float*)d_in[4];
    const float* Wq    = (const float*)d_in[5];
    const float* bq    = (const float*)d_in[6];
    const float* Wk    = (const float*)d_in[7];
    const float* bk    = (const float*)d_in[8];
    const float* Wv    = (const float*)d_in[9];
    const float* bv    = (const float*)d_in[10];
    const float* Wo    = (const float*)d_in[11];
    const float* bo    = (const float*)d_in[12];
    const float* ln2_g = (const float*)d_in[13];
    const float* ln2_b = (const float*)d_in[14];
    const float* W1    = (const float*)d_in[15];
    const float* b1    = (const float*)d_in[16];
    const float* W2    = (const float*)d_in[17];
    const float* b2    = (const float*)d_in[18];
    const float* lno_g = (const float*)d_in[19];
    const float* lno_b = (const float*)d_in[20];
    float* out = (float*)d_out;

    float *e, *bqkv;
    __nv_bfloat16 *xc, *ec, *cc, *hc, *Winc, *Wqkvc, *Woc, *W1c, *W2c;
    __nv_bfloat16 *qs, *ks, *vt;
    cudaGetSymbolAddress((void**)&e,    g_e);
    cudaGetSymbolAddress((void**)&bqkv, g_bqkv);
    cudaGetSymbolAddress((void**)&xc,   g_xcvt);
    cudaGetSymbolAddress((void**)&ec,   g_ecvt);
    cudaGetSymbolAddress((void**)&cc,   g_ccvt);
    cudaGetSymbolAddress((void**)&hc,   g_hcvt);
    cudaGetSymbolAddress((void**)&Winc,  g_Winc);
    cudaGetSymbolAddress((void**)&Wqkvc, g_Wqkvc);
    cudaGetSymbolAddress((void**)&Woc,   g_Woc);
    cudaGetSymbolAddress((void**)&W1c,   g_W1c);
    cudaGetSymbolAddress((void**)&W2c,   g_W2c);
    cudaGetSymbolAddress((void**)&qs,   g_qs);
    cudaGetSymbolAddress((void**)&ks,   g_ks);
    cudaGetSymbolAddress((void**)&vt,   g_vt);

    cudaFuncSetAttribute(mma_gemm<0>, cudaFuncAttributeMaxDynamicSharedMemorySize, GEMM_DSMEM);
    cudaFuncSetAttribute(mma_gemm<1>, cudaFuncAttributeMaxDynamicSharedMemorySize, GEMM_DSMEM);
    cudaFuncSetAttribute(mma_gemm<2>, cudaFuncAttributeMaxDynamicSharedMemorySize, GEMM_DSMEM);
    cudaFuncSetAttribute(mma_gemm<3>, cudaFuncAttributeMaxDynamicSharedMemorySize, GEMM_DSMEM);
    cudaFuncSetAttribute(flash_attn,  cudaFuncAttributeMaxDynamicSharedMemorySize, FA_DSMEM);

    // operand conversions (every launch; deterministic)
    {
        int t;
        t = NU * IDIM;          convert_B_kernel<<<(t + 255) / 256, 256>>>(Win, Winc, IDIM, t);
        for (int i = 0; i < NLAYERS; i++) {
            const size_t lb = (size_t)i * QKVW * 3 * NU;
            int tt = NU * NU;
            convert_B_kernel<<<(tt + 255) / 256, 256>>>(Wq + (size_t)i * NU * NU, Wqkvc + lb, NU, tt);
            convert_B_kernel<<<(tt + 255) / 256, 256>>>(Wk + (size_t)i * NU * NU, Wqkvc + lb + (size_t)NU * 3 * NU, NU, tt);
            convert_B_kernel<<<(tt + 255) / 256, 256>>>(Wv + (size_t)i * NU * NU, Wqkvc + lb + (size_t)2 * NU * 3 * NU, NU, tt);
        }
        t = NLAYERS * NU * NU;  convert_B_kernel<<<(t + 255) / 256, 256>>>(Wo, Woc, NU, t);
        t = NLAYERS * EU * NU;  convert_B_kernel<<<(t + 255) / 256, 256>>>(W1, W1c, NU, t);
        t = NLAYERS * NU * EU;  convert_B_kernel<<<(t + 255) / 256, 256>>>(W2, W2c, EU, t);
        t = TOK * IDIM;         convert_A_kernel<<<(t + 255) / 256, 256>>>(x, xc, IDIM, t);
        t = NLAYERS * QKVW;     pack_bqkv_kernel<<<(t + 255) / 256, 256>>>(bq, bk, bv, bqkv);
    }

    dim3 g512 (NU   / 128, TOK / 128);   // (4, 64)
    dim3 gqkv (QKVW / 128, TOK / 128);   // (12, 64)
    dim3 g2048(EU   / 128, TOK / 128);   // (16, 64)
    dim3 gflash(SEQ / 128, BH);          // (8, 64)

    // input projection: e = x @ Win^T + bin
    mma_gemm<0><<<g512, 256, GEMM_DSMEM>>>(xc, Winc, bin, nullptr, e, nullptr,
                                           nullptr, nullptr, nullptr, NU, 3 * IDIM);

    for (int i = 0; i < NLAYERS; i++) {
        const size_t wqkv = (size_t)i * QKVW * 3 * NU;
        const size_t wo   = (size_t)i * NU * 3 * NU;
        const size_t w1o  = (size_t)i * EU * 3 * NU;
        const size_t w2o  = (size_t)i * NU * 3 * EU;

        ln_kernel<true><<<TOK, 128>>>(e, ln1_g + i * NU, ln1_b + i * NU, e, ec);

        // fused qkv GEMM with direct attention-operand epilogue
        mma_gemm<3><<<gqkv, 256, GEMM_DSMEM>>>(ec, Wqkvc + wqkv, bqkv + i * QKVW, nullptr,
                                               nullptr, nullptr, qs, ks, vt, QKVW, 3 * NU);

        // fused attention
        flash_attn<<<gflash, 256, FA_DSMEM>>>(qs, ks, vt, cc);

        // e = e + ctx @ Wo^T + bo
        mma_gemm<1><<<g512, 256, GEMM_DSMEM>>>(cc, Woc + wo, bo + i * NU, e, e, nullptr,
                                               nullptr, nullptr, nullptr, NU, 3 * NU);

        ln_kernel<true><<<TOK, 128>>>(e, ln2_g + i * NU, ln2_b + i * NU, e, ec);

        // h = relu(e @ W1^T + b1) -> split bf16
        mma_gemm<2><<<g2048, 256, GEMM_DSMEM>>>(ec, W1c + w1o, b1 + (size_t)i * EU, nullptr,
                                                nullptr, hc, nullptr, nullptr, nullptr, EU, 3 * NU);
        // e = e + h @ W2^T + b2
        mma_gemm<1><<<g512, 256, GEMM_DSMEM>>>(hc, W2c + w2o, b2 + i * NU, e, e, nullptr,
                                               nullptr, nullptr, nullptr, NU, 3 * EU);
    }

    ln_kernel<false><<<TOK, 128>>>(e, lno_g, lno_b, out, nullptr);
}

// round 14
// speedup vs baseline: 1.0796x; 1.0057x over previous
#include <cuda_runtime.h>
#include <cuda_bf16.h>
#include <math.h>
#include <stdint.h>

// ---------------------------------------------------------------------------
// Problem constants
// ---------------------------------------------------------------------------
#define TOK      8192
#define IDIM     256
#define NU       512
#define EU       2048
#define NLAYERS  4
#define HEADS    8
#define DK       64
#define SEQ      1024
#define NBATCH   8
#define QKVW     1536
#define BH       (NBATCH * HEADS)   // 64

// ---------------------------------------------------------------------------
// Scratch (static device memory; allocation APIs are forbidden)
// ---------------------------------------------------------------------------
__device__ float g_e[TOK * NU];

// split-bf16 operand buffers (K-concat: activations [hi|hi|lo], weights [hi|lo|hi])
__device__ __nv_bfloat16 g_xcvt [TOK * 3 * IDIM];
__device__ __nv_bfloat16 g_ecvt [TOK * 3 * NU];
__device__ __nv_bfloat16 g_ccvt [TOK * 3 * NU];
__device__ __nv_bfloat16 g_hcvt [TOK * 3 * EU];

__device__ __nv_bfloat16 g_Winc  [NU * 3 * IDIM];
__device__ __nv_bfloat16 g_Wqkvc [NLAYERS * QKVW * 3 * NU];
__device__ __nv_bfloat16 g_Woc   [NLAYERS * NU * 3 * NU];
__device__ __nv_bfloat16 g_W1c   [NLAYERS * EU * 3 * NU];
__device__ __nv_bfloat16 g_W2c   [NLAYERS * NU * 3 * EU];
__device__ float         g_bqkv  [NLAYERS * QKVW];

// attention operands, 2-slab [hi|lo] layouts
__device__ __nv_bfloat16 g_qs [BH * SEQ * 128];        // [bh][t][hi64|lo64] (scaled)
__device__ __nv_bfloat16 g_ks [BH * SEQ * 128];        // [bh][t][hi64|lo64]
__device__ __nv_bfloat16 g_vt [BH * DK * 2 * SEQ];     // [bh][d][hi@s | lo@1024+s]

// ---------------------------------------------------------------------------
// split helpers
// ---------------------------------------------------------------------------
__device__ __forceinline__ void split_bf16(float f, __nv_bfloat16& hi, __nv_bfloat16& lo) {
    hi = __float2bfloat16(f);
    lo = __float2bfloat16(f - __bfloat162float(hi));
}
__device__ __forceinline__ uint32_t packbf(float a, float b) {
    __nv_bfloat162 t = __halves2bfloat162(__float2bfloat16(a), __float2bfloat16(b));
    return *(uint32_t*)&t;
}
__device__ __forceinline__ float lof(float a) {
    return a - __bfloat162float(__float2bfloat16(a));
}

// weights: out row = [hi | lo | hi], row width 3K
__global__ void convert_B_kernel(const float* __restrict__ W, __nv_bfloat16* __restrict__ out,
                                 int K, int total) {
    int idx = blockIdx.x * 256 + threadIdx.x;
    if (idx >= total) return;
    int n = idx / K, k = idx - n * K;
    __nv_bfloat16 hi, lo;
    split_bf16(W[idx], hi, lo);
    size_t base = (size_t)n * 3 * K;
    out[base + k] = hi;
    out[base + K + k] = lo;
    out[base + 2 * K + k] = hi;
}

// batched qkv weight conversion: all layers, all three matrices, one launch
__global__ void convert_qkv_kernel(const float* __restrict__ Wq, const float* __restrict__ Wk,
                                   const float* __restrict__ Wv, __nv_bfloat16* __restrict__ out) {
    const int per = NU * NU;
    int idx = blockIdx.x * 256 + threadIdx.x;
    if (idx >= NLAYERS * 3 * per) return;
    int mat = idx / per;
    int rem = idx - mat * per;
    int l = mat / 3, sec = mat - l * 3;
    int n = rem / NU, k = rem - n * NU;
    const float* W = (sec == 0) ? Wq : (sec == 1) ? Wk : Wv;
    __nv_bfloat16 hi, lo;
    split_bf16(W[(size_t)l * per + rem], hi, lo);
    size_t base = (size_t)l * QKVW * 3 * NU + (size_t)(sec * NU + n) * 3 * NU;
    out[base + k] = hi;
    out[base + NU + k] = lo;
    out[base + 2 * NU + k] = hi;
}

// activations: out row = [hi | hi | lo]
__global__ void convert_A_kernel(const float* __restrict__ A, __nv_bfloat16* __restrict__ out,
                                 int K, int total) {
    int idx = blockIdx.x * 256 + threadIdx.x;
    if (idx >= total) return;
    int n = idx / K, k = idx - n * K;
    __nv_bfloat16 hi, lo;
    split_bf16(A[idx], hi, lo);
    size_t base = (size_t)n * 3 * K;
    out[base + k] = hi;
    out[base + K + k] = hi;
    out[base + 2 * K + k] = lo;
}

// pack per-layer q|k|v biases into 1536-wide rows
__global__ void pack_bqkv_kernel(const float* __restrict__ bq, const float* __restrict__ bk,
                                 const float* __restrict__ bv, float* __restrict__ out) {
    int i = blockIdx.x * 256 + threadIdx.x;
    if (i >= NLAYERS * QKVW) return;
    int l = i / QKVW, c = i - l * QKVW;
    float v = (c < NU) ? bq[l * NU + c]
            : (c < 2 * NU) ? bk[l * NU + c - NU]
            : bv[l * NU + c - 2 * NU];
    out[i] = v;
}

// ---------------------------------------------------------------------------
// mma.sync common pieces
// ---------------------------------------------------------------------------
#define STAGE_BYTES 32768
#define GEMM_DSMEM  (2 * STAGE_BYTES)
#define FA_STAGE    32768          // Khi 8K | Klo 8K | Vhi 8K | Vlo 8K (64 s-rows)
#define FA_DSMEM    (32768 + 2 * FA_STAGE)   // Q 32K + 2 stages = 96K -> 2 CTAs/SM

__device__ __forceinline__ uint32_t smem_u32(const void* p) {
    uint32_t a;
    asm("{ .reg .u64 t; cvta.to.shared.u64 t, %1; cvt.u32.u64 %0, t; }" : "=r"(a) : "l"(p));
    return a;
}

#define CP_ASYNC16(dst, src) \
    asm volatile("cp.async.cg.shared.global [%0], [%1], 16;" :: "r"(dst), "l"(src) : "memory")
#define CP_COMMIT() asm volatile("cp.async.commit_group;" ::: "memory")
#define CP_WAIT1()  asm volatile("cp.async.wait_group 1;" ::: "memory")

#define LDMATRIX_X4(r0, r1, r2, r3, addr) \
    asm volatile("ldmatrix.sync.aligned.m8n8.x4.shared.b16 {%0,%1,%2,%3}, [%4];" \
        : "=r"(r0), "=r"(r1), "=r"(r2), "=r"(r3) : "r"(addr))

__device__ __forceinline__ void mma16816(float* d, const uint32_t* a, const uint32_t* b) {
    asm volatile(
        "mma.sync.aligned.m16n8k16.row.col.f32.bf16.bf16.f32 "
        "{%0,%1,%2,%3}, {%4,%5,%6,%7}, {%8,%9}, {%0,%1,%2,%3};"
        : "+f"(d[0]), "+f"(d[1]), "+f"(d[2]), "+f"(d[3])
        : "r"(a[0]), "r"(a[1]), "r"(a[2]), "r"(a[3]), "r"(b[0]), "r"(b[1]));
}

// ---------------------------------------------------------------------------
// Linear GEMM, 2-stage cp.async (verified R10/R13 datapath): C = A @ B^T
// EP: 0 = fp32 out, 1 = fp32 + residual, 2 = relu + split-bf16 out (A-style)
//     3 = fused qkv epilogue: write per-head attention operand layouts
// ---------------------------------------------------------------------------
template<int EP>
__global__ __launch_bounds__(256) void mma_gemm(
    const __nv_bfloat16* __restrict__ A, const __nv_bfloat16* __restrict__ B,
    const float* __restrict__ bias, const float* __restrict__ res,
    float* __restrict__ Cf, __nv_bfloat16* __restrict__ Cb,
    __nv_bfloat16* __restrict__ q_out, __nv_bfloat16* __restrict__ k_out,
    __nv_bfloat16* __restrict__ v_out,
    int N, int Kp)
{
    extern __shared__ __align__(16) char dsm[];
    const uint32_t sbase = smem_u32(dsm);

    const int tid  = threadIdx.x;
    const int wid  = tid >> 5;
    const int lane = tid & 31;
    const int g    = lane >> 2;
    const int cq   = lane & 3;
    const int lr   = lane & 15;
    const int lc   = lane >> 4;
    const int wm   = wid & 3;
    const int wn   = wid >> 2;
    const int n0   = blockIdx.x * 128;
    const int m0   = blockIdx.y * 128;

    const __nv_bfloat16* Ap = A + (size_t)m0 * Kp;
    const __nv_bfloat16* Bp = B + (size_t)n0 * Kp;
    const int nchunk = Kp >> 6;

    float acc[2][8][4];
#pragma unroll
    for (int mi = 0; mi < 2; mi++)
#pragma unroll
        for (int ni = 0; ni < 8; ni++)
#pragma unroll
            for (int r = 0; r < 4; r++) acc[mi][ni][r] = 0.0f;

    auto load_stage = [&](int c, int stage) {
        const int k0 = c << 6;
        const uint32_t sA = sbase + stage * STAGE_BYTES;
        const uint32_t sB = sA + 16384;
#pragma unroll
        for (int i = 0; i < 4; i++) {
            int lin = tid + i * 256;
            int r   = lin >> 3;
            int c16 = lin & 7;
            uint32_t off = (uint32_t)(r * 128 + ((c16 ^ (r & 7)) * 16));
            CP_ASYNC16(sA + off, (const void*)(Ap + (size_t)r * Kp + k0 + c16 * 8));
            CP_ASYNC16(sB + off, (const void*)(Bp + (size_t)r * Kp + k0 + c16 * 8));
        }
    };

    load_stage(0, 0);
    CP_COMMIT();

    for (int c = 0; c < nchunk; c++) {
        const int cur = c & 1;
        if (c + 1 < nchunk) load_stage(c + 1, cur ^ 1);
        CP_COMMIT();
        CP_WAIT1();
        __syncthreads();

        const uint32_t sA = sbase + cur * STAGE_BYTES;
        const uint32_t sB = sA + 16384;

#pragma unroll
        for (int ks = 0; ks < 4; ks++) {
            const int kblk = ks * 2 + lc;
            uint32_t afr[2][4], bfr[4][4];
#pragma unroll
            for (int mi = 0; mi < 2; mi++) {
                int row = wm * 32 + mi * 16 + lr;
                uint32_t addr = sA + (uint32_t)(row * 128 + ((kblk ^ (row & 7)) * 16));
                LDMATRIX_X4(afr[mi][0], afr[mi][1], afr[mi][2], afr[mi][3], addr);
            }
#pragma unroll
            for (int p = 0; p < 4; p++) {
                int row = wn * 64 + p * 16 + lr;
                uint32_t addr = sB + (uint32_t)(row * 128 + ((kblk ^ (row & 7)) * 16));
                LDMATRIX_X4(bfr[p][0], bfr[p][1], bfr[p][2], bfr[p][3], addr);
            }
#pragma unroll
            for (int mi = 0; mi < 2; mi++)
#pragma unroll
                for (int ni = 0; ni < 8; ni++) {
                    const int p = ni >> 1, o = ni & 1;
                    uint32_t b2[2] = { bfr[p][o], bfr[p][2 + o] };
                    mma16816(acc[mi][ni], afr[mi], b2);
                }
        }
        __syncthreads();
    }

#pragma unroll
    for (int mi = 0; mi < 2; mi++) {
#pragma unroll
        for (int half = 0; half < 2; half++) {
            const int m = m0 + wm * 32 + mi * 16 + g + half * 8;
#pragma unroll
            for (int ni = 0; ni < 8; ni++) {
                const int n = n0 + wn * 64 + ni * 8 + 2 * cq;
                float2 bv = *(const float2*)(bias + n);
                float v0 = acc[mi][ni][half * 2 + 0] + bv.x;
                float v1 = acc[mi][ni][half * 2 + 1] + bv.y;
                if (EP == 2) {
                    v0 = fmaxf(v0, 0.f); v1 = fmaxf(v1, 0.f);
                    __nv_bfloat16 h0, h1, l0, l1;
                    split_bf16(v0, h0, l0); split_bf16(v1, h1, l1);
                    uint32_t hp, lp;
                    *(__nv_bfloat162*)&hp = __halves2bfloat162(h0, h1);
                    *(__nv_bfloat162*)&lp = __halves2bfloat162(l0, l1);
                    size_t rb = (size_t)m * 3 * N;
                    *(uint32_t*)(Cb + rb + n)         = hp;
                    *(uint32_t*)(Cb + rb + N + n)     = hp;
                    *(uint32_t*)(Cb + rb + 2 * N + n) = lp;
                } else if (EP == 3) {
                    // fused qkv epilogue: n in [0,1536) = q|k|v sections
                    const int sec = n >> 9;            // 0=q 1=k 2=v
                    const int hh  = (n >> 6) & 7;      // head
                    const int d   = n & 63;            // dim within head (even)
                    const int t   = m & (SEQ - 1);
                    const int bh  = (m >> 10) * HEADS + hh;
                    if (sec == 0) {
                        float q0 = v0 * 0.125f, q1 = v1 * 0.125f;
                        __nv_bfloat16 h0, h1, l0, l1;
                        split_bf16(q0, h0, l0); split_bf16(q1, h1, l1);
                        uint32_t hp, lp;
                        *(__nv_bfloat162*)&hp = __halves2bfloat162(h0, h1);
                        *(__nv_bfloat162*)&lp = __halves2bfloat162(l0, l1);
                        __nv_bfloat16* qb = q_out + ((size_t)bh * SEQ + t) * 128 + d;
                        *(uint32_t*)(qb)      = hp;
                        *(uint32_t*)(qb + 64) = lp;
                    } else if (sec == 1) {
                        __nv_bfloat16 h0, h1, l0, l1;
                        split_bf16(v0, h0, l0); split_bf16(v1, h1, l1);
                        uint32_t hp, lp;
                        *(__nv_bfloat162*)&hp = __halves2bfloat162(h0, h1);
                        *(__nv_bfloat162*)&lp = __halves2bfloat162(l0, l1);
                        __nv_bfloat16* kb = k_out + ((size_t)bh * SEQ + t) * 128 + d;
                        *(uint32_t*)(kb)      = hp;
                        *(uint32_t*)(kb + 64) = lp;
                    } else {
                        __nv_bfloat16 h0, h1, l0, l1;
                        split_bf16(v0, h0, l0); split_bf16(v1, h1, l1);
                        __nv_bfloat16* vb0 = v_out + ((size_t)bh * DK + d) * (2 * SEQ) + t;
                        __nv_bfloat16* vb1 = vb0 + 2 * SEQ;
                        vb0[0]   = h0; vb0[SEQ] = l0;
                        vb1[0]   = h1; vb1[SEQ] = l1;
                    }
                } else {
                    if (EP == 1) {
                        float2 rv = *(const float2*)(res + (size_t)m * N + n);
                        v0 += rv.x; v1 += rv.y;
                    }
                    *(float2*)(Cf + (size_t)m * N + n) = make_float2(v0, v1);
                }
            }
        }
    }
}

// ---------------------------------------------------------------------------
// Fused flash attention (no-max softmax), 64-row KV chunks for 2 CTAs/SM.
// Same fragment algebra as the verified R13 kernel; only the chunk tiling
// changed (16 stages of 64 s-rows instead of 8 of 128).
// ---------------------------------------------------------------------------
__global__ __launch_bounds__(256, 2) void flash_attn(
    const __nv_bfloat16* __restrict__ qs, const __nv_bfloat16* __restrict__ ks,
    const __nv_bfloat16* __restrict__ vt, __nv_bfloat16* __restrict__ Ccvt)
{
    extern __shared__ __align__(16) char dsm[];
    const uint32_t sb  = smem_u32(dsm);
    const uint32_t Qhi = sb;               // [128][64] bf16
    const uint32_t Qlo = sb + 16384;
    const uint32_t ST0 = sb + 32768;       // stage: Khi 8K | Klo 8K | Vhi 8K | Vlo 8K

    const int tid  = threadIdx.x;
    const int wid  = tid >> 5;
    const int lane = tid & 31;
    const int g    = lane >> 2;
    const int cq   = lane & 3;
    const int lr   = lane & 15;
    const int lc   = lane >> 4;
    const int q0   = blockIdx.x * 128;
    const int bh   = blockIdx.y;
    const int b    = bh >> 3, h = bh & 7;

    // --- load Q (once) ---
#pragma unroll
    for (int i = 0; i < 8; i++) {
        int id = tid + i * 256;
        int slab = id >> 10, r = (id >> 3) & 127, u = id & 7;
        const __nv_bfloat16* src = qs + ((size_t)bh * SEQ + q0 + r) * 128 + slab * 64 + u * 8;
        CP_ASYNC16((slab ? Qlo : Qhi) + (uint32_t)(r * 128 + ((u ^ (r & 7)) * 16)), src);
    }

    auto load_kv = [&](int st, uint32_t stage) {
        const int s0 = st * 64;
#pragma unroll
        for (int i = 0; i < 4; i++) {          // K: 2 slabs x 64 rows x 8 units
            int id = tid + i * 256;            // 0..1023
            int slab = id >> 9, r = (id >> 3) & 63, u = id & 7;
            const __nv_bfloat16* src = ks + ((size_t)bh * SEQ + s0 + r) * 128 + slab * 64 + u * 8;
            CP_ASYNC16(stage + slab * 8192 + (uint32_t)(r * 128 + ((u ^ (r & 7)) * 16)), src);
        }
#pragma unroll
        for (int i = 0; i < 4; i++) {          // V: 2 slabs x 64 rows x 8 units
            int id = tid + i * 256;
            int slab = id >> 9, r = (id >> 3) & 63, u = id & 7;
            const __nv_bfloat16* src = vt + ((size_t)bh * DK + r) * (2 * SEQ) + slab * SEQ + s0 + u * 8;
            CP_ASYNC16(stage + 16384 + slab * 8192 + (uint32_t)(r * 128 + ((u ^ (r & 7)) * 16)), src);
        }
    };

    load_kv(0, ST0);
    CP_COMMIT();

    float oacc[8][4];
#pragma unroll
    for (int ni = 0; ni < 8; ni++)
#pragma unroll
        for (int r = 0; r < 4; r++) oacc[ni][r] = 0.0f;
    float lsum0 = 0.0f, lsum1 = 0.0f;

    const int arow = wid * 16 + lr;
    const uint32_t aoff = (uint32_t)(arow * 128);

    for (int st = 0; st < 16; st++) {
        const int cur = st & 1;
        if (st + 1 < 16) load_kv(st + 1, ST0 + (cur ^ 1) * FA_STAGE);
        CP_COMMIT();
        CP_WAIT1();
        __syncthreads();

        const uint32_t Kh = ST0 + cur * FA_STAGE;
        const uint32_t Kl = Kh + 8192;
        const uint32_t Vh = Kh + 16384;
        const uint32_t Vl = Kh + 24576;

        // ---- S = Q K^T (3 logical slabs) over 64 s-cols ----
        float sacc[8][4];
#pragma unroll
        for (int ni = 0; ni < 8; ni++)
#pragma unroll
            for (int r = 0; r < 4; r++) sacc[ni][r] = 0.0f;

        uint32_t ahi[4][4];
#pragma unroll
        for (int j = 0; j < 4; j++) {
            const int kblk = j * 2 + lc;
            const uint32_t asw = (uint32_t)((kblk ^ (arow & 7)) * 16);
            LDMATRIX_X4(ahi[j][0], ahi[j][1], ahi[j][2], ahi[j][3], Qhi + aoff + asw);
#pragma unroll
            for (int p = 0; p < 4; p++) {
                int row = p * 16 + lr;
                uint32_t addr = Kh + (uint32_t)(row * 128 + ((kblk ^ (row & 7)) * 16));
                uint32_t bfr[4];
                LDMATRIX_X4(bfr[0], bfr[1], bfr[2], bfr[3], addr);
#pragma unroll
                for (int o = 0; o < 2; o++) {
                    uint32_t b2[2] = { bfr[o], bfr[2 + o] };
                    mma16816(sacc[2 * p + o], ahi[j], b2);
                }
            }
#pragma unroll
            for (int p = 0; p < 4; p++) {
                int row = p * 16 + lr;
                uint32_t addr = Kl + (uint32_t)(row * 128 + ((kblk ^ (row & 7)) * 16));
                uint32_t bfr[4];
                LDMATRIX_X4(bfr[0], bfr[1], bfr[2], bfr[3], addr);
#pragma unroll
                for (int o = 0; o < 2; o++) {
                    uint32_t b2[2] = { bfr[o], bfr[2 + o] };
                    mma16816(sacc[2 * p + o], ahi[j], b2);
                }
            }
        }
#pragma unroll
        for (int j = 0; j < 4; j++) {
            const int kblk = j * 2 + lc;
            const uint32_t asw = (uint32_t)((kblk ^ (arow & 7)) * 16);
            uint32_t alo[4];
            LDMATRIX_X4(alo[0], alo[1], alo[2], alo[3], Qlo + aoff + asw);
#pragma unroll
            for (int p = 0; p < 4; p++) {
                int row = p * 16 + lr;
                uint32_t addr = Kh + (uint32_t)(row * 128 + ((kblk ^ (row & 7)) * 16));
                uint32_t bfr[4];
                LDMATRIX_X4(bfr[0], bfr[1], bfr[2], bfr[3], addr);
#pragma unroll
                for (int o = 0; o < 2; o++) {
                    uint32_t b2[2] = { bfr[o], bfr[2 + o] };
                    mma16816(sacc[2 * p + o], alo, b2);
                }
            }
        }

        // ---- P = exp(S); accumulate row sums; build hi A-fragments ----
#pragma unroll
        for (int ni = 0; ni < 8; ni++) {
            float p0 = __expf(sacc[ni][0]);
            float p1 = __expf(sacc[ni][1]);
            float p2 = __expf(sacc[ni][2]);
            float p3 = __expf(sacc[ni][3]);
            lsum0 += p0 + p1;
            lsum1 += p2 + p3;
            sacc[ni][0] = p0; sacc[ni][1] = p1;
            sacc[ni][2] = p2; sacc[ni][3] = p3;
        }
        uint32_t phi[4][4];
#pragma unroll
        for (int jj = 0; jj < 4; jj++) {
            phi[jj][0] = packbf(sacc[2 * jj][0],     sacc[2 * jj][1]);
            phi[jj][1] = packbf(sacc[2 * jj][2],     sacc[2 * jj][3]);
            phi[jj][2] = packbf(sacc[2 * jj + 1][0], sacc[2 * jj + 1][1]);
            phi[jj][3] = packbf(sacc[2 * jj + 1][2], sacc[2 * jj + 1][3]);
        }

        // ---- ctx += P V^T (3 logical slabs) ----
#pragma unroll
        for (int jj = 0; jj < 4; jj++) {
            const int kblk = jj * 2 + lc;
            // P_hi x V_hi
#pragma unroll
            for (int p = 0; p < 4; p++) {
                int row = p * 16 + lr;
                uint32_t addr = Vh + (uint32_t)(row * 128 + ((kblk ^ (row & 7)) * 16));
                uint32_t bfr[4];
                LDMATRIX_X4(bfr[0], bfr[1], bfr[2], bfr[3], addr);
#pragma unroll
                for (int o = 0; o < 2; o++) {
                    uint32_t b2[2] = { bfr[o], bfr[2 + o] };
                    mma16816(oacc[2 * p + o], phi[jj], b2);
                }
            }
            // P_hi x V_lo
#pragma unroll
            for (int p = 0; p < 4; p++) {
                int row = p * 16 + lr;
                uint32_t addr = Vl + (uint32_t)(row * 128 + ((kblk ^ (row & 7)) * 16));
                uint32_t bfr[4];
                LDMATRIX_X4(bfr[0], bfr[1], bfr[2], bfr[3], addr);
#pragma unroll
                for (int o = 0; o < 2; o++) {
                    uint32_t b2[2] = { bfr[o], bfr[2 + o] };
                    mma16816(oacc[2 * p + o], phi[jj], b2);
                }
            }
            // P_lo x V_hi
            uint32_t plo[4];
            plo[0] = packbf(lof(sacc[2 * jj][0]),     lof(sacc[2 * jj][1]));
            plo[1] = packbf(lof(sacc[2 * jj][2]),     lof(sacc[2 * jj][3]));
            plo[2] = packbf(lof(sacc[2 * jj + 1][0]), lof(sacc[2 * jj + 1][1]));
            plo[3] = packbf(lof(sacc[2 * jj + 1][2]), lof(sacc[2 * jj + 1][3]));
#pragma unroll
            for (int p = 0; p < 4; p++) {
                int row = p * 16 + lr;
                uint32_t addr = Vh + (uint32_t)(row * 128 + ((kblk ^ (row & 7)) * 16));
                uint32_t bfr[4];
                LDMATRIX_X4(bfr[0], bfr[1], bfr[2], bfr[3], addr);
#pragma unroll
                for (int o = 0; o < 2; o++) {
                    uint32_t b2[2] = { bfr[o], bfr[2 + o] };
                    mma16816(oacc[2 * p + o], plo, b2);
                }
            }
        }
        __syncthreads();
    }

    // row-sum reduction over the quad (cq lanes)
    lsum0 += __shfl_xor_sync(0xffffffffu, lsum0, 1);
    lsum0 += __shfl_xor_sync(0xffffffffu, lsum0, 2);
    lsum1 += __shfl_xor_sync(0xffffffffu, lsum1, 1);
    lsum1 += __shfl_xor_sync(0xffffffffu, lsum1, 2);
    const float inv0 = 1.0f / lsum0;
    const float inv1 = 1.0f / lsum1;

    // epilogue: split write into g_ccvt [tok][3*512] at cols h*64 + n
#pragma unroll
    for (int half = 0; half < 2; half++) {
        const int m = q0 + wid * 16 + g + half * 8;
        const size_t tok = (size_t)b * SEQ + m;
        const size_t rb = tok * (3 * NU);
        const float inv = half ? inv1 : inv0;
#pragma unroll
        for (int ni = 0; ni < 8; ni++) {
            const int col = h * DK + ni * 8 + 2 * cq;
            float v0 = oacc[ni][half * 2 + 0] * inv;
            float v1 = oacc[ni][half * 2 + 1] * inv;
            __nv_bfloat16 h0, h1, l0, l1;
            split_bf16(v0, h0, l0); split_bf16(v1, h1, l1);
            uint32_t hp, lp;
            *(__nv_bfloat162*)&hp = __halves2bfloat162(h0, h1);
            *(__nv_bfloat162*)&lp = __halves2bfloat162(l0, l1);
            *(uint32_t*)(Ccvt + rb + col)          = hp;
            *(uint32_t*)(Ccvt + rb + NU + col)     = hp;
            *(uint32_t*)(Ccvt + rb + 2 * NU + col) = lp;
        }
    }
}

// ---------------------------------------------------------------------------
// LayerNorm over rows of 512; optionally also writes split-bf16 (A-style)
// ---------------------------------------------------------------------------
template<bool CVT>
__global__ __launch_bounds__(128) void ln_kernel(
    const float* __restrict__ X, const float* __restrict__ gamma,
    const float* __restrict__ beta, float* __restrict__ O,
    __nv_bfloat16* __restrict__ Ocvt)
{
    __shared__ float red[4];
    const int row = blockIdx.x;
    const int tid = threadIdx.x;

    float4 v = *(const float4*)(X + (size_t)row * NU + tid * 4);
    float s = v.x + v.y + v.z + v.w;
#pragma unroll
    for (int o = 16; o > 0; o >>= 1) s += __shfl_xor_sync(0xffffffffu, s, o);
    if ((tid & 31) == 0) red[tid >> 5] = s;
    __syncthreads();
    float mean = (red[0] + red[1] + red[2] + red[3]) * (1.0f / 512.0f);
    __syncthreads();

    float dx = v.x - mean, dy = v.y - mean, dz = v.z - mean, dw = v.w - mean;
    float sq = dx * dx + dy * dy + dz * dz + dw * dw;
#pragma unroll
    for (int o = 16; o > 0; o >>= 1) sq += __shfl_xor_sync(0xffffffffu, sq, o);
    if ((tid & 31) == 0) red[tid >> 5] = sq;
    __syncthreads();
    float var = (red[0] + red[1] + red[2] + red[3]) * (1.0f / 512.0f);
    float inv = rsqrtf(var + 1e-5f);

    float4 g = *(const float4*)(gamma + tid * 4);
    float4 b = *(const float4*)(beta  + tid * 4);
    float4 o4;
    o4.x = dx * inv * g.x + b.x;
    o4.y = dy * inv * g.y + b.y;
    o4.z = dz * inv * g.z + b.z;
    o4.w = dw * inv * g.w + b.w;
    *(float4*)(O + (size_t)row * NU + tid * 4) = o4;

    if (CVT) {
        __nv_bfloat16 h0, h1, h2, h3, l0, l1, l2, l3;
        split_bf16(o4.x, h0, l0); split_bf16(o4.y, h1, l1);
        split_bf16(o4.z, h2, l2); split_bf16(o4.w, h3, l3);
        uint2 hp, lp;
        *(__nv_bfloat162*)&hp.x = __halves2bfloat162(h0, h1);
        *(__nv_bfloat162*)&hp.y = __halves2bfloat162(h2, h3);
        *(__nv_bfloat162*)&lp.x = __halves2bfloat162(l0, l1);
        *(__nv_bfloat162*)&lp.y = __halves2bfloat162(l2, l3);
        size_t rb = (size_t)row * (3 * NU);
        int col = tid * 4;
        *(uint2*)(Ocvt + rb + col)            = hp;
        *(uint2*)(Ocvt + rb + NU + col)       = hp;
        *(uint2*)(Ocvt + rb + 2 * NU + col)   = lp;
    }
}

// ---------------------------------------------------------------------------
// Host orchestration (graph-capturable: kernel launches only)
// ---------------------------------------------------------------------------
extern "C" void kernel_launch(void* const* d_in, const int* in_sizes, int n_in,
                              void* d_out, int out_size)
{
    (void)in_sizes; (void)n_in; (void)out_size;

    const float* x     = (const float*)d_in[0];
    const float* Win   = (const float*)d_in[1];
    const float* bin   = (const float*)d_in[2];
    const float* ln1_g = (const float*)d_in[3];
    const float* ln1_b = (const float*)d_in[4];
    const float* Wq    = (const float*)d_in[5];
    const float* bq    = (const float*)d_in[6];
    const float* Wk    = (const float*)d_in[7];
    const float* bk    = (const float*)d_in[8];
    const float* Wv    = (const float*)d_in[9];
    const float* bv    = (const float*)d_in[10];
    const float* Wo    = (const float*)d_in[11];
    const float* bo    = (const float*)d_in[12];
    const float* ln2_g = (const float*)d_in[13];
    const float* ln2_b = (const float*)d_in[14];
    const float* W1    = (const float*)d_in[15];
    const float* b1    = (const float*)d_in[16];
    const float* W2    = (const float*)d_in[17];
    const float* b2    = (const float*)d_in[18];
    const float* lno_g = (const float*)d_in[19];
    const float* lno_b = (const float*)d_in[20];
    float* out = (float*)d_out;

    float *e, *bqkv;
    __nv_bfloat16 *xc, *ec, *cc, *hc, *Winc, *Wqkvc, *Woc, *W1c, *W2c;
    __nv_bfloat16 *qs, *ks, *vt;
    cudaGetSymbolAddress((void**)&e,    g_e);
    cudaGetSymbolAddress((void**)&bqkv, g_bqkv);
    cudaGetSymbolAddress((void**)&xc,   g_xcvt);
    cudaGetSymbolAddress((void**)&ec,   g_ecvt);
    cudaGetSymbolAddress((void**)&cc,   g_ccvt);
    cudaGetSymbolAddress((void**)&hc,   g_hcvt);
    cudaGetSymbolAddress((void**)&Winc,  g_Winc);
    cudaGetSymbolAddress((void**)&Wqkvc, g_Wqkvc);
    cudaGetSymbolAddress((void**)&Woc,   g_Woc);
    cudaGetSymbolAddress((void**)&W1c,   g_W1c);
    cudaGetSymbolAddress((void**)&W2c,   g_W2c);
    cudaGetSymbolAddress((void**)&qs,   g_qs);
    cudaGetSymbolAddress((void**)&ks,   g_ks);
    cudaGetSymbolAddress((void**)&vt,   g_vt);

    cudaFuncSetAttribute(mma_gemm<0>, cudaFuncAttributeMaxDynamicSharedMemorySize, GEMM_DSMEM);
    cudaFuncSetAttribute(mma_gemm<1>, cudaFuncAttributeMaxDynamicSharedMemorySize, GEMM_DSMEM);
    cudaFuncSetAttribute(mma_gemm<2>, cudaFuncAttributeMaxDynamicSharedMemorySize, GEMM_DSMEM);
    cudaFuncSetAttribute(mma_gemm<3>, cudaFuncAttributeMaxDynamicSharedMemorySize, GEMM_DSMEM);
    cudaFuncSetAttribute(flash_attn,  cudaFuncAttributeMaxDynamicSharedMemorySize, FA_DSMEM);

    // operand conversions (every launch; deterministic)
    {
        int t;
        t = NU * IDIM;          convert_B_kernel<<<(t + 255) / 256, 256>>>(Win, Winc, IDIM, t);
        t = NLAYERS * 3 * NU * NU;
                                convert_qkv_kernel<<<(t + 255) / 256, 256>>>(Wq, Wk, Wv, Wqkvc);
        t = NLAYERS * NU * NU;  convert_B_kernel<<<(t + 255) / 256, 256>>>(Wo, Woc, NU, t);
        t = NLAYERS * EU * NU;  convert_B_kernel<<<(t + 255) / 256, 256>>>(W1, W1c, NU, t);
        t = NLAYERS * NU * EU;  convert_B_kernel<<<(t + 255) / 256, 256>>>(W2, W2c, EU, t);
        t = TOK * IDIM;         convert_A_kernel<<<(t + 255) / 256, 256>>>(x, xc, IDIM, t);
        t = NLAYERS * QKVW;     pack_bqkv_kernel<<<(t + 255) / 256, 256>>>(bq, bk, bv, bqkv);
    }

    dim3 g512 (NU   / 128, TOK / 128);   // (4, 64)
    dim3 gqkv (QKVW / 128, TOK / 128);   // (12, 64)
    dim3 g2048(EU   / 128, TOK / 128);   // (16, 64)
    dim3 gflash(SEQ / 128, BH);          // (8, 64)

    // input projection: e = x @ Win^T + bin
    mma_gemm<0><<<g512, 256, GEMM_DSMEM>>>(xc, Winc, bin, nullptr, e, nullptr,
                                           nullptr, nullptr, nullptr, NU, 3 * IDIM);

    for (int i = 0; i < NLAYERS; i++) {
        const size_t wqkv = (size_t)i * QKVW * 3 * NU;
        const size_t wo   = (size_t)i * NU * 3 * NU;
        const size_t w1o  = (size_t)i * EU * 3 * NU;
        const size_t w2o  = (size_t)i * NU * 3 * EU;

        ln_kernel<true><<<TOK, 128>>>(e, ln1_g + i * NU, ln1_b + i * NU, e, ec);

        // fused qkv GEMM with direct attention-operand epilogue
        mma_gemm<3><<<gqkv, 256, GEMM_DSMEM>>>(ec, Wqkvc + wqkv, bqkv + i * QKVW, nullptr,
                                               nullptr, nullptr, qs, ks, vt, QKVW, 3 * NU);

        // fused attention
        flash_attn<<<gflash, 256, FA_DSMEM>>>(qs, ks, vt, cc);

        // e = e + ctx @ Wo^T + bo
        mma_gemm<1><<<g512, 256, GEMM_DSMEM>>>(cc, Woc + wo, bo + i * NU, e, e, nullptr,
                                               nullptr, nullptr, nullptr, NU, 3 * NU);

        ln_kernel<true><<<TOK, 128>>>(e, ln2_g + i * NU, ln2_b + i * NU, e, ec);

        // h = relu(e @ W1^T + b1) -> split bf16
        mma_gemm<2><<<g2048, 256, GEMM_DSMEM>>>(ec, W1c + w1o, b1 + (size_t)i * EU, nullptr,
                                                nullptr, hc, nullptr, nullptr, nullptr, EU, 3 * NU);
        // e = e + h @ W2^T + b2
        mma_gemm<1><<<g512, 256, GEMM_DSMEM>>>(hc, W2c + w2o, b2 + i * NU, e, e, nullptr,
                                               nullptr, nullptr, nullptr, NU, 3 * EU);
    }

    ln_kernel<false><<<TOK, 128>>>(e, lno_g, lno_b, out, nullptr);
}

// round 15
// speedup vs baseline: 1.1148x; 1.0326x over previous
#include <cuda_runtime.h>
#include <cuda_bf16.h>
#include <math.h>
#include <stdint.h>

// ---------------------------------------------------------------------------
// Problem constants
// ---------------------------------------------------------------------------
#define TOK      8192
#define IDIM     256
#define NU       512
#define EU       2048
#define NLAYERS  4
#define HEADS    8
#define DK       64
#define SEQ      1024
#define NBATCH   8
#define QKVW     1536
#define BH       (NBATCH * HEADS)   // 64

// ---------------------------------------------------------------------------
// Scratch (static device memory; allocation APIs are forbidden)
// ---------------------------------------------------------------------------
__device__ float g_e[TOK * NU];

// split-bf16 operand buffers (K-concat: activations [hi|hi|lo], weights [hi|lo|hi])
__device__ __nv_bfloat16 g_xcvt [TOK * 3 * IDIM];
__device__ __nv_bfloat16 g_ecvt [TOK * 3 * NU];
__device__ __nv_bfloat16 g_ccvt [TOK * 3 * NU];
__device__ __nv_bfloat16 g_hcvt [TOK * 3 * EU];

__device__ __nv_bfloat16 g_Winc  [NU * 3 * IDIM];
__device__ __nv_bfloat16 g_Wqkvc [NLAYERS * QKVW * 3 * NU];
__device__ __nv_bfloat16 g_Woc   [NLAYERS * NU * 3 * NU];
__device__ __nv_bfloat16 g_W1c   [NLAYERS * EU * 3 * NU];
__device__ __nv_bfloat16 g_W2c   [NLAYERS * NU * 3 * EU];
__device__ float         g_bqkv  [NLAYERS * QKVW];

// attention operands, 2-slab [hi|lo] layouts
__device__ __nv_bfloat16 g_qs [BH * SEQ * 128];        // [bh][t][hi64|lo64] (scaled)
__device__ __nv_bfloat16 g_ks [BH * SEQ * 128];        // [bh][t][hi64|lo64]
__device__ __nv_bfloat16 g_vt [BH * DK * 2 * SEQ];     // [bh][d][hi@s | lo@1024+s]

// ---------------------------------------------------------------------------
// split helpers
// ---------------------------------------------------------------------------
__device__ __forceinline__ void split_bf16(float f, __nv_bfloat16& hi, __nv_bfloat16& lo) {
    hi = __float2bfloat16(f);
    lo = __float2bfloat16(f - __bfloat162float(hi));
}
__device__ __forceinline__ uint32_t packbf(float a, float b) {
    __nv_bfloat162 t = __halves2bfloat162(__float2bfloat16(a), __float2bfloat16(b));
    return *(uint32_t*)&t;
}
__device__ __forceinline__ float lof(float a) {
    return a - __bfloat162float(__float2bfloat16(a));
}

// weights: out row = [hi | lo | hi], row width 3K
__global__ void convert_B_kernel(const float* __restrict__ W, __nv_bfloat16* __restrict__ out,
                                 int K, int total) {
    int idx = blockIdx.x * 256 + threadIdx.x;
    if (idx >= total) return;
    int n = idx / K, k = idx - n * K;
    __nv_bfloat16 hi, lo;
    split_bf16(W[idx], hi, lo);
    size_t base = (size_t)n * 3 * K;
    out[base + k] = hi;
    out[base + K + k] = lo;
    out[base + 2 * K + k] = hi;
}

// batched qkv weight conversion: all layers, all three matrices, one launch
__global__ void convert_qkv_kernel(const float* __restrict__ Wq, const float* __restrict__ Wk,
                                   const float* __restrict__ Wv, __nv_bfloat16* __restrict__ out) {
    const int per = NU * NU;
    int idx = blockIdx.x * 256 + threadIdx.x;
    if (idx >= NLAYERS * 3 * per) return;
    int mat = idx / per;
    int rem = idx - mat * per;
    int l = mat / 3, sec = mat - l * 3;
    int n = rem / NU, k = rem - n * NU;
    const float* W = (sec == 0) ? Wq : (sec == 1) ? Wk : Wv;
    __nv_bfloat16 hi, lo;
    split_bf16(W[(size_t)l * per + rem], hi, lo);
    size_t base = (size_t)l * QKVW * 3 * NU + (size_t)(sec * NU + n) * 3 * NU;
    out[base + k] = hi;
    out[base + NU + k] = lo;
    out[base + 2 * NU + k] = hi;
}

// activations: out row = [hi | hi | lo]
__global__ void convert_A_kernel(const float* __restrict__ A, __nv_bfloat16* __restrict__ out,
                                 int K, int total) {
    int idx = blockIdx.x * 256 + threadIdx.x;
    if (idx >= total) return;
    int n = idx / K, k = idx - n * K;
    __nv_bfloat16 hi, lo;
    split_bf16(A[idx], hi, lo);
    size_t base = (size_t)n * 3 * K;
    out[base + k] = hi;
    out[base + K + k] = hi;
    out[base + 2 * K + k] = lo;
}

// pack per-layer q|k|v biases into 1536-wide rows
__global__ void pack_bqkv_kernel(const float* __restrict__ bq, const float* __restrict__ bk,
                                 const float* __restrict__ bv, float* __restrict__ out) {
    int i = blockIdx.x * 256 + threadIdx.x;
    if (i >= NLAYERS * QKVW) return;
    int l = i / QKVW, c = i - l * QKVW;
    float v = (c < NU) ? bq[l * NU + c]
            : (c < 2 * NU) ? bk[l * NU + c - NU]
            : bv[l * NU + c - 2 * NU];
    out[i] = v;
}

// ---------------------------------------------------------------------------
// mma.sync common pieces
// ---------------------------------------------------------------------------
#define STAGE_BYTES 32768
#define GEMM_DSMEM  (2 * STAGE_BYTES)
#define FA_STAGE    32768          // Khi 8K | Klo 8K | Vhi 8K | Vlo 8K (64 s-rows)
#define FA_DSMEM    (32768 + 2 * FA_STAGE)   // Q 32K + 2 stages = 96K -> 2 CTAs/SM

__device__ __forceinline__ uint32_t smem_u32(const void* p) {
    uint32_t a;
    asm("{ .reg .u64 t; cvta.to.shared.u64 t, %1; cvt.u32.u64 %0, t; }" : "=r"(a) : "l"(p));
    return a;
}

#define CP_ASYNC16(dst, src) \
    asm volatile("cp.async.cg.shared.global [%0], [%1], 16;" :: "r"(dst), "l"(src) : "memory")
#define CP_COMMIT() asm volatile("cp.async.commit_group;" ::: "memory")
#define CP_WAIT0()  asm volatile("cp.async.wait_group 0;" ::: "memory")

#define LDMATRIX_X4(r0, r1, r2, r3, addr) \
    asm volatile("ldmatrix.sync.aligned.m8n8.x4.shared.b16 {%0,%1,%2,%3}, [%4];" \
        : "=r"(r0), "=r"(r1), "=r"(r2), "=r"(r3) : "r"(addr))

__device__ __forceinline__ void mma16816(float* d, const uint32_t* a, const uint32_t* b) {
    asm volatile(
        "mma.sync.aligned.m16n8k16.row.col.f32.bf16.bf16.f32 "
        "{%0,%1,%2,%3}, {%4,%5,%6,%7}, {%8,%9}, {%0,%1,%2,%3};"
        : "+f"(d[0]), "+f"(d[1]), "+f"(d[2]), "+f"(d[3])
        : "r"(a[0]), "r"(a[1]), "r"(a[2]), "r"(a[3]), "r"(b[0]), "r"(b[1]));
}

// ---------------------------------------------------------------------------
// Linear GEMM, 2-stage cp.async, single-sync pipeline: C = A @ B^T
// EP: 0 = fp32 out, 1 = fp32 + residual, 2 = relu + split-bf16 out (A-style)
//     3 = fused qkv epilogue: write per-head attention operand layouts
// ---------------------------------------------------------------------------
template<int EP>
__global__ __launch_bounds__(256) void mma_gemm(
    const __nv_bfloat16* __restrict__ A, const __nv_bfloat16* __restrict__ B,
    const float* __restrict__ bias, const float* __restrict__ res,
    float* __restrict__ Cf, __nv_bfloat16* __restrict__ Cb,
    __nv_bfloat16* __restrict__ q_out, __nv_bfloat16* __restrict__ k_out,
    __nv_bfloat16* __restrict__ v_out,
    int N, int Kp)
{
    extern __shared__ __align__(16) char dsm[];
    const uint32_t sbase = smem_u32(dsm);

    const int tid  = threadIdx.x;
    const int wid  = tid >> 5;
    const int lane = tid & 31;
    const int g    = lane >> 2;
    const int cq   = lane & 3;
    const int lr   = lane & 15;
    const int lc   = lane >> 4;
    const int wm   = wid & 3;
    const int wn   = wid >> 2;
    const int n0   = blockIdx.x * 128;
    const int m0   = blockIdx.y * 128;

    const __nv_bfloat16* Ap = A + (size_t)m0 * Kp;
    const __nv_bfloat16* Bp = B + (size_t)n0 * Kp;
    const int nchunk = Kp >> 6;

    float acc[2][8][4];
#pragma unroll
    for (int mi = 0; mi < 2; mi++)
#pragma unroll
        for (int ni = 0; ni < 8; ni++)
#pragma unroll
            for (int r = 0; r < 4; r++) acc[mi][ni][r] = 0.0f;

    auto load_stage = [&](int c, int stage) {
        const int k0 = c << 6;
        const uint32_t sA = sbase + stage * STAGE_BYTES;
        const uint32_t sB = sA + 16384;
#pragma unroll
        for (int i = 0; i < 4; i++) {
            int lin = tid + i * 256;
            int r   = lin >> 3;
            int c16 = lin & 7;
            uint32_t off = (uint32_t)(r * 128 + ((c16 ^ (r & 7)) * 16));
            CP_ASYNC16(sA + off, (const void*)(Ap + (size_t)r * Kp + k0 + c16 * 8));
            CP_ASYNC16(sB + off, (const void*)(Bp + (size_t)r * Kp + k0 + c16 * 8));
        }
    };

    load_stage(0, 0);
    CP_COMMIT();

    for (int c = 0; c < nchunk; c++) {
        const int cur = c & 1;
        CP_WAIT0();
        __syncthreads();
        if (c + 1 < nchunk) {
            load_stage(c + 1, cur ^ 1);
            CP_COMMIT();
        }

        const uint32_t sA = sbase + cur * STAGE_BYTES;
        const uint32_t sB = sA + 16384;

#pragma unroll
        for (int ks = 0; ks < 4; ks++) {
            const int kblk = ks * 2 + lc;
            uint32_t afr[2][4], bfr[4][4];
#pragma unroll
            for (int mi = 0; mi < 2; mi++) {
                int row = wm * 32 + mi * 16 + lr;
                uint32_t addr = sA + (uint32_t)(row * 128 + ((kblk ^ (row & 7)) * 16));
                LDMATRIX_X4(afr[mi][0], afr[mi][1], afr[mi][2], afr[mi][3], addr);
            }
#pragma unroll
            for (int p = 0; p < 4; p++) {
                int row = wn * 64 + p * 16 + lr;
                uint32_t addr = sB + (uint32_t)(row * 128 + ((kblk ^ (row & 7)) * 16));
                LDMATRIX_X4(bfr[p][0], bfr[p][1], bfr[p][2], bfr[p][3], addr);
            }
#pragma unroll
            for (int mi = 0; mi < 2; mi++)
#pragma unroll
                for (int ni = 0; ni < 8; ni++) {
                    const int p = ni >> 1, o = ni & 1;
                    uint32_t b2[2] = { bfr[p][o], bfr[p][2 + o] };
                    mma16816(acc[mi][ni], afr[mi], b2);
                }
        }
    }

#pragma unroll
    for (int mi = 0; mi < 2; mi++) {
#pragma unroll
        for (int half = 0; half < 2; half++) {
            const int m = m0 + wm * 32 + mi * 16 + g + half * 8;
#pragma unroll
            for (int ni = 0; ni < 8; ni++) {
                const int n = n0 + wn * 64 + ni * 8 + 2 * cq;
                float2 bv = *(const float2*)(bias + n);
                float v0 = acc[mi][ni][half * 2 + 0] + bv.x;
                float v1 = acc[mi][ni][half * 2 + 1] + bv.y;
                if (EP == 2) {
                    v0 = fmaxf(v0, 0.f); v1 = fmaxf(v1, 0.f);
                    __nv_bfloat16 h0, h1, l0, l1;
                    split_bf16(v0, h0, l0); split_bf16(v1, h1, l1);
                    uint32_t hp, lp;
                    *(__nv_bfloat162*)&hp = __halves2bfloat162(h0, h1);
                    *(__nv_bfloat162*)&lp = __halves2bfloat162(l0, l1);
                    size_t rb = (size_t)m * 3 * N;
                    *(uint32_t*)(Cb + rb + n)         = hp;
                    *(uint32_t*)(Cb + rb + N + n)     = hp;
                    *(uint32_t*)(Cb + rb + 2 * N + n) = lp;
                } else if (EP == 3) {
                    const int sec = n >> 9;            // 0=q 1=k 2=v
                    const int hh  = (n >> 6) & 7;      // head
                    const int d   = n & 63;            // dim within head (even)
                    const int t   = m & (SEQ - 1);
                    const int bh  = (m >> 10) * HEADS + hh;
                    if (sec == 0) {
                        float q0 = v0 * 0.125f, q1 = v1 * 0.125f;
                        __nv_bfloat16 h0, h1, l0, l1;
                        split_bf16(q0, h0, l0); split_bf16(q1, h1, l1);
                        uint32_t hp, lp;
                        *(__nv_bfloat162*)&hp = __halves2bfloat162(h0, h1);
                        *(__nv_bfloat162*)&lp = __halves2bfloat162(l0, l1);
                        __nv_bfloat16* qb = q_out + ((size_t)bh * SEQ + t) * 128 + d;
                        *(uint32_t*)(qb)      = hp;
                        *(uint32_t*)(qb + 64) = lp;
                    } else if (sec == 1) {
                        __nv_bfloat16 h0, h1, l0, l1;
                        split_bf16(v0, h0, l0); split_bf16(v1, h1, l1);
                        uint32_t hp, lp;
                        *(__nv_bfloat162*)&hp = __halves2bfloat162(h0, h1);
                        *(__nv_bfloat162*)&lp = __halves2bfloat162(l0, l1);
                        __nv_bfloat16* kb = k_out + ((size_t)bh * SEQ + t) * 128 + d;
                        *(uint32_t*)(kb)      = hp;
                        *(uint32_t*)(kb + 64) = lp;
                    } else {
                        __nv_bfloat16 h0, h1, l0, l1;
                        split_bf16(v0, h0, l0); split_bf16(v1, h1, l1);
                        __nv_bfloat16* vb0 = v_out + ((size_t)bh * DK + d) * (2 * SEQ) + t;
                        __nv_bfloat16* vb1 = vb0 + 2 * SEQ;
                        vb0[0]   = h0; vb0[SEQ] = l0;
                        vb1[0]   = h1; vb1[SEQ] = l1;
                    }
                } else {
                    if (EP == 1) {
                        float2 rv = *(const float2*)(res + (size_t)m * N + n);
                        v0 += rv.x; v1 += rv.y;
                    }
                    *(float2*)(Cf + (size_t)m * N + n) = make_float2(v0, v1);
                }
            }
        }
    }
}

// ---------------------------------------------------------------------------
// Fused flash attention (no-max softmax), 64-row KV chunks, 2 CTAs/SM.
// Fragment-reuse interleave: each K_hi / V_hi fragment is loaded once and fed
// to both split terms that consume it. Same MMA operand set as R13/R14.
// ---------------------------------------------------------------------------
__global__ __launch_bounds__(256, 2) void flash_attn(
    const __nv_bfloat16* __restrict__ qs, const __nv_bfloat16* __restrict__ ks,
    const __nv_bfloat16* __restrict__ vt, __nv_bfloat16* __restrict__ Ccvt)
{
    extern __shared__ __align__(16) char dsm[];
    const uint32_t sb  = smem_u32(dsm);
    const uint32_t Qhi = sb;               // [128][64] bf16
    const uint32_t Qlo = sb + 16384;
    const uint32_t ST0 = sb + 32768;       // stage: Khi 8K | Klo 8K | Vhi 8K | Vlo 8K

    const int tid  = threadIdx.x;
    const int wid  = tid >> 5;
    const int lane = tid & 31;
    const int g    = lane >> 2;
    const int cq   = lane & 3;
    const int lr   = lane & 15;
    const int lc   = lane >> 4;
    const int q0   = blockIdx.x * 128;
    const int bh   = blockIdx.y;
    const int b    = bh >> 3, h = bh & 7;

    // --- load Q (once) ---
#pragma unroll
    for (int i = 0; i < 8; i++) {
        int id = tid + i * 256;
        int slab = id >> 10, r = (id >> 3) & 127, u = id & 7;
        const __nv_bfloat16* src = qs + ((size_t)bh * SEQ + q0 + r) * 128 + slab * 64 + u * 8;
        CP_ASYNC16((slab ? Qlo : Qhi) + (uint32_t)(r * 128 + ((u ^ (r & 7)) * 16)), src);
    }

    auto load_kv = [&](int st, uint32_t stage) {
        const int s0 = st * 64;
#pragma unroll
        for (int i = 0; i < 4; i++) {          // K: 2 slabs x 64 rows x 8 units
            int id = tid + i * 256;
            int slab = id >> 9, r = (id >> 3) & 63, u = id & 7;
            const __nv_bfloat16* src = ks + ((size_t)bh * SEQ + s0 + r) * 128 + slab * 64 + u * 8;
            CP_ASYNC16(stage + slab * 8192 + (uint32_t)(r * 128 + ((u ^ (r & 7)) * 16)), src);
        }
#pragma unroll
        for (int i = 0; i < 4; i++) {          // V: 2 slabs x 64 rows x 8 units
            int id = tid + i * 256;
            int slab = id >> 9, r = (id >> 3) & 63, u = id & 7;
            const __nv_bfloat16* src = vt + ((size_t)bh * DK + r) * (2 * SEQ) + slab * SEQ + s0 + u * 8;
            CP_ASYNC16(stage + 16384 + slab * 8192 + (uint32_t)(r * 128 + ((u ^ (r & 7)) * 16)), src);
        }
    };

    load_kv(0, ST0);
    CP_COMMIT();

    float oacc[8][4];
#pragma unroll
    for (int ni = 0; ni < 8; ni++)
#pragma unroll
        for (int r = 0; r < 4; r++) oacc[ni][r] = 0.0f;
    float lsum0 = 0.0f, lsum1 = 0.0f;

    const int arow = wid * 16 + lr;
    const uint32_t aoff = (uint32_t)(arow * 128);

    for (int st = 0; st < 16; st++) {
        const int cur = st & 1;
        CP_WAIT0();
        __syncthreads();
        if (st + 1 < 16) {
            load_kv(st + 1, ST0 + (cur ^ 1) * FA_STAGE);
            CP_COMMIT();
        }

        const uint32_t Kh = ST0 + cur * FA_STAGE;
        const uint32_t Kl = Kh + 8192;
        const uint32_t Vh = Kh + 16384;
        const uint32_t Vl = Kh + 24576;

        // ---- S = Q K^T : interleaved 3-term (Khi loaded once per fragment) ----
        float sacc[8][4];
#pragma unroll
        for (int ni = 0; ni < 8; ni++)
#pragma unroll
            for (int r = 0; r < 4; r++) sacc[ni][r] = 0.0f;

#pragma unroll
        for (int j = 0; j < 4; j++) {
            const int kblk = j * 2 + lc;
            const uint32_t asw = (uint32_t)((kblk ^ (arow & 7)) * 16);
            uint32_t ahi[4], alo[4];
            LDMATRIX_X4(ahi[0], ahi[1], ahi[2], ahi[3], Qhi + aoff + asw);
            LDMATRIX_X4(alo[0], alo[1], alo[2], alo[3], Qlo + aoff + asw);
#pragma unroll
            for (int p = 0; p < 4; p++) {
                int row = p * 16 + lr;
                const uint32_t rsw = (uint32_t)(row * 128 + ((kblk ^ (row & 7)) * 16));
                uint32_t kh[4];
                LDMATRIX_X4(kh[0], kh[1], kh[2], kh[3], Kh + rsw);
#pragma unroll
                for (int o = 0; o < 2; o++) {
                    uint32_t b2[2] = { kh[o], kh[2 + o] };
                    mma16816(sacc[2 * p + o], ahi, b2);
                    mma16816(sacc[2 * p + o], alo, b2);
                }
                uint32_t kl[4];
                LDMATRIX_X4(kl[0], kl[1], kl[2], kl[3], Kl + rsw);
#pragma unroll
                for (int o = 0; o < 2; o++) {
                    uint32_t b2[2] = { kl[o], kl[2 + o] };
                    mma16816(sacc[2 * p + o], ahi, b2);
                }
            }
        }

        // ---- P = exp(S); accumulate row sums ----
#pragma unroll
        for (int ni = 0; ni < 8; ni++) {
            float p0 = __expf(sacc[ni][0]);
            float p1 = __expf(sacc[ni][1]);
            float p2 = __expf(sacc[ni][2]);
            float p3 = __expf(sacc[ni][3]);
            lsum0 += p0 + p1;
            lsum1 += p2 + p3;
            sacc[ni][0] = p0; sacc[ni][1] = p1;
            sacc[ni][2] = p2; sacc[ni][3] = p3;
        }

        // ---- ctx += P V^T : interleaved 3-term (Vhi loaded once per fragment) ----
#pragma unroll
        for (int jj = 0; jj < 4; jj++) {
            const int kblk = jj * 2 + lc;
            uint32_t phi[4], plo[4];
            phi[0] = packbf(sacc[2 * jj][0],     sacc[2 * jj][1]);
            phi[1] = packbf(sacc[2 * jj][2],     sacc[2 * jj][3]);
            phi[2] = packbf(sacc[2 * jj + 1][0], sacc[2 * jj + 1][1]);
            phi[3] = packbf(sacc[2 * jj + 1][2], sacc[2 * jj + 1][3]);
            plo[0] = packbf(lof(sacc[2 * jj][0]),     lof(sacc[2 * jj][1]));
            plo[1] = packbf(lof(sacc[2 * jj][2]),     lof(sacc[2 * jj][3]));
            plo[2] = packbf(lof(sacc[2 * jj + 1][0]), lof(sacc[2 * jj + 1][1]));
            plo[3] = packbf(lof(sacc[2 * jj + 1][2]), lof(sacc[2 * jj + 1][3]));
#pragma unroll
            for (int p = 0; p < 4; p++) {
                int row = p * 16 + lr;
                const uint32_t rsw = (uint32_t)(row * 128 + ((kblk ^ (row & 7)) * 16));
                uint32_t vh[4];
                LDMATRIX_X4(vh[0], vh[1], vh[2], vh[3], Vh + rsw);
#pragma unroll
                for (int o = 0; o < 2; o++) {
                    uint32_t b2[2] = { vh[o], vh[2 + o] };
                    mma16816(oacc[2 * p + o], phi, b2);
                    mma16816(oacc[2 * p + o], plo, b2);
                }
                uint32_t vl[4];
                LDMATRIX_X4(vl[0], vl[1], vl[2], vl[3], Vl + rsw);
#pragma unroll
                for (int o = 0; o < 2; o++) {
                    uint32_t b2[2] = { vl[o], vl[2 + o] };
                    mma16816(oacc[2 * p + o], phi, b2);
                }
            }
        }
    }

    // row-sum reduction over the quad (cq lanes)
    lsum0 += __shfl_xor_sync(0xffffffffu, lsum0, 1);
    lsum0 += __shfl_xor_sync(0xffffffffu, lsum0, 2);
    lsum1 += __shfl_xor_sync(0xffffffffu, lsum1, 1);
    lsum1 += __shfl_xor_sync(0xffffffffu, lsum1, 2);
    const float inv0 = 1.0f / lsum0;
    const float inv1 = 1.0f / lsum1;

    // epilogue: split write into g_ccvt [tok][3*512] at cols h*64 + n
#pragma unroll
    for (int half = 0; half < 2; half++) {
        const int m = q0 + wid * 16 + g + half * 8;
        const size_t tok = (size_t)b * SEQ + m;
        const size_t rb = tok * (3 * NU);
        const float inv = half ? inv1 : inv0;
#pragma unroll
        for (int ni = 0; ni < 8; ni++) {
            const int col = h * DK + ni * 8 + 2 * cq;
            float v0 = oacc[ni][half * 2 + 0] * inv;
            float v1 = oacc[ni][half * 2 + 1] * inv;
            __nv_bfloat16 h0, h1, l0, l1;
            split_bf16(v0, h0, l0); split_bf16(v1, h1, l1);
            uint32_t hp, lp;
            *(__nv_bfloat162*)&hp = __halves2bfloat162(h0, h1);
            *(__nv_bfloat162*)&lp = __halves2bfloat162(l0, l1);
            *(uint32_t*)(Ccvt + rb + col)          = hp;
            *(uint32_t*)(Ccvt + rb + NU + col)     = hp;
            *(uint32_t*)(Ccvt + rb + 2 * NU + col) = lp;
        }
    }
}

// ---------------------------------------------------------------------------
// LayerNorm over rows of 512; optionally also writes split-bf16 (A-style)
// ---------------------------------------------------------------------------
template<bool CVT>
__global__ __launch_bounds__(128) void ln_kernel(
    const float* __restrict__ X, const float* __restrict__ gamma,
    const float* __restrict__ beta, float* __restrict__ O,
    __nv_bfloat16* __restrict__ Ocvt)
{
    __shared__ float red[4];
    const int row = blockIdx.x;
    const int tid = threadIdx.x;

    float4 v = *(const float4*)(X + (size_t)row * NU + tid * 4);
    float s = v.x + v.y + v.z + v.w;
#pragma unroll
    for (int o = 16; o > 0; o >>= 1) s += __shfl_xor_sync(0xffffffffu, s, o);
    if ((tid & 31) == 0) red[tid >> 5] = s;
    __syncthreads();
    float mean = (red[0] + red[1] + red[2] + red[3]) * (1.0f / 512.0f);
    __syncthreads();

    float dx = v.x - mean, dy = v.y - mean, dz = v.z - mean, dw = v.w - mean;
    float sq = dx * dx + dy * dy + dz * dz + dw * dw;
#pragma unroll
    for (int o = 16; o > 0; o >>= 1) sq += __shfl_xor_sync(0xffffffffu, sq, o);
    if ((tid & 31) == 0) red[tid >> 5] = sq;
    __syncthreads();
    float var = (red[0] + red[1] + red[2] + red[3]) * (1.0f / 512.0f);
    float inv = rsqrtf(var + 1e-5f);

    float4 g = *(const float4*)(gamma + tid * 4);
    float4 b = *(const float4*)(beta  + tid * 4);
    float4 o4;
    o4.x = dx * inv * g.x + b.x;
    o4.y = dy * inv * g.y + b.y;
    o4.z = dz * inv * g.z + b.z;
    o4.w = dw * inv * g.w + b.w;
    *(float4*)(O + (size_t)row * NU + tid * 4) = o4;

    if (CVT) {
        __nv_bfloat16 h0, h1, h2, h3, l0, l1, l2, l3;
        split_bf16(o4.x, h0, l0); split_bf16(o4.y, h1, l1);
        split_bf16(o4.z, h2, l2); split_bf16(o4.w, h3, l3);
        uint2 hp, lp;
        *(__nv_bfloat162*)&hp.x = __halves2bfloat162(h0, h1);
        *(__nv_bfloat162*)&hp.y = __halves2bfloat162(h2, h3);
        *(__nv_bfloat162*)&lp.x = __halves2bfloat162(l0, l1);
        *(__nv_bfloat162*)&lp.y = __halves2bfloat162(l2, l3);
        size_t rb = (size_t)row * (3 * NU);
        int col = tid * 4;
        *(uint2*)(Ocvt + rb + col)            = hp;
        *(uint2*)(Ocvt + rb + NU + col)       = hp;
        *(uint2*)(Ocvt + rb + 2 * NU + col)   = lp;
    }
}

// ---------------------------------------------------------------------------
// Host orchestration (graph-capturable: kernel launches only)
// ---------------------------------------------------------------------------
extern "C" void kernel_launch(void* const* d_in, const int* in_sizes, int n_in,
                              void* d_out, int out_size)
{
    (void)in_sizes; (void)n_in; (void)out_size;

    const float* x     = (const float*)d_in[0];
    const float* Win   = (const float*)d_in[1];
    const float* bin   = (const float*)d_in[2];
    const float* ln1_g = (const float*)d_in[3];
    const float* ln1_b = (const float*)d_in[4];
    const float* Wq    = (const float*)d_in[5];
    const float* bq    = (const float*)d_in[6];
    const float* Wk    = (const float*)d_in[7];
    const float* bk    = (const float*)d_in[8];
    const float* Wv    = (const float*)d_in[9];
    const float* bv    = (const float*)d_in[10];
    const float* Wo    = (const float*)d_in[11];
    const float* bo    = (const float*)d_in[12];
    const float* ln2_g = (const float*)d_in[13];
    const float* ln2_b = (const float*)d_in[14];
    const float* W1    = (const float*)d_in[15];
    const float* b1    = (const float*)d_in[16];
    const float* W2    = (const float*)d_in[17];
    const float* b2    = (const float*)d_in[18];
    const float* lno_g = (const float*)d_in[19];
    const float* lno_b = (const float*)d_in[20];
    float* out = (float*)d_out;

    float *e, *bqkv;
    __nv_bfloat16 *xc, *ec, *cc, *hc, *Winc, *Wqkvc, *Woc, *W1c, *W2c;
    __nv_bfloat16 *qs, *ks, *vt;
    cudaGetSymbolAddress((void**)&e,    g_e);
    cudaGetSymbolAddress((void**)&bqkv, g_bqkv);
    cudaGetSymbolAddress((void**)&xc,   g_xcvt);
    cudaGetSymbolAddress((void**)&ec,   g_ecvt);
    cudaGetSymbolAddress((void**)&cc,   g_ccvt);
    cudaGetSymbolAddress((void**)&hc,   g_hcvt);
    cudaGetSymbolAddress((void**)&Winc,  g_Winc);
    cudaGetSymbolAddress((void**)&Wqkvc, g_Wqkvc);
    cudaGetSymbolAddress((void**)&Woc,   g_Woc);
    cudaGetSymbolAddress((void**)&W1c,   g_W1c);
    cudaGetSymbolAddress((void**)&W2c,   g_W2c);
    cudaGetSymbolAddress((void**)&qs,   g_qs);
    cudaGetSymbolAddress((void**)&ks,   g_ks);
    cudaGetSymbolAddress((void**)&vt,   g_vt);

    cudaFuncSetAttribute(mma_gemm<0>, cudaFuncAttributeMaxDynamicSharedMemorySize, GEMM_DSMEM);
    cudaFuncSetAttribute(mma_gemm<1>, cudaFuncAttributeMaxDynamicSharedMemorySize, GEMM_DSMEM);
    cudaFuncSetAttribute(mma_gemm<2>, cudaFuncAttributeMaxDynamicSharedMemorySize, GEMM_DSMEM);
    cudaFuncSetAttribute(mma_gemm<3>, cudaFuncAttributeMaxDynamicSharedMemorySize, GEMM_DSMEM);
    cudaFuncSetAttribute(flash_attn,  cudaFuncAttributeMaxDynamicSharedMemorySize, FA_DSMEM);

    // operand conversions (every launch; deterministic)
    {
        int t;
        t = NU * IDIM;          convert_B_kernel<<<(t + 255) / 256, 256>>>(Win, Winc, IDIM, t);
        t = NLAYERS * 3 * NU * NU;
                                convert_qkv_kernel<<<(t + 255) / 256, 256>>>(Wq, Wk, Wv, Wqkvc);
        t = NLAYERS * NU * NU;  convert_B_kernel<<<(t + 255) / 256, 256>>>(Wo, Woc, NU, t);
        t = NLAYERS * EU * NU;  convert_B_kernel<<<(t + 255) / 256, 256>>>(W1, W1c, NU, t);
        t = NLAYERS * NU * EU;  convert_B_kernel<<<(t + 255) / 256, 256>>>(W2, W2c, EU, t);
        t = TOK * IDIM;         convert_A_kernel<<<(t + 255) / 256, 256>>>(x, xc, IDIM, t);
        t = NLAYERS * QKVW;     pack_bqkv_kernel<<<(t + 255) / 256, 256>>>(bq, bk, bv, bqkv);
    }

    dim3 g512 (NU   / 128, TOK / 128);   // (4, 64)
    dim3 gqkv (QKVW / 128, TOK / 128);   // (12, 64)
    dim3 g2048(EU   / 128, TOK / 128);   // (16, 64)
    dim3 gflash(SEQ / 128, BH);          // (8, 64)

    // input projection: e = x @ Win^T + bin
    mma_gemm<0><<<g512, 256, GEMM_DSMEM>>>(xc, Winc, bin, nullptr, e, nullptr,
                                           nullptr, nullptr, nullptr, NU, 3 * IDIM);

    for (int i = 0; i < NLAYERS; i++) {
        const size_t wqkv = (size_t)i * QKVW * 3 * NU;
        const size_t wo   = (size_t)i * NU * 3 * NU;
        const size_t w1o  = (size_t)i * EU * 3 * NU;
        const size_t w2o  = (size_t)i * NU * 3 * EU;

        ln_kernel<true><<<TOK, 128>>>(e, ln1_g + i * NU, ln1_b + i * NU, e, ec);

        // fused qkv GEMM with direct attention-operand epilogue
        mma_gemm<3><<<gqkv, 256, GEMM_DSMEM>>>(ec, Wqkvc + wqkv, bqkv + i * QKVW, nullptr,
                                               nullptr, nullptr, qs, ks, vt, QKVW, 3 * NU);

        // fused attention
        flash_attn<<<gflash, 256, FA_DSMEM>>>(qs, ks, vt, cc);

        // e = e + ctx @ Wo^T + bo
        mma_gemm<1><<<g512, 256, GEMM_DSMEM>>>(cc, Woc + wo, bo + i * NU, e, e, nullptr,
                                               nullptr, nullptr, nullptr, NU, 3 * NU);

        ln_kernel<true><<<TOK, 128>>>(e, ln2_g + i * NU, ln2_b + i * NU, e, ec);

        // h = relu(e @ W1^T + b1) -> split bf16
        mma_gemm<2><<<g2048, 256, GEMM_DSMEM>>>(ec, W1c + w1o, b1 + (size_t)i * EU, nullptr,
                                                nullptr, hc, nullptr, nullptr, nullptr, EU, 3 * NU);
        // e = e + h @ W2^T + b2
        mma_gemm<1><<<g512, 256, GEMM_DSMEM>>>(hc, W2c + w2o, b2 + i * NU, e, e, nullptr,
                                               nullptr, nullptr, nullptr, NU, 3 * EU);
    }

    ln_kernel<false><<<TOK, 128>>>(e, lno_g, lno_b, out, nullptr);
}

// round 16
// speedup vs baseline: 1.4699x; 1.3185x over previous
#include <cuda_runtime.h>
#include <cuda_bf16.h>
#include <cuda_fp16.h>
#include <math.h>
#include <stdint.h>

// ---------------------------------------------------------------------------
// Problem constants
// ---------------------------------------------------------------------------
#define TOK      8192
#define IDIM     256
#define NU       512
#define EU       2048
#define NLAYERS  4
#define HEADS    8
#define DK       64
#define SEQ      1024
#define NBATCH   8
#define QKVW     1536
#define BH       (NBATCH * HEADS)   // 64

// ---------------------------------------------------------------------------
// Scratch (static device memory; allocation APIs are forbidden)
// ---------------------------------------------------------------------------
__device__ float g_e[TOK * NU];

// fp16 2-slab operand buffers: activations [hi|lo], weights [hi|hi], width 2K
__device__ __half g_xcvt [TOK * 2 * IDIM];
__device__ __half g_ecvt [TOK * 2 * NU];
__device__ __half g_ccvt [TOK * 2 * NU];
__device__ __half g_hcvt [TOK * 2 * EU];

__device__ __half g_Winc  [NU * 2 * IDIM];
__device__ __half g_Wqkvc [NLAYERS * QKVW * 2 * NU];
__device__ __half g_Woc   [NLAYERS * NU * 2 * NU];
__device__ __half g_W1c   [NLAYERS * EU * 2 * NU];
__device__ __half g_W2c   [NLAYERS * NU * 2 * EU];
__device__ float  g_bqkv  [NLAYERS * QKVW];

// attention operands (bf16, 3-term via hi/lo slabs — unchanged, verified)
__device__ __nv_bfloat16 g_qs [BH * SEQ * 128];        // [bh][t][hi64|lo64] (scaled)
__device__ __nv_bfloat16 g_ks [BH * SEQ * 128];        // [bh][t][hi64|lo64]
__device__ __nv_bfloat16 g_vt [BH * DK * 2 * SEQ];     // [bh][d][hi@s | lo@1024+s]

// ---------------------------------------------------------------------------
// split helpers
// ---------------------------------------------------------------------------
__device__ __forceinline__ void split_bf16(float f, __nv_bfloat16& hi, __nv_bfloat16& lo) {
    hi = __float2bfloat16(f);
    lo = __float2bfloat16(f - __bfloat162float(hi));
}
__device__ __forceinline__ void split_h16(float f, __half& hi, __half& lo) {
    hi = __float2half(f);
    lo = __float2half(f - __half2float(hi));
}
__device__ __forceinline__ uint32_t packbf(float a, float b) {
    __nv_bfloat162 t = __halves2bfloat162(__float2bfloat16(a), __float2bfloat16(b));
    return *(uint32_t*)&t;
}
__device__ __forceinline__ uint32_t packh(__half a, __half b) {
    __half2 t = __halves2half2(a, b);
    return *(uint32_t*)&t;
}
__device__ __forceinline__ float lof(float a) {
    return a - __bfloat162float(__float2bfloat16(a));
}

// weights: out row = [hi | hi], row width 2K (fp16 2-term: only hi used)
__global__ void convert_B_kernel(const float* __restrict__ W, __half* __restrict__ out,
                                 int K, int total) {
    int idx = blockIdx.x * 256 + threadIdx.x;
    if (idx >= total) return;
    int n = idx / K, k = idx - n * K;
    __half hi = __float2half(W[idx]);
    size_t base = (size_t)n * 2 * K;
    out[base + k] = hi;
    out[base + K + k] = hi;
}

// batched qkv weight conversion: all layers, q|k|v, one launch ([hi|hi] fp16)
__global__ void convert_qkv_kernel(const float* __restrict__ Wq, const float* __restrict__ Wk,
                                   const float* __restrict__ Wv, __half* __restrict__ out) {
    const int per = NU * NU;
    int idx = blockIdx.x * 256 + threadIdx.x;
    if (idx >= NLAYERS * 3 * per) return;
    int mat = idx / per;
    int rem = idx - mat * per;
    int l = mat / 3, sec = mat - l * 3;
    int n = rem / NU, k = rem - n * NU;
    const float* W = (sec == 0) ? Wq : (sec == 1) ? Wk : Wv;
    __half hi = __float2half(W[(size_t)l * per + rem]);
    size_t base = (size_t)l * QKVW * 2 * NU + (size_t)(sec * NU + n) * 2 * NU;
    out[base + k] = hi;
    out[base + NU + k] = hi;
}

// activations: out row = [hi | lo] fp16
__global__ void convert_A_kernel(const float* __restrict__ A, __half* __restrict__ out,
                                 int K, int total) {
    int idx = blockIdx.x * 256 + threadIdx.x;
    if (idx >= total) return;
    int n = idx / K, k = idx - n * K;
    __half hi, lo;
    split_h16(A[idx], hi, lo);
    size_t base = (size_t)n * 2 * K;
    out[base + k] = hi;
    out[base + K + k] = lo;
}

// pack per-layer q|k|v biases into 1536-wide rows
__global__ void pack_bqkv_kernel(const float* __restrict__ bq, const float* __restrict__ bk,
                                 const float* __restrict__ bv, float* __restrict__ out) {
    int i = blockIdx.x * 256 + threadIdx.x;
    if (i >= NLAYERS * QKVW) return;
    int l = i / QKVW, c = i - l * QKVW;
    float v = (c < NU) ? bq[l * NU + c]
            : (c < 2 * NU) ? bk[l * NU + c - NU]
            : bv[l * NU + c - 2 * NU];
    out[i] = v;
}

// ---------------------------------------------------------------------------
// mma.sync common pieces
// ---------------------------------------------------------------------------
#define STAGE_BYTES 32768
#define GEMM_DSMEM  (2 * STAGE_BYTES)
#define FA_STAGE    32768          // Khi 8K | Klo 8K | Vhi 8K | Vlo 8K (64 s-rows)
#define FA_DSMEM    (32768 + 2 * FA_STAGE)   // Q 32K + 2 stages = 96K -> 2 CTAs/SM

__device__ __forceinline__ uint32_t smem_u32(const void* p) {
    uint32_t a;
    asm("{ .reg .u64 t; cvta.to.shared.u64 t, %1; cvt.u32.u64 %0, t; }" : "=r"(a) : "l"(p));
    return a;
}

#define CP_ASYNC16(dst, src) \
    asm volatile("cp.async.cg.shared.global [%0], [%1], 16;" :: "r"(dst), "l"(src) : "memory")
#define CP_COMMIT() asm volatile("cp.async.commit_group;" ::: "memory")
#define CP_WAIT0()  asm volatile("cp.async.wait_group 0;" ::: "memory")

#define LDMATRIX_X4(r0, r1, r2, r3, addr) \
    asm volatile("ldmatrix.sync.aligned.m8n8.x4.shared.b16 {%0,%1,%2,%3}, [%4];" \
        : "=r"(r0), "=r"(r1), "=r"(r2), "=r"(r3) : "r"(addr))

__device__ __forceinline__ void mma16816(float* d, const uint32_t* a, const uint32_t* b) {
    asm volatile(
        "mma.sync.aligned.m16n8k16.row.col.f32.bf16.bf16.f32 "
        "{%0,%1,%2,%3}, {%4,%5,%6,%7}, {%8,%9}, {%0,%1,%2,%3};"
        : "+f"(d[0]), "+f"(d[1]), "+f"(d[2]), "+f"(d[3])
        : "r"(a[0]), "r"(a[1]), "r"(a[2]), "r"(a[3]), "r"(b[0]), "r"(b[1]));
}
__device__ __forceinline__ void mma16816h(float* d, const uint32_t* a, const uint32_t* b) {
    asm volatile(
        "mma.sync.aligned.m16n8k16.row.col.f32.f16.f16.f32 "
        "{%0,%1,%2,%3}, {%4,%5,%6,%7}, {%8,%9}, {%0,%1,%2,%3};"
        : "+f"(d[0]), "+f"(d[1]), "+f"(d[2]), "+f"(d[3])
        : "r"(a[0]), "r"(a[1]), "r"(a[2]), "r"(a[3]), "r"(b[0]), "r"(b[1]));
}

// ---------------------------------------------------------------------------
// Linear GEMM (fp16 2-term): C[M,N] = A[M,Kp] @ B[N,Kp]^T, Kp = 2*K
// EP: 0 = fp32 out, 1 = fp32 + residual, 2 = relu + fp16 [hi|lo] out
//     3 = fused qkv epilogue: write per-head bf16 attention operand layouts
// ---------------------------------------------------------------------------
template<int EP>
__global__ __launch_bounds__(256) void mma_gemm(
    const __half* __restrict__ A, const __half* __restrict__ B,
    const float* __restrict__ bias, const float* __restrict__ res,
    float* __restrict__ Cf, __half* __restrict__ Cb,
    __nv_bfloat16* __restrict__ q_out, __nv_bfloat16* __restrict__ k_out,
    __nv_bfloat16* __restrict__ v_out,
    int N, int Kp)
{
    extern __shared__ __align__(16) char dsm[];
    const uint32_t sbase = smem_u32(dsm);

    const int tid  = threadIdx.x;
    const int wid  = tid >> 5;
    const int lane = tid & 31;
    const int g    = lane >> 2;
    const int cq   = lane & 3;
    const int lr   = lane & 15;
    const int lc   = lane >> 4;
    const int wm   = wid & 3;
    const int wn   = wid >> 2;
    const int n0   = blockIdx.x * 128;
    const int m0   = blockIdx.y * 128;

    const __half* Ap = A + (size_t)m0 * Kp;
    const __half* Bp = B + (size_t)n0 * Kp;
    const int nchunk = Kp >> 6;

    float acc[2][8][4];
#pragma unroll
    for (int mi = 0; mi < 2; mi++)
#pragma unroll
        for (int ni = 0; ni < 8; ni++)
#pragma unroll
            for (int r = 0; r < 4; r++) acc[mi][ni][r] = 0.0f;

    auto load_stage = [&](int c, int stage) {
        const int k0 = c << 6;
        const uint32_t sA = sbase + stage * STAGE_BYTES;
        const uint32_t sB = sA + 16384;
#pragma unroll
        for (int i = 0; i < 4; i++) {
            int lin = tid + i * 256;
            int r   = lin >> 3;
            int c16 = lin & 7;
            uint32_t off = (uint32_t)(r * 128 + ((c16 ^ (r & 7)) * 16));
            CP_ASYNC16(sA + off, (const void*)(Ap + (size_t)r * Kp + k0 + c16 * 8));
            CP_ASYNC16(sB + off, (const void*)(Bp + (size_t)r * Kp + k0 + c16 * 8));
        }
    };

    load_stage(0, 0);
    CP_COMMIT();

    for (int c = 0; c < nchunk; c++) {
        const int cur = c & 1;
        CP_WAIT0();
        __syncthreads();
        if (c + 1 < nchunk) {
            load_stage(c + 1, cur ^ 1);
            CP_COMMIT();
        }

        const uint32_t sA = sbase + cur * STAGE_BYTES;
        const uint32_t sB = sA + 16384;

#pragma unroll
        for (int ks = 0; ks < 4; ks++) {
            const int kblk = ks * 2 + lc;
            uint32_t afr[2][4], bfr[4][4];
#pragma unroll
            for (int mi = 0; mi < 2; mi++) {
                int row = wm * 32 + mi * 16 + lr;
                uint32_t addr = sA + (uint32_t)(row * 128 + ((kblk ^ (row & 7)) * 16));
                LDMATRIX_X4(afr[mi][0], afr[mi][1], afr[mi][2], afr[mi][3], addr);
            }
#pragma unroll
            for (int p = 0; p < 4; p++) {
                int row = wn * 64 + p * 16 + lr;
                uint32_t addr = sB + (uint32_t)(row * 128 + ((kblk ^ (row & 7)) * 16));
                LDMATRIX_X4(bfr[p][0], bfr[p][1], bfr[p][2], bfr[p][3], addr);
            }
#pragma unroll
            for (int mi = 0; mi < 2; mi++)
#pragma unroll
                for (int ni = 0; ni < 8; ni++) {
                    const int p = ni >> 1, o = ni & 1;
                    uint32_t b2[2] = { bfr[p][o], bfr[p][2 + o] };
                    mma16816h(acc[mi][ni], afr[mi], b2);
                }
        }
    }

#pragma unroll
    for (int mi = 0; mi < 2; mi++) {
#pragma unroll
        for (int half = 0; half < 2; half++) {
            const int m = m0 + wm * 32 + mi * 16 + g + half * 8;
#pragma unroll
            for (int ni = 0; ni < 8; ni++) {
                const int n = n0 + wn * 64 + ni * 8 + 2 * cq;
                float2 bv = *(const float2*)(bias + n);
                float v0 = acc[mi][ni][half * 2 + 0] + bv.x;
                float v1 = acc[mi][ni][half * 2 + 1] + bv.y;
                if (EP == 2) {
                    v0 = fmaxf(v0, 0.f); v1 = fmaxf(v1, 0.f);
                    __half h0, h1, l0, l1;
                    split_h16(v0, h0, l0); split_h16(v1, h1, l1);
                    size_t rb = (size_t)m * 2 * N;
                    *(uint32_t*)(Cb + rb + n)     = packh(h0, h1);
                    *(uint32_t*)(Cb + rb + N + n) = packh(l0, l1);
                } else if (EP == 3) {
                    const int sec = n >> 9;            // 0=q 1=k 2=v
                    const int hh  = (n >> 6) & 7;      // head
                    const int d   = n & 63;            // dim within head (even)
                    const int t   = m & (SEQ - 1);
                    const int bh  = (m >> 10) * HEADS + hh;
                    if (sec == 0) {
                        float q0 = v0 * 0.125f, q1 = v1 * 0.125f;
                        __nv_bfloat16 h0, h1, l0, l1;
                        split_bf16(q0, h0, l0); split_bf16(q1, h1, l1);
                        uint32_t hp, lp;
                        *(__nv_bfloat162*)&hp = __halves2bfloat162(h0, h1);
                        *(__nv_bfloat162*)&lp = __halves2bfloat162(l0, l1);
                        __nv_bfloat16* qb = q_out + ((size_t)bh * SEQ + t) * 128 + d;
                        *(uint32_t*)(qb)      = hp;
                        *(uint32_t*)(qb + 64) = lp;
                    } else if (sec == 1) {
                        __nv_bfloat16 h0, h1, l0, l1;
                        split_bf16(v0, h0, l0); split_bf16(v1, h1, l1);
                        uint32_t hp, lp;
                        *(__nv_bfloat162*)&hp = __halves2bfloat162(h0, h1);
                        *(__nv_bfloat162*)&lp = __halves2bfloat162(l0, l1);
                        __nv_bfloat16* kb = k_out + ((size_t)bh * SEQ + t) * 128 + d;
                        *(uint32_t*)(kb)      = hp;
                        *(uint32_t*)(kb + 64) = lp;
                    } else {
                        __nv_bfloat16 h0, h1, l0, l1;
                        split_bf16(v0, h0, l0); split_bf16(v1, h1, l1);
                        __nv_bfloat16* vb0 = v_out + ((size_t)bh * DK + d) * (2 * SEQ) + t;
                        __nv_bfloat16* vb1 = vb0 + 2 * SEQ;
                        vb0[0]   = h0; vb0[SEQ] = l0;
                        vb1[0]   = h1; vb1[SEQ] = l1;
                    }
                } else {
                    if (EP == 1) {
                        float2 rv = *(const float2*)(res + (size_t)m * N + n);
                        v0 += rv.x; v1 += rv.y;
                    }
                    *(float2*)(Cf + (size_t)m * N + n) = make_float2(v0, v1);
                }
            }
        }
    }
}

// ---------------------------------------------------------------------------
// Fused flash attention (bf16 3-term, no-max softmax) — verified R14/R15.
// Only the ctx epilogue changed: writes fp16 [hi|lo] (width 2*NU) for Wo GEMM.
// ---------------------------------------------------------------------------
__global__ __launch_bounds__(256, 2) void flash_attn(
    const __nv_bfloat16* __restrict__ qs, const __nv_bfloat16* __restrict__ ks,
    const __nv_bfloat16* __restrict__ vt, __half* __restrict__ Ccvt)
{
    extern __shared__ __align__(16) char dsm[];
    const uint32_t sb  = smem_u32(dsm);
    const uint32_t Qhi = sb;               // [128][64] bf16
    const uint32_t Qlo = sb + 16384;
    const uint32_t ST0 = sb + 32768;       // stage: Khi 8K | Klo 8K | Vhi 8K | Vlo 8K

    const int tid  = threadIdx.x;
    const int wid  = tid >> 5;
    const int lane = tid & 31;
    const int g    = lane >> 2;
    const int cq   = lane & 3;
    const int lr   = lane & 15;
    const int lc   = lane >> 4;
    const int q0   = blockIdx.x * 128;
    const int bh   = blockIdx.y;
    const int b    = bh >> 3, h = bh & 7;

    // --- load Q (once) ---
#pragma unroll
    for (int i = 0; i < 8; i++) {
        int id = tid + i * 256;
        int slab = id >> 10, r = (id >> 3) & 127, u = id & 7;
        const __nv_bfloat16* src = qs + ((size_t)bh * SEQ + q0 + r) * 128 + slab * 64 + u * 8;
        CP_ASYNC16((slab ? Qlo : Qhi) + (uint32_t)(r * 128 + ((u ^ (r & 7)) * 16)), src);
    }

    auto load_kv = [&](int st, uint32_t stage) {
        const int s0 = st * 64;
#pragma unroll
        for (int i = 0; i < 4; i++) {          // K: 2 slabs x 64 rows x 8 units
            int id = tid + i * 256;
            int slab = id >> 9, r = (id >> 3) & 63, u = id & 7;
            const __nv_bfloat16* src = ks + ((size_t)bh * SEQ + s0 + r) * 128 + slab * 64 + u * 8;
            CP_ASYNC16(stage + slab * 8192 + (uint32_t)(r * 128 + ((u ^ (r & 7)) * 16)), src);
        }
#pragma unroll
        for (int i = 0; i < 4; i++) {          // V: 2 slabs x 64 rows x 8 units
            int id = tid + i * 256;
            int slab = id >> 9, r = (id >> 3) & 63, u = id & 7;
            const __nv_bfloat16* src = vt + ((size_t)bh * DK + r) * (2 * SEQ) + slab * SEQ + s0 + u * 8;
            CP_ASYNC16(stage + 16384 + slab * 8192 + (uint32_t)(r * 128 + ((u ^ (r & 7)) * 16)), src);
        }
    };

    load_kv(0, ST0);
    CP_COMMIT();

    float oacc[8][4];
#pragma unroll
    for (int ni = 0; ni < 8; ni++)
#pragma unroll
        for (int r = 0; r < 4; r++) oacc[ni][r] = 0.0f;
    float lsum0 = 0.0f, lsum1 = 0.0f;

    const int arow = wid * 16 + lr;
    const uint32_t aoff = (uint32_t)(arow * 128);

    for (int st = 0; st < 16; st++) {
        const int cur = st & 1;
        CP_WAIT0();
        __syncthreads();
        if (st + 1 < 16) {
            load_kv(st + 1, ST0 + (cur ^ 1) * FA_STAGE);
            CP_COMMIT();
        }

        const uint32_t Kh = ST0 + cur * FA_STAGE;
        const uint32_t Kl = Kh + 8192;
        const uint32_t Vh = Kh + 16384;
        const uint32_t Vl = Kh + 24576;

        // ---- S = Q K^T : interleaved 3-term ----
        float sacc[8][4];
#pragma unroll
        for (int ni = 0; ni < 8; ni++)
#pragma unroll
            for (int r = 0; r < 4; r++) sacc[ni][r] = 0.0f;

#pragma unroll
        for (int j = 0; j < 4; j++) {
            const int kblk = j * 2 + lc;
            const uint32_t asw = (uint32_t)((kblk ^ (arow & 7)) * 16);
            uint32_t ahi[4], alo[4];
            LDMATRIX_X4(ahi[0], ahi[1], ahi[2], ahi[3], Qhi + aoff + asw);
            LDMATRIX_X4(alo[0], alo[1], alo[2], alo[3], Qlo + aoff + asw);
#pragma unroll
            for (int p = 0; p < 4; p++) {
                int row = p * 16 + lr;
                const uint32_t rsw = (uint32_t)(row * 128 + ((kblk ^ (row & 7)) * 16));
                uint32_t kh[4];
                LDMATRIX_X4(kh[0], kh[1], kh[2], kh[3], Kh + rsw);
#pragma unroll
                for (int o = 0; o < 2; o++) {
                    uint32_t b2[2] = { kh[o], kh[2 + o] };
                    mma16816(sacc[2 * p + o], ahi, b2);
                    mma16816(sacc[2 * p + o], alo, b2);
                }
                uint32_t kl[4];
                LDMATRIX_X4(kl[0], kl[1], kl[2], kl[3], Kl + rsw);
#pragma unroll
                for (int o = 0; o < 2; o++) {
                    uint32_t b2[2] = { kl[o], kl[2 + o] };
                    mma16816(sacc[2 * p + o], ahi, b2);
                }
            }
        }

        // ---- P = exp(S); accumulate row sums ----
#pragma unroll
        for (int ni = 0; ni < 8; ni++) {
            float p0 = __expf(sacc[ni][0]);
            float p1 = __expf(sacc[ni][1]);
            float p2 = __expf(sacc[ni][2]);
            float p3 = __expf(sacc[ni][3]);
            lsum0 += p0 + p1;
            lsum1 += p2 + p3;
            sacc[ni][0] = p0; sacc[ni][1] = p1;
            sacc[ni][2] = p2; sacc[ni][3] = p3;
        }

        // ---- ctx += P V^T : interleaved 3-term ----
#pragma unroll
        for (int jj = 0; jj < 4; jj++) {
            const int kblk = jj * 2 + lc;
            uint32_t phi[4], plo[4];
            phi[0] = packbf(sacc[2 * jj][0],     sacc[2 * jj][1]);
            phi[1] = packbf(sacc[2 * jj][2],     sacc[2 * jj][3]);
            phi[2] = packbf(sacc[2 * jj + 1][0], sacc[2 * jj + 1][1]);
            phi[3] = packbf(sacc[2 * jj + 1][2], sacc[2 * jj + 1][3]);
            plo[0] = packbf(lof(sacc[2 * jj][0]),     lof(sacc[2 * jj][1]));
            plo[1] = packbf(lof(sacc[2 * jj][2]),     lof(sacc[2 * jj][3]));
            plo[2] = packbf(lof(sacc[2 * jj + 1][0]), lof(sacc[2 * jj + 1][1]));
            plo[3] = packbf(lof(sacc[2 * jj + 1][2]), lof(sacc[2 * jj + 1][3]));
#pragma unroll
            for (int p = 0; p < 4; p++) {
                int row = p * 16 + lr;
                const uint32_t rsw = (uint32_t)(row * 128 + ((kblk ^ (row & 7)) * 16));
                uint32_t vh[4];
                LDMATRIX_X4(vh[0], vh[1], vh[2], vh[3], Vh + rsw);
#pragma unroll
                for (int o = 0; o < 2; o++) {
                    uint32_t b2[2] = { vh[o], vh[2 + o] };
                    mma16816(oacc[2 * p + o], phi, b2);
                    mma16816(oacc[2 * p + o], plo, b2);
                }
                uint32_t vl[4];
                LDMATRIX_X4(vl[0], vl[1], vl[2], vl[3], Vl + rsw);
#pragma unroll
                for (int o = 0; o < 2; o++) {
                    uint32_t b2[2] = { vl[o], vl[2 + o] };
                    mma16816(oacc[2 * p + o], phi, b2);
                }
            }
        }
    }

    // row-sum reduction over the quad (cq lanes)
    lsum0 += __shfl_xor_sync(0xffffffffu, lsum0, 1);
    lsum0 += __shfl_xor_sync(0xffffffffu, lsum0, 2);
    lsum1 += __shfl_xor_sync(0xffffffffu, lsum1, 1);
    lsum1 += __shfl_xor_sync(0xffffffffu, lsum1, 2);
    const float inv0 = 1.0f / lsum0;
    const float inv1 = 1.0f / lsum1;

    // epilogue: fp16 [hi|lo] write into g_ccvt [tok][2*512] at cols h*64 + n
#pragma unroll
    for (int half = 0; half < 2; half++) {
        const int m = q0 + wid * 16 + g + half * 8;
        const size_t tok = (size_t)b * SEQ + m;
        const size_t rb = tok * (2 * NU);
        const float inv = half ? inv1 : inv0;
#pragma unroll
        for (int ni = 0; ni < 8; ni++) {
            const int col = h * DK + ni * 8 + 2 * cq;
            float v0 = oacc[ni][half * 2 + 0] * inv;
            float v1 = oacc[ni][half * 2 + 1] * inv;
            __half h0, h1, l0, l1;
            split_h16(v0, h0, l0); split_h16(v1, h1, l1);
            *(uint32_t*)(Ccvt + rb + col)      = packh(h0, h1);
            *(uint32_t*)(Ccvt + rb + NU + col) = packh(l0, l1);
        }
    }
}

// ---------------------------------------------------------------------------
// LayerNorm over rows of 512; optionally also writes fp16 [hi|lo]
// ---------------------------------------------------------------------------
template<bool CVT>
__global__ __launch_bounds__(128) void ln_kernel(
    const float* __restrict__ X, const float* __restrict__ gamma,
    const float* __restrict__ beta, float* __restrict__ O,
    __half* __restrict__ Ocvt)
{
    __shared__ float red[4];
    const int row = blockIdx.x;
    const int tid = threadIdx.x;

    float4 v = *(const float4*)(X + (size_t)row * NU + tid * 4);
    float s = v.x + v.y + v.z + v.w;
#pragma unroll
    for (int o = 16; o > 0; o >>= 1) s += __shfl_xor_sync(0xffffffffu, s, o);
    if ((tid & 31) == 0) red[tid >> 5] = s;
    __syncthreads();
    float mean = (red[0] + red[1] + red[2] + red[3]) * (1.0f / 512.0f);
    __syncthreads();

    float dx = v.x - mean, dy = v.y - mean, dz = v.z - mean, dw = v.w - mean;
    float sq = dx * dx + dy * dy + dz * dz + dw * dw;
#pragma unroll
    for (int o = 16; o > 0; o >>= 1) sq += __shfl_xor_sync(0xffffffffu, sq, o);
    if ((tid & 31) == 0) red[tid >> 5] = sq;
    __syncthreads();
    float var = (red[0] + red[1] + red[2] + red[3]) * (1.0f / 512.0f);
    float inv = rsqrtf(var + 1e-5f);

    float4 g = *(const float4*)(gamma + tid * 4);
    float4 b = *(const float4*)(beta  + tid * 4);
    float4 o4;
    o4.x = dx * inv * g.x + b.x;
    o4.y = dy * inv * g.y + b.y;
    o4.z = dz * inv * g.z + b.z;
    o4.w = dw * inv * g.w + b.w;
    *(float4*)(O + (size_t)row * NU + tid * 4) = o4;

    if (CVT) {
        __half h0, h1, h2, h3, l0, l1, l2, l3;
        split_h16(o4.x, h0, l0); split_h16(o4.y, h1, l1);
        split_h16(o4.z, h2, l2); split_h16(o4.w, h3, l3);
        uint2 hp, lp;
        hp.x = packh(h0, h1); hp.y = packh(h2, h3);
        lp.x = packh(l0, l1); lp.y = packh(l2, l3);
        size_t rb = (size_t)row * (2 * NU);
        int col = tid * 4;
        *(uint2*)(Ocvt + rb + col)      = hp;
        *(uint2*)(Ocvt + rb + NU + col) = lp;
    }
}

// ---------------------------------------------------------------------------
// Host orchestration (graph-capturable: kernel launches only)
// ---------------------------------------------------------------------------
extern "C" void kernel_launch(void* const* d_in, const int* in_sizes, int n_in,
                              void* d_out, int out_size)
{
    (void)in_sizes; (void)n_in; (void)out_size;

    const float* x     = (const float*)d_in[0];
    const float* Win   = (const float*)d_in[1];
    const float* bin   = (const float*)d_in[2];
    const float* ln1_g = (const float*)d_in[3];
    const float* ln1_b = (const float*)d_in[4];
    const float* Wq    = (const float*)d_in[5];
    const float* bq    = (const float*)d_in[6];
    const float* Wk    = (const float*)d_in[7];
    const float* bk    = (const float*)d_in[8];
    const float* Wv    = (const float*)d_in[9];
    const float* bv    = (const float*)d_in[10];
    const float* Wo    = (const float*)d_in[11];
    const float* bo    = (const float*)d_in[12];
    const float* ln2_g = (const float*)d_in[13];
    const float* ln2_b = (const float*)d_in[14];
    const float* W1    = (const float*)d_in[15];
    const float* b1    = (const float*)d_in[16];
    const float* W2    = (const float*)d_in[17];
    const float* b2    = (const float*)d_in[18];
    const float* lno_g = (const float*)d_in[19];
    const float* lno_b = (const float*)d_in[20];
    float* out = (float*)d_out;

    float *e, *bqkv;
    __half *xc, *ec, *cc, *hc, *Winc, *Wqkvc, *Woc, *W1c, *W2c;
    __nv_bfloat16 *qs, *ks, *vt;
    cudaGetSymbolAddress((void**)&e,    g_e);
    cudaGetSymbolAddress((void**)&bqkv, g_bqkv);
    cudaGetSymbolAddress((void**)&xc,   g_xcvt);
    cudaGetSymbolAddress((void**)&ec,   g_ecvt);
    cudaGetSymbolAddress((void**)&cc,   g_ccvt);
    cudaGetSymbolAddress((void**)&hc,   g_hcvt);
    cudaGetSymbolAddress((void**)&Winc,  g_Winc);
    cudaGetSymbolAddress((void**)&Wqkvc, g_Wqkvc);
    cudaGetSymbolAddress((void**)&Woc,   g_Woc);
    cudaGetSymbolAddress((void**)&W1c,   g_W1c);
    cudaGetSymbolAddress((void**)&W2c,   g_W2c);
    cudaGetSymbolAddress((void**)&qs,   g_qs);
    cudaGetSymbolAddress((void**)&ks,   g_ks);
    cudaGetSymbolAddress((void**)&vt,   g_vt);

    cudaFuncSetAttribute(mma_gemm<0>, cudaFuncAttributeMaxDynamicSharedMemorySize, GEMM_DSMEM);
    cudaFuncSetAttribute(mma_gemm<1>, cudaFuncAttributeMaxDynamicSharedMemorySize, GEMM_DSMEM);
    cudaFuncSetAttribute(mma_gemm<2>, cudaFuncAttributeMaxDynamicSharedMemorySize, GEMM_DSMEM);
    cudaFuncSetAttribute(mma_gemm<3>, cudaFuncAttributeMaxDynamicSharedMemorySize, GEMM_DSMEM);
    cudaFuncSetAttribute(flash_attn,  cudaFuncAttributeMaxDynamicSharedMemorySize, FA_DSMEM);

    // operand conversions (every launch; deterministic)
    {
        int t;
        t = NU * IDIM;          convert_B_kernel<<<(t + 255) / 256, 256>>>(Win, Winc, IDIM, t);
        t = NLAYERS * 3 * NU * NU;
                                convert_qkv_kernel<<<(t + 255) / 256, 256>>>(Wq, Wk, Wv, Wqkvc);
        t = NLAYERS * NU * NU;  convert_B_kernel<<<(t + 255) / 256, 256>>>(Wo, Woc, NU, t);
        t = NLAYERS * EU * NU;  convert_B_kernel<<<(t + 255) / 256, 256>>>(W1, W1c, NU, t);
        t = NLAYERS * NU * EU;  convert_B_kernel<<<(t + 255) / 256, 256>>>(W2, W2c, EU, t);
        t = TOK * IDIM;         convert_A_kernel<<<(t + 255) / 256, 256>>>(x, xc, IDIM, t);
        t = NLAYERS * QKVW;     pack_bqkv_kernel<<<(t + 255) / 256, 256>>>(bq, bk, bv, bqkv);
    }

    dim3 g512 (NU   / 128, TOK / 128);   // (4, 64)
    dim3 gqkv (QKVW / 128, TOK / 128);   // (12, 64)
    dim3 g2048(EU   / 128, TOK / 128);   // (16, 64)
    dim3 gflash(SEQ / 128, BH);          // (8, 64)

    // input projection: e = x @ Win^T + bin
    mma_gemm<0><<<g512, 256, GEMM_DSMEM>>>(xc, Winc, bin, nullptr, e, nullptr,
                                           nullptr, nullptr, nullptr, NU, 2 * IDIM);

    for (int i = 0; i < NLAYERS; i++) {
        const size_t wqkv = (size_t)i * QKVW * 2 * NU;
        const size_t wo   = (size_t)i * NU * 2 * NU;
        const size_t w1o  = (size_t)i * EU * 2 * NU;
        const size_t w2o  = (size_t)i * NU * 2 * EU;

        ln_kernel<true><<<TOK, 128>>>(e, ln1_g + i * NU, ln1_b + i * NU, e, ec);

        // fused qkv GEMM with direct attention-operand epilogue
        mma_gemm<3><<<gqkv, 256, GEMM_DSMEM>>>(ec, Wqkvc + wqkv, bqkv + i * QKVW, nullptr,
                                               nullptr, nullptr, qs, ks, vt, QKVW, 2 * NU);

        // fused attention
        flash_attn<<<gflash, 256, FA_DSMEM>>>(qs, ks, vt, cc);

        // e = e + ctx @ Wo^T + bo
        mma_gemm<1><<<g512, 256, GEMM_DSMEM>>>(cc, Woc + wo, bo + i * NU, e, e, nullptr,
                                               nullptr, nullptr, nullptr, NU, 2 * NU);

        ln_kernel<true><<<TOK, 128>>>(e, ln2_g + i * NU, ln2_b + i * NU, e, ec);

        // h = relu(e @ W1^T + b1) -> fp16 [hi|lo]
        mma_gemm<2><<<g2048, 256, GEMM_DSMEM>>>(ec, W1c + w1o, b1 + (size_t)i * EU, nullptr,
                                                nullptr, hc, nullptr, nullptr, nullptr, EU, 2 * NU);
        // e = e + h @ W2^T + b2
        mma_gemm<1><<<g512, 256, GEMM_DSMEM>>>(hc, W2c + w2o, b2 + i * NU, e, e, nullptr,
                                               nullptr, nullptr, nullptr, NU, 2 * EU);
    }

    ln_kernel<false><<<TOK, 128>>>(e, lno_g, lno_b, out, nullptr);
}

// round 17
// speedup vs baseline: 1.6109x; 1.0959x over previous
#include <cuda_runtime.h>
#include <cuda_bf16.h>
#include <cuda_fp16.h>
#include <math.h>
#include <stdint.h>

// ---------------------------------------------------------------------------
// Problem constants
// ---------------------------------------------------------------------------
#define TOK      8192
#define IDIM     256
#define NU       512
#define EU       2048
#define NLAYERS  4
#define HEADS    8
#define DK       64
#define SEQ      1024
#define NBATCH   8
#define QKVW     1536
#define BH       (NBATCH * HEADS)   // 64

// ---------------------------------------------------------------------------
// Scratch (static device memory; allocation APIs are forbidden)
// ---------------------------------------------------------------------------
__device__ float g_e[TOK * NU];

// fp16 2-slab operand buffers: activations [hi|lo], weights [hi|hi], width 2K
__device__ __half g_xcvt [TOK * 2 * IDIM];
__device__ __half g_ecvt [TOK * 2 * NU];
__device__ __half g_ccvt [TOK * 2 * NU];
__device__ __half g_hcvt [TOK * 2 * EU];

__device__ __half g_Winc  [NU * 2 * IDIM];
__device__ __half g_Wqkvc [NLAYERS * QKVW * 2 * NU];
__device__ __half g_Woc   [NLAYERS * NU * 2 * NU];
__device__ __half g_W1c   [NLAYERS * EU * 2 * NU];
__device__ __half g_W2c   [NLAYERS * NU * 2 * EU];
__device__ float  g_bqkv  [NLAYERS * QKVW];

// attention operands, fp16 2-term: Q [hi|lo], K hi-only, V^T hi-only
__device__ __half g_qs [BH * SEQ * 128];   // [bh][t][hi64|lo64] (scaled)
__device__ __half g_ks [BH * SEQ * 64];    // [bh][t][hi64]
__device__ __half g_vt [BH * DK * SEQ];    // [bh][d][hi@s]

// ---------------------------------------------------------------------------
// split helpers
// ---------------------------------------------------------------------------
__device__ __forceinline__ void split_h16(float f, __half& hi, __half& lo) {
    hi = __float2half(f);
    lo = __float2half(f - __half2float(hi));
}
__device__ __forceinline__ uint32_t packh(__half a, __half b) {
    __half2 t = __halves2half2(a, b);
    return *(uint32_t*)&t;
}
__device__ __forceinline__ uint32_t packhf(float a, float b) {
    __half2 t = __halves2half2(__float2half(a), __float2half(b));
    return *(uint32_t*)&t;
}
__device__ __forceinline__ float lofh(float a) {
    return a - __half2float(__float2half(a));
}

// weights: out row = [hi | hi], row width 2K (fp16 2-term: only hi used)
__global__ void convert_B_kernel(const float* __restrict__ W, __half* __restrict__ out,
                                 int K, int total) {
    int idx = blockIdx.x * 256 + threadIdx.x;
    if (idx >= total) return;
    int n = idx / K, k = idx - n * K;
    __half hi = __float2half(W[idx]);
    size_t base = (size_t)n * 2 * K;
    out[base + k] = hi;
    out[base + K + k] = hi;
}

// batched qkv weight conversion: all layers, q|k|v, one launch ([hi|hi] fp16)
__global__ void convert_qkv_kernel(const float* __restrict__ Wq, const float* __restrict__ Wk,
                                   const float* __restrict__ Wv, __half* __restrict__ out) {
    const int per = NU * NU;
    int idx = blockIdx.x * 256 + threadIdx.x;
    if (idx >= NLAYERS * 3 * per) return;
    int mat = idx / per;
    int rem = idx - mat * per;
    int l = mat / 3, sec = mat - l * 3;
    int n = rem / NU, k = rem - n * NU;
    const float* W = (sec == 0) ? Wq : (sec == 1) ? Wk : Wv;
    __half hi = __float2half(W[(size_t)l * per + rem]);
    size_t base = (size_t)l * QKVW * 2 * NU + (size_t)(sec * NU + n) * 2 * NU;
    out[base + k] = hi;
    out[base + NU + k] = hi;
}

// activations: out row = [hi | lo] fp16
__global__ void convert_A_kernel(const float* __restrict__ A, __half* __restrict__ out,
                                 int K, int total) {
    int idx = blockIdx.x * 256 + threadIdx.x;
    if (idx >= total) return;
    int n = idx / K, k = idx - n * K;
    __half hi, lo;
    split_h16(A[idx], hi, lo);
    size_t base = (size_t)n * 2 * K;
    out[base + k] = hi;
    out[base + K + k] = lo;
}

// pack per-layer q|k|v biases into 1536-wide rows
__global__ void pack_bqkv_kernel(const float* __restrict__ bq, const float* __restrict__ bk,
                                 const float* __restrict__ bv, float* __restrict__ out) {
    int i = blockIdx.x * 256 + threadIdx.x;
    if (i >= NLAYERS * QKVW) return;
    int l = i / QKVW, c = i - l * QKVW;
    float v = (c < NU) ? bq[l * NU + c]
            : (c < 2 * NU) ? bk[l * NU + c - NU]
            : bv[l * NU + c - 2 * NU];
    out[i] = v;
}

// ---------------------------------------------------------------------------
// mma.sync common pieces
// ---------------------------------------------------------------------------
#define STAGE_BYTES 32768
#define GEMM_DSMEM  (2 * STAGE_BYTES)
#define FA_STAGE    16384          // K 8K | V 8K (64 s-rows, fp16 hi only)
#define FA_DSMEM    (32768 + 2 * FA_STAGE)   // Q 32K + 2 stages = 64K

__device__ __forceinline__ uint32_t smem_u32(const void* p) {
    uint32_t a;
    asm("{ .reg .u64 t; cvta.to.shared.u64 t, %1; cvt.u32.u64 %0, t; }" : "=r"(a) : "l"(p));
    return a;
}

#define CP_ASYNC16(dst, src) \
    asm volatile("cp.async.cg.shared.global [%0], [%1], 16;" :: "r"(dst), "l"(src) : "memory")
#define CP_COMMIT() asm volatile("cp.async.commit_group;" ::: "memory")
#define CP_WAIT0()  asm volatile("cp.async.wait_group 0;" ::: "memory")

#define LDMATRIX_X4(r0, r1, r2, r3, addr) \
    asm volatile("ldmatrix.sync.aligned.m8n8.x4.shared.b16 {%0,%1,%2,%3}, [%4];" \
        : "=r"(r0), "=r"(r1), "=r"(r2), "=r"(r3) : "r"(addr))

__device__ __forceinline__ void mma16816h(float* d, const uint32_t* a, const uint32_t* b) {
    asm volatile(
        "mma.sync.aligned.m16n8k16.row.col.f32.f16.f16.f32 "
        "{%0,%1,%2,%3}, {%4,%5,%6,%7}, {%8,%9}, {%0,%1,%2,%3};"
        : "+f"(d[0]), "+f"(d[1]), "+f"(d[2]), "+f"(d[3])
        : "r"(a[0]), "r"(a[1]), "r"(a[2]), "r"(a[3]), "r"(b[0]), "r"(b[1]));
}

// ---------------------------------------------------------------------------
// Linear GEMM (fp16 2-term, verified R15): C[M,N] = A[M,Kp] @ B[N,Kp]^T
// EP: 0 = fp32 out, 1 = fp32 + residual, 2 = relu + fp16 [hi|lo] out
//     3 = fused qkv epilogue: write fp16 attention operand layouts
// ---------------------------------------------------------------------------
template<int EP>
__global__ __launch_bounds__(256) void mma_gemm(
    const __half* __restrict__ A, const __half* __restrict__ B,
    const float* __restrict__ bias, const float* __restrict__ res,
    float* __restrict__ Cf, __half* __restrict__ Cb,
    __half* __restrict__ q_out, __half* __restrict__ k_out,
    __half* __restrict__ v_out,
    int N, int Kp)
{
    extern __shared__ __align__(16) char dsm[];
    const uint32_t sbase = smem_u32(dsm);

    const int tid  = threadIdx.x;
    const int wid  = tid >> 5;
    const int lane = tid & 31;
    const int g    = lane >> 2;
    const int cq   = lane & 3;
    const int lr   = lane & 15;
    const int lc   = lane >> 4;
    const int wm   = wid & 3;
    const int wn   = wid >> 2;
    const int n0   = blockIdx.x * 128;
    const int m0   = blockIdx.y * 128;

    const __half* Ap = A + (size_t)m0 * Kp;
    const __half* Bp = B + (size_t)n0 * Kp;
    const int nchunk = Kp >> 6;

    float acc[2][8][4];
#pragma unroll
    for (int mi = 0; mi < 2; mi++)
#pragma unroll
        for (int ni = 0; ni < 8; ni++)
#pragma unroll
            for (int r = 0; r < 4; r++) acc[mi][ni][r] = 0.0f;

    auto load_stage = [&](int c, int stage) {
        const int k0 = c << 6;
        const uint32_t sA = sbase + stage * STAGE_BYTES;
        const uint32_t sB = sA + 16384;
#pragma unroll
        for (int i = 0; i < 4; i++) {
            int lin = tid + i * 256;
            int r   = lin >> 3;
            int c16 = lin & 7;
            uint32_t off = (uint32_t)(r * 128 + ((c16 ^ (r & 7)) * 16));
            CP_ASYNC16(sA + off, (const void*)(Ap + (size_t)r * Kp + k0 + c16 * 8));
            CP_ASYNC16(sB + off, (const void*)(Bp + (size_t)r * Kp + k0 + c16 * 8));
        }
    };

    load_stage(0, 0);
    CP_COMMIT();

    for (int c = 0; c < nchunk; c++) {
        const int cur = c & 1;
        CP_WAIT0();
        __syncthreads();
        if (c + 1 < nchunk) {
            load_stage(c + 1, cur ^ 1);
            CP_COMMIT();
        }

        const uint32_t sA = sbase + cur * STAGE_BYTES;
        const uint32_t sB = sA + 16384;

#pragma unroll
        for (int ks = 0; ks < 4; ks++) {
            const int kblk = ks * 2 + lc;
            uint32_t afr[2][4], bfr[4][4];
#pragma unroll
            for (int mi = 0; mi < 2; mi++) {
                int row = wm * 32 + mi * 16 + lr;
                uint32_t addr = sA + (uint32_t)(row * 128 + ((kblk ^ (row & 7)) * 16));
                LDMATRIX_X4(afr[mi][0], afr[mi][1], afr[mi][2], afr[mi][3], addr);
            }
#pragma unroll
            for (int p = 0; p < 4; p++) {
                int row = wn * 64 + p * 16 + lr;
                uint32_t addr = sB + (uint32_t)(row * 128 + ((kblk ^ (row & 7)) * 16));
                LDMATRIX_X4(bfr[p][0], bfr[p][1], bfr[p][2], bfr[p][3], addr);
            }
#pragma unroll
            for (int mi = 0; mi < 2; mi++)
#pragma unroll
                for (int ni = 0; ni < 8; ni++) {
                    const int p = ni >> 1, o = ni & 1;
                    uint32_t b2[2] = { bfr[p][o], bfr[p][2 + o] };
                    mma16816h(acc[mi][ni], afr[mi], b2);
                }
        }
    }

#pragma unroll
    for (int mi = 0; mi < 2; mi++) {
#pragma unroll
        for (int half = 0; half < 2; half++) {
            const int m = m0 + wm * 32 + mi * 16 + g + half * 8;
#pragma unroll
            for (int ni = 0; ni < 8; ni++) {
                const int n = n0 + wn * 64 + ni * 8 + 2 * cq;
                float2 bv = *(const float2*)(bias + n);
                float v0 = acc[mi][ni][half * 2 + 0] + bv.x;
                float v1 = acc[mi][ni][half * 2 + 1] + bv.y;
                if (EP == 2) {
                    v0 = fmaxf(v0, 0.f); v1 = fmaxf(v1, 0.f);
                    __half h0, h1, l0, l1;
                    split_h16(v0, h0, l0); split_h16(v1, h1, l1);
                    size_t rb = (size_t)m * 2 * N;
                    *(uint32_t*)(Cb + rb + n)     = packh(h0, h1);
                    *(uint32_t*)(Cb + rb + N + n) = packh(l0, l1);
                } else if (EP == 3) {
                    const int sec = n >> 9;            // 0=q 1=k 2=v
                    const int hh  = (n >> 6) & 7;      // head
                    const int d   = n & 63;            // dim within head (even)
                    const int t   = m & (SEQ - 1);
                    const int bh  = (m >> 10) * HEADS + hh;
                    if (sec == 0) {
                        float q0 = v0 * 0.125f, q1 = v1 * 0.125f;
                        __half h0, h1, l0, l1;
                        split_h16(q0, h0, l0); split_h16(q1, h1, l1);
                        __half* qb = q_out + ((size_t)bh * SEQ + t) * 128 + d;
                        *(uint32_t*)(qb)      = packh(h0, h1);
                        *(uint32_t*)(qb + 64) = packh(l0, l1);
                    } else if (sec == 1) {
                        __half* kb = k_out + ((size_t)bh * SEQ + t) * 64 + d;
                        *(uint32_t*)(kb) = packhf(v0, v1);
                    } else {
                        __half* vb0 = v_out + ((size_t)bh * DK + d) * SEQ + t;
                        vb0[0]   = __float2half(v0);
                        vb0[SEQ] = __float2half(v1);
                    }
                } else {
                    if (EP == 1) {
                        float2 rv = *(const float2*)(res + (size_t)m * N + n);
                        v0 += rv.x; v1 += rv.y;
                    }
                    *(float2*)(Cf + (size_t)m * N + n) = make_float2(v0, v1);
                }
            }
        }
    }
}

// ---------------------------------------------------------------------------
// Fused flash attention, fp16 2-term (no-max softmax), 64-row KV chunks.
// Q = [hi|lo] fp16 (exact), K/V hi-only: S = (Qhi+Qlo)·Khi, ctx = (Phi+Plo)·Vhi.
// Same tiling/sync structure as the verified R15 kernel.
// ---------------------------------------------------------------------------
__global__ __launch_bounds__(256, 2) void flash_attn(
    const __half* __restrict__ qs, const __half* __restrict__ ks,
    const __half* __restrict__ vt, __half* __restrict__ Ccvt)
{
    extern __shared__ __align__(16) char dsm[];
    const uint32_t sb  = smem_u32(dsm);
    const uint32_t Qhi = sb;               // [128][64] fp16
    const uint32_t Qlo = sb + 16384;
    const uint32_t ST0 = sb + 32768;       // stage: K 8K | V 8K

    const int tid  = threadIdx.x;
    const int wid  = tid >> 5;
    const int lane = tid & 31;
    const int g    = lane >> 2;
    const int cq   = lane & 3;
    const int lr   = lane & 15;
    const int lc   = lane >> 4;
    const int q0   = blockIdx.x * 128;
    const int bh   = blockIdx.y;
    const int b    = bh >> 3, h = bh & 7;

    // --- load Q (once): 2 slabs x 128 rows x 8 16B-units ---
#pragma unroll
    for (int i = 0; i < 8; i++) {
        int id = tid + i * 256;
        int slab = id >> 10, r = (id >> 3) & 127, u = id & 7;
        const __half* src = qs + ((size_t)bh * SEQ + q0 + r) * 128 + slab * 64 + u * 8;
        CP_ASYNC16((slab ? Qlo : Qhi) + (uint32_t)(r * 128 + ((u ^ (r & 7)) * 16)), src);
    }

    auto load_kv = [&](int st, uint32_t stage) {
        const int s0 = st * 64;
#pragma unroll
        for (int i = 0; i < 2; i++) {          // K: 64 rows x 8 units
            int id = tid + i * 256;
            int r = id >> 3, u = id & 7;
            const __half* src = ks + ((size_t)bh * SEQ + s0 + r) * 64 + u * 8;
            CP_ASYNC16(stage + (uint32_t)(r * 128 + ((u ^ (r & 7)) * 16)), src);
        }
#pragma unroll
        for (int i = 0; i < 2; i++) {          // V: 64 d-rows x 8 units
            int id = tid + i * 256;
            int r = id >> 3, u = id & 7;
            const __half* src = vt + ((size_t)bh * DK + r) * SEQ + s0 + u * 8;
            CP_ASYNC16(stage + 8192 + (uint32_t)(r * 128 + ((u ^ (r & 7)) * 16)), src);
        }
    };

    load_kv(0, ST0);
    CP_COMMIT();

    float oacc[8][4];
#pragma unroll
    for (int ni = 0; ni < 8; ni++)
#pragma unroll
        for (int r = 0; r < 4; r++) oacc[ni][r] = 0.0f;
    float lsum0 = 0.0f, lsum1 = 0.0f;

    const int arow = wid * 16 + lr;
    const uint32_t aoff = (uint32_t)(arow * 128);

    for (int st = 0; st < 16; st++) {
        const int cur = st & 1;
        CP_WAIT0();
        __syncthreads();
        if (st + 1 < 16) {
            load_kv(st + 1, ST0 + (cur ^ 1) * FA_STAGE);
            CP_COMMIT();
        }

        const uint32_t Kh = ST0 + cur * FA_STAGE;
        const uint32_t Vh = Kh + 8192;

        // ---- S = Q K^T : fp16 2-term (Qhi + Qlo vs Khi) ----
        float sacc[8][4];
#pragma unroll
        for (int ni = 0; ni < 8; ni++)
#pragma unroll
            for (int r = 0; r < 4; r++) sacc[ni][r] = 0.0f;

#pragma unroll
        for (int j = 0; j < 4; j++) {
            const int kblk = j * 2 + lc;
            const uint32_t asw = (uint32_t)((kblk ^ (arow & 7)) * 16);
            uint32_t ahi[4], alo[4];
            LDMATRIX_X4(ahi[0], ahi[1], ahi[2], ahi[3], Qhi + aoff + asw);
            LDMATRIX_X4(alo[0], alo[1], alo[2], alo[3], Qlo + aoff + asw);
#pragma unroll
            for (int p = 0; p < 4; p++) {
                int row = p * 16 + lr;
                const uint32_t rsw = (uint32_t)(row * 128 + ((kblk ^ (row & 7)) * 16));
                uint32_t kh[4];
                LDMATRIX_X4(kh[0], kh[1], kh[2], kh[3], Kh + rsw);
#pragma unroll
                for (int o = 0; o < 2; o++) {
                    uint32_t b2[2] = { kh[o], kh[2 + o] };
                    mma16816h(sacc[2 * p + o], ahi, b2);
                    mma16816h(sacc[2 * p + o], alo, b2);
                }
            }
        }

        // ---- P = exp(S); accumulate row sums ----
#pragma unroll
        for (int ni = 0; ni < 8; ni++) {
            float p0 = __expf(sacc[ni][0]);
            float p1 = __expf(sacc[ni][1]);
            float p2 = __expf(sacc[ni][2]);
            float p3 = __expf(sacc[ni][3]);
            lsum0 += p0 + p1;
            lsum1 += p2 + p3;
            sacc[ni][0] = p0; sacc[ni][1] = p1;
            sacc[ni][2] = p2; sacc[ni][3] = p3;
        }

        // ---- ctx += P V^T : fp16 2-term (Phi + Plo vs Vhi) ----
#pragma unroll
        for (int jj = 0; jj < 4; jj++) {
            const int kblk = jj * 2 + lc;
            uint32_t phi[4], plo[4];
            phi[0] = packhf(sacc[2 * jj][0],     sacc[2 * jj][1]);
            phi[1] = packhf(sacc[2 * jj][2],     sacc[2 * jj][3]);
            phi[2] = packhf(sacc[2 * jj + 1][0], sacc[2 * jj + 1][1]);
            phi[3] = packhf(sacc[2 * jj + 1][2], sacc[2 * jj + 1][3]);
            plo[0] = packhf(lofh(sacc[2 * jj][0]),     lofh(sacc[2 * jj][1]));
            plo[1] = packhf(lofh(sacc[2 * jj][2]),     lofh(sacc[2 * jj][3]));
            plo[2] = packhf(lofh(sacc[2 * jj + 1][0]), lofh(sacc[2 * jj + 1][1]));
            plo[3] = packhf(lofh(sacc[2 * jj + 1][2]), lofh(sacc[2 * jj + 1][3]));
#pragma unroll
            for (int p = 0; p < 4; p++) {
                int row = p * 16 + lr;
                const uint32_t rsw = (uint32_t)(row * 128 + ((kblk ^ (row & 7)) * 16));
                uint32_t vh[4];
                LDMATRIX_X4(vh[0], vh[1], vh[2], vh[3], Vh + rsw);
#pragma unroll
                for (int o = 0; o < 2; o++) {
                    uint32_t b2[2] = { vh[o], vh[2 + o] };
                    mma16816h(oacc[2 * p + o], phi, b2);
                    mma16816h(oacc[2 * p + o], plo, b2);
                }
            }
        }
    }

    // row-sum reduction over the quad (cq lanes)
    lsum0 += __shfl_xor_sync(0xffffffffu, lsum0, 1);
    lsum0 += __shfl_xor_sync(0xffffffffu, lsum0, 2);
    lsum1 += __shfl_xor_sync(0xffffffffu, lsum1, 1);
    lsum1 += __shfl_xor_sync(0xffffffffu, lsum1, 2);
    const float inv0 = 1.0f / lsum0;
    const float inv1 = 1.0f / lsum1;

    // epilogue: fp16 [hi|lo] write into g_ccvt [tok][2*512] at cols h*64 + n
#pragma unroll
    for (int half = 0; half < 2; half++) {
        const int m = q0 + wid * 16 + g + half * 8;
        const size_t tok = (size_t)b * SEQ + m;
        const size_t rb = tok * (2 * NU);
        const float inv = half ? inv1 : inv0;
#pragma unroll
        for (int ni = 0; ni < 8; ni++) {
            const int col = h * DK + ni * 8 + 2 * cq;
            float v0 = oacc[ni][half * 2 + 0] * inv;
            float v1 = oacc[ni][half * 2 + 1] * inv;
            __half h0, h1, l0, l1;
            split_h16(v0, h0, l0); split_h16(v1, h1, l1);
            *(uint32_t*)(Ccvt + rb + col)      = packh(h0, h1);
            *(uint32_t*)(Ccvt + rb + NU + col) = packh(l0, l1);
        }
    }
}

// ---------------------------------------------------------------------------
// LayerNorm over rows of 512; optionally also writes fp16 [hi|lo]
// ---------------------------------------------------------------------------
template<bool CVT>
__global__ __launch_bounds__(128) void ln_kernel(
    const float* __restrict__ X, const float* __restrict__ gamma,
    const float* __restrict__ beta, float* __restrict__ O,
    __half* __restrict__ Ocvt)
{
    __shared__ float red[4];
    const int row = blockIdx.x;
    const int tid = threadIdx.x;

    float4 v = *(const float4*)(X + (size_t)row * NU + tid * 4);
    float s = v.x + v.y + v.z + v.w;
#pragma unroll
    for (int o = 16; o > 0; o >>= 1) s += __shfl_xor_sync(0xffffffffu, s, o);
    if ((tid & 31) == 0) red[tid >> 5] = s;
    __syncthreads();
    float mean = (red[0] + red[1] + red[2] + red[3]) * (1.0f / 512.0f);
    __syncthreads();

    float dx = v.x - mean, dy = v.y - mean, dz = v.z - mean, dw = v.w - mean;
    float sq = dx * dx + dy * dy + dz * dz + dw * dw;
#pragma unroll
    for (int o = 16; o > 0; o >>= 1) sq += __shfl_xor_sync(0xffffffffu, sq, o);
    if ((tid & 31) == 0) red[tid >> 5] = sq;
    __syncthreads();
    float var = (red[0] + red[1] + red[2] + red[3]) * (1.0f / 512.0f);
    float inv = rsqrtf(var + 1e-5f);

    float4 g = *(const float4*)(gamma + tid * 4);
    float4 b = *(const float4*)(beta  + tid * 4);
    float4 o4;
    o4.x = dx * inv * g.x + b.x;
    o4.y = dy * inv * g.y + b.y;
    o4.z = dz * inv * g.z + b.z;
    o4.w = dw * inv * g.w + b.w;
    *(float4*)(O + (size_t)row * NU + tid * 4) = o4;

    if (CVT) {
        __half h0, h1, h2, h3, l0, l1, l2, l3;
        split_h16(o4.x, h0, l0); split_h16(o4.y, h1, l1);
        split_h16(o4.z, h2, l2); split_h16(o4.w, h3, l3);
        uint2 hp, lp;
        hp.x = packh(h0, h1); hp.y = packh(h2, h3);
        lp.x = packh(l0, l1); lp.y = packh(l2, l3);
        size_t rb = (size_t)row * (2 * NU);
        int col = tid * 4;
        *(uint2*)(Ocvt + rb + col)      = hp;
        *(uint2*)(Ocvt + rb + NU + col) = lp;
    }
}

// ---------------------------------------------------------------------------
// Host orchestration (graph-capturable: kernel launches only)
// ---------------------------------------------------------------------------
extern "C" void kernel_launch(void* const* d_in, const int* in_sizes, int n_in,
                              void* d_out, int out_size)
{
    (void)in_sizes; (void)n_in; (void)out_size;

    const float* x     = (const float*)d_in[0];
    const float* Win   = (const float*)d_in[1];
    const float* bin   = (const float*)d_in[2];
    const float* ln1_g = (const float*)d_in[3];
    const float* ln1_b = (const float*)d_in[4];
    const float* Wq    = (const float*)d_in[5];
    const float* bq    = (const float*)d_in[6];
    const float* Wk    = (const float*)d_in[7];
    const float* bk    = (const float*)d_in[8];
    const float* Wv    = (const float*)d_in[9];
    const float* bv    = (const float*)d_in[10];
    const float* Wo    = (const float*)d_in[11];
    const float* bo    = (const float*)d_in[12];
    const float* ln2_g = (const float*)d_in[13];
    const float* ln2_b = (const float*)d_in[14];
    const float* W1    = (const float*)d_in[15];
    const float* b1    = (const float*)d_in[16];
    const float* W2    = (const float*)d_in[17];
    const float* b2    = (const float*)d_in[18];
    const float* lno_g = (const float*)d_in[19];
    const float* lno_b = (const float*)d_in[20];
    float* out = (float*)d_out;

    float *e, *bqkv;
    __half *xc, *ec, *cc, *hc, *Winc, *Wqkvc, *Woc, *W1c, *W2c;
    __half *qs, *ks, *vt;
    cudaGetSymbolAddress((void**)&e,    g_e);
    cudaGetSymbolAddress((void**)&bqkv, g_bqkv);
    cudaGetSymbolAddress((void**)&xc,   g_xcvt);
    cudaGetSymbolAddress((void**)&ec,   g_ecvt);
    cudaGetSymbolAddress((void**)&cc,   g_ccvt);
    cudaGetSymbolAddress((void**)&hc,   g_hcvt);
    cudaGetSymbolAddress((void**)&Winc,  g_Winc);
    cudaGetSymbolAddress((void**)&Wqkvc, g_Wqkvc);
    cudaGetSymbolAddress((void**)&Woc,   g_Woc);
    cudaGetSymbolAddress((void**)&W1c,   g_W1c);
    cudaGetSymbolAddress((void**)&W2c,   g_W2c);
    cudaGetSymbolAddress((void**)&qs,   g_qs);
    cudaGetSymbolAddress((void**)&ks,   g_ks);
    cudaGetSymbolAddress((void**)&vt,   g_vt);

    cudaFuncSetAttribute(mma_gemm<0>, cudaFuncAttributeMaxDynamicSharedMemorySize, GEMM_DSMEM);
    cudaFuncSetAttribute(mma_gemm<1>, cudaFuncAttributeMaxDynamicSharedMemorySize, GEMM_DSMEM);
    cudaFuncSetAttribute(mma_gemm<2>, cudaFuncAttributeMaxDynamicSharedMemorySize, GEMM_DSMEM);
    cudaFuncSetAttribute(mma_gemm<3>, cudaFuncAttributeMaxDynamicSharedMemorySize, GEMM_DSMEM);
    cudaFuncSetAttribute(flash_attn,  cudaFuncAttributeMaxDynamicSharedMemorySize, FA_DSMEM);

    // operand conversions (every launch; deterministic)
    {
        int t;
        t = NU * IDIM;          convert_B_kernel<<<(t + 255) / 256, 256>>>(Win, Winc, IDIM, t);
        t = NLAYERS * 3 * NU * NU;
                                convert_qkv_kernel<<<(t + 255) / 256, 256>>>(Wq, Wk, Wv, Wqkvc);
        t = NLAYERS * NU * NU;  convert_B_kernel<<<(t + 255) / 256, 256>>>(Wo, Woc, NU, t);
        t = NLAYERS * EU * NU;  convert_B_kernel<<<(t + 255) / 256, 256>>>(W1, W1c, NU, t);
        t = NLAYERS * NU * EU;  convert_B_kernel<<<(t + 255) / 256, 256>>>(W2, W2c, EU, t);
        t = TOK * IDIM;         convert_A_kernel<<<(t + 255) / 256, 256>>>(x, xc, IDIM, t);
        t = NLAYERS * QKVW;     pack_bqkv_kernel<<<(t + 255) / 256, 256>>>(bq, bk, bv, bqkv);
    }

    dim3 g512 (NU   / 128, TOK / 128);   // (4, 64)
    dim3 gqkv (QKVW / 128, TOK / 128);   // (12, 64)
    dim3 g2048(EU   / 128, TOK / 128);   // (16, 64)
    dim3 gflash(SEQ / 128, BH);          // (8, 64)

    // input projection: e = x @ Win^T + bin
    mma_gemm<0><<<g512, 256, GEMM_DSMEM>>>(xc, Winc, bin, nullptr, e, nullptr,
                                           nullptr, nullptr, nullptr, NU, 2 * IDIM);

    for (int i = 0; i < NLAYERS; i++) {
        const size_t wqkv = (size_t)i * QKVW * 2 * NU;
        const size_t wo   = (size_t)i * NU * 2 * NU;
        const size_t w1o  = (size_t)i * EU * 2 * NU;
        const size_t w2o  = (size_t)i * NU * 2 * EU;

        ln_kernel<true><<<TOK, 128>>>(e, ln1_g + i * NU, ln1_b + i * NU, e, ec);

        // fused qkv GEMM with direct attention-operand epilogue
        mma_gemm<3><<<gqkv, 256, GEMM_DSMEM>>>(ec, Wqkvc + wqkv, bqkv + i * QKVW, nullptr,
                                               nullptr, nullptr, qs, ks, vt, QKVW, 2 * NU);

        // fused attention
        flash_attn<<<gflash, 256, FA_DSMEM>>>(qs, ks, vt, cc);

        // e = e + ctx @ Wo^T + bo
        mma_gemm<1><<<g512, 256, GEMM_DSMEM>>>(cc, Woc + wo, bo + i * NU, e, e, nullptr,
                                               nullptr, nullptr, nullptr, NU, 2 * NU);

        ln_kernel<true><<<TOK, 128>>>(e, ln2_g + i * NU, ln2_b + i * NU, e, ec);

        // h = relu(e @ W1^T + b1) -> fp16 [hi|lo]
        mma_gemm<2><<<g2048, 256, GEMM_DSMEM>>>(ec, W1c + w1o, b1 + (size_t)i * EU, nullptr,
                                                nullptr, hc, nullptr, nullptr, nullptr, EU, 2 * NU);
        // e = e + h @ W2^T + b2
        mma_gemm<1><<<g512, 256, GEMM_DSMEM>>>(hc, W2c + w2o, b2 + i * NU, e, e, nullptr,
                                               nullptr, nullptr, nullptr, NU, 2 * EU);
    }

    ln_kernel<false><<<TOK, 128>>>(e, lno_g, lno_b, out, nullptr);
}